// round 9
// baseline (speedup 1.0000x reference)
#include <cuda_runtime.h>
#include <cuda_bf16.h>
#include <cstdint>

#define N_NODES 50000
#define N_EDGES 800000
#define D 128
#define DE 16
#define K1 272
#define K1PAD 320
#define TM 128
#define NTILES (N_EDGES / TM)           // 6250
#define NNT ((N_NODES + 127) / 128)     // 391

#define W1B_BYTES (128 * K1PAD * 2)   // 81920
#define W2B_BYTES (128 * 128 * 2)     // 32768
#define A1B_BYTES (128 * K1PAD * 2)   // 81920
#define NW1_WORDS (256 * 128)
#define NW2_WORDS (128 * 128)

// edge TMEM: D1 double-buffered
#define TMEM_D1A 0      // 128 cols fp32
#define TMEM_D1B 128    // 128 cols fp32
#define TMEM_D2  256    // 128 cols fp32
#define TMEM_A2  384    // 64 cols bf16

#define IDESC_BF16 0x8200490u
#define IDESC_TF32 0x8200910u

// ---------------- scratch -----------------------------------------------
__device__ int      g_is64;
__device__ int      g_row[N_EDGES];
__device__ int      g_col[N_EDGES];
__device__ float    g_agg[(size_t)N_NODES * D];
__device__ uint16_t g_W1B[W1B_BYTES / 2];
__device__ uint16_t g_W2B[W2B_BYTES / 2];
__device__ uint32_t g_NW1B[NW1_WORDS];
__device__ uint32_t g_NW2B[NW2_WORDS];

// silu via tanh.approx: 1 MUFU + FMA (vs ex2+rcp = 2 MUFU)
__device__ __forceinline__ float silu_f(float v) {
    float t;
    asm("tanh.approx.f32 %0, %1;" : "=f"(t) : "f"(0.5f * v));
    return v * fmaf(0.5f, t, 0.5f);
}
__device__ __forceinline__ uint32_t smem_u32(const void* p) {
    uint32_t a;
    asm("{ .reg .u64 t; cvta.to.shared.u64 t, %1; cvt.u32.u64 %0, t; }"
        : "=r"(a) : "l"(p));
    return a;
}
__device__ __forceinline__ uint32_t pack_bf16x2(float lo, float hi) {
    uint32_t d;
    asm("cvt.rn.bf16x2.f32 %0, %1, %2;" : "=r"(d) : "f"(hi), "f"(lo));
    return d;
}
__device__ __forceinline__ uint16_t bf16_bits(float v) {
    __nv_bfloat16 b = __float2bfloat16(v);
    return *reinterpret_cast<uint16_t*>(&b);
}
__device__ __forceinline__ uint32_t f2tf32(float f) {
    uint32_t u;
    asm("cvt.rna.tf32.f32 %0, %1;" : "=r"(u) : "f"(f));
    return u;
}
__device__ __forceinline__ void sts8(uint32_t addr, uint32_t a, uint32_t b) {
    asm volatile("st.shared.v2.b32 [%0], {%1, %2};" :: "r"(addr), "r"(a), "r"(b) : "memory");
}
__device__ __forceinline__ uint32_t abyte(int row, int k) {
    return (uint32_t)((((row >> 3) + ((k >> 6) << 4)) << 10) | ((row & 7) << 7) | ((k & 63) << 1));
}
__device__ __forceinline__ uint32_t abyte32(int row, int k) {
    return (uint32_t)((((row >> 3) + ((k >> 5) << 4)) << 10) | ((row & 7) << 7) | ((k & 31) << 2));
}
__device__ __forceinline__ uint32_t swz(uint32_t b) {
    return b ^ ((b >> 3) & 0x70);
}

#if defined(__CUDA_ARCH__) && defined(__CUDA_ARCH_FEAT_SM103_ALL)

__device__ __forceinline__ uint32_t elect_one() {
    uint32_t pred;
    asm volatile("{\n\t.reg .pred p;\n\telect.sync _|p, 0xFFFFFFFF;\n\t"
                 "selp.b32 %0, 1, 0, p;\n\t}" : "=r"(pred));
    return pred;
}

#define TC_ALLOC(smemaddr, n) \
    asm volatile("tcgen05.alloc.cta_group::1.sync.aligned.shared::cta.b32 [%0], %1;" \
                 :: "r"(smemaddr), "r"((uint32_t)(n)) : "memory")
#define TC_RELINQ() \
    asm volatile("tcgen05.relinquish_alloc_permit.cta_group::1.sync.aligned;")
#define TC_DEALLOC(tmem, n) \
    asm volatile("tcgen05.dealloc.cta_group::1.sync.aligned.b32 %0, %1;" \
                 :: "r"(tmem), "r"((uint32_t)(n)))
#define TC_WAIT_ST() asm volatile("tcgen05.wait::st.sync.aligned;" ::: "memory")
#define TC_WAIT_LD() asm volatile("tcgen05.wait::ld.sync.aligned;" ::: "memory")
#define TC_FENCE_BEFORE() asm volatile("tcgen05.fence::before_thread_sync;" ::: "memory")
#define TC_FENCE_AFTER()  asm volatile("tcgen05.fence::after_thread_sync;" ::: "memory")
#define TC_COMMIT(mbar) \
    asm volatile("tcgen05.commit.cta_group::1.mbarrier::arrive::one.shared::cluster.b64 [%0];" \
                 :: "r"(mbar) : "memory")
#define MBAR_INIT(mbar, cnt) \
    asm volatile("mbarrier.init.shared.b64 [%0], %1;" :: "r"(mbar), "r"((uint32_t)(cnt)) : "memory")
#define FENCE_PROXY_ASYNC() \
    asm volatile("fence.proxy.async.shared::cta;" ::: "memory")
#define NAMED_BAR(id, n) \
    asm volatile("bar.sync %0, %1;" :: "r"(id), "r"(n) : "memory")
#define NAMED_ARRIVE(id, n) \
    asm volatile("bar.arrive %0, %1;" :: "r"(id), "r"(n) : "memory")

#define MBAR_WAIT(mbar, ph) do {                                             \
    uint32_t _m = (mbar), _p = (uint32_t)(ph), _d;                           \
    asm volatile("{\n\t.reg .pred p;\n\t"                                    \
        "mbarrier.try_wait.parity.acquire.cta.shared::cta.b64 p, [%1], %2;\n\t" \
        "selp.b32 %0, 1, 0, p;\n\t}" : "=r"(_d) : "r"(_m), "r"(_p) : "memory"); \
    if (!_d) {                                                               \
        asm volatile("{\n\t.reg .pred P1;\n\t"                               \
            "WL_%=:\n\t"                                                     \
            "mbarrier.try_wait.parity.acquire.cta.shared::cta.b64 P1, [%0], %1, 0x989680;\n\t" \
            "@P1 bra.uni WD_%=;\n\t"                                         \
            "bra.uni WL_%=;\n\t"                                             \
            "WD_%=:\n\t}" :: "r"(_m), "r"(_p) : "memory");                   \
    }                                                                        \
} while (0)

#define TC_MMA_SS(dtm, adesc, bdesc, en) do {                                \
    uint32_t _e = (en) ? 1u : 0u;                                            \
    asm volatile("{\n\t.reg .pred p;\n\t"                                    \
        "setp.ne.u32 p, %5, 0;\n\t"                                          \
        "tcgen05.mma.cta_group::1.kind::f16 [%0], %1, %2, %3, {%4, %4, %4, %4}, p;\n\t" \
        "}" :: "r"(dtm), "l"(adesc), "l"(bdesc), "r"(IDESC_BF16),            \
               "r"(0u), "r"(_e) : "memory");                                 \
} while (0)

#define TC_MMA_TS(dtm, atm, bdesc, en) do {                                  \
    uint32_t _e = (en) ? 1u : 0u;                                            \
    asm volatile("{\n\t.reg .pred p;\n\t"                                    \
        "setp.ne.u32 p, %5, 0;\n\t"                                          \
        "tcgen05.mma.cta_group::1.kind::f16 [%0], [%1], %2, %3, {%4, %4, %4, %4}, p;\n\t" \
        "}" :: "r"(dtm), "r"(atm), "l"(bdesc), "r"(IDESC_BF16),              \
               "r"(0u), "r"(_e) : "memory");                                 \
} while (0)

#define TC_MMA_TF32_TS(dtm, atm, bdesc, en) do {                             \
    uint32_t _e = (en) ? 1u : 0u;                                            \
    asm volatile("{\n\t.reg .pred p;\n\t"                                    \
        "setp.ne.u32 p, %5, 0;\n\t"                                          \
        "tcgen05.mma.cta_group::1.kind::tf32 [%0], [%1], %2, %3, {%4, %4, %4, %4}, p;\n\t" \
        "}" :: "r"(dtm), "r"(atm), "l"(bdesc), "r"(IDESC_TF32),              \
               "r"(0u), "r"(_e) : "memory");                                 \
} while (0)

#define TC_ST_X16(tmem_addr, r)                                              \
    asm volatile("tcgen05.st.sync.aligned.32x32b.x16.b32 [%0], "             \
        "{%1, %2, %3, %4, %5, %6, %7, %8, "                                  \
        " %9, %10, %11, %12, %13, %14, %15, %16};"                           \
        :: "r"(tmem_addr),                                                   \
           "r"((r)[0]),  "r"((r)[1]),  "r"((r)[2]),  "r"((r)[3]),            \
           "r"((r)[4]),  "r"((r)[5]),  "r"((r)[6]),  "r"((r)[7]),            \
           "r"((r)[8]),  "r"((r)[9]),  "r"((r)[10]), "r"((r)[11]),           \
           "r"((r)[12]), "r"((r)[13]), "r"((r)[14]), "r"((r)[15])            \
        : "memory")

#define TC_ST_X32(tmem_addr, r)                                              \
    asm volatile("tcgen05.st.sync.aligned.32x32b.x32.b32 [%0], "             \
        "{%1, %2, %3, %4, %5, %6, %7, %8, "                                  \
        " %9, %10, %11, %12, %13, %14, %15, %16, "                           \
        " %17, %18, %19, %20, %21, %22, %23, %24, "                          \
        " %25, %26, %27, %28, %29, %30, %31, %32};"                          \
        :: "r"(tmem_addr),                                                   \
           "r"((r)[0]),  "r"((r)[1]),  "r"((r)[2]),  "r"((r)[3]),            \
           "r"((r)[4]),  "r"((r)[5]),  "r"((r)[6]),  "r"((r)[7]),            \
           "r"((r)[8]),  "r"((r)[9]),  "r"((r)[10]), "r"((r)[11]),           \
           "r"((r)[12]), "r"((r)[13]), "r"((r)[14]), "r"((r)[15]),           \
           "r"((r)[16]), "r"((r)[17]), "r"((r)[18]), "r"((r)[19]),           \
           "r"((r)[20]), "r"((r)[21]), "r"((r)[22]), "r"((r)[23]),           \
           "r"((r)[24]), "r"((r)[25]), "r"((r)[26]), "r"((r)[27]),           \
           "r"((r)[28]), "r"((r)[29]), "r"((r)[30]), "r"((r)[31])            \
        : "memory")

#define TC_LD_X32(r, tmem_addr)                                              \
    asm volatile("tcgen05.ld.sync.aligned.32x32b.x32.b32 "                   \
        "{%0, %1, %2, %3, %4, %5, %6, %7, "                                  \
        " %8, %9, %10, %11, %12, %13, %14, %15, "                            \
        " %16, %17, %18, %19, %20, %21, %22, %23, "                          \
        " %24, %25, %26, %27, %28, %29, %30, %31}, [%32];"                   \
        : "=r"((r)[0]),  "=r"((r)[1]),  "=r"((r)[2]),  "=r"((r)[3]),         \
          "=r"((r)[4]),  "=r"((r)[5]),  "=r"((r)[6]),  "=r"((r)[7]),         \
          "=r"((r)[8]),  "=r"((r)[9]),  "=r"((r)[10]), "=r"((r)[11]),        \
          "=r"((r)[12]), "=r"((r)[13]), "=r"((r)[14]), "=r"((r)[15]),        \
          "=r"((r)[16]), "=r"((r)[17]), "=r"((r)[18]), "=r"((r)[19]),        \
          "=r"((r)[20]), "=r"((r)[21]), "=r"((r)[22]), "=r"((r)[23]),        \
          "=r"((r)[24]), "=r"((r)[25]), "=r"((r)[26]), "=r"((r)[27]),        \
          "=r"((r)[28]), "=r"((r)[29]), "=r"((r)[30]), "=r"((r)[31])         \
        : "r"(tmem_addr))

static constexpr unsigned long long SMEM_DESC_BASE =
    (2ull << 61) | (1ull << 46) | (64ull << 32) | (1ull << 16);
__device__ __forceinline__ uint64_t mk_desc(uint32_t addr) {
    return SMEM_DESC_BASE | ((uint64_t)(addr >> 4) & 0x3FFF);
}
__device__ __forceinline__ uint64_t koff(int s) {
    return (uint64_t)((s >> 2) * 1024 + (s & 3) * 2);
}

#endif // sm_103a device helpers

// ---------------- small kernels ------------------------------------------
__global__ void k_detect(const int* ei32) {
    if (blockIdx.x == 0 && threadIdx.x == 0) {
        int is64 = 1;
        #pragma unroll 1
        for (int i = 0; i < 64; ++i)
            if (ei32[2 * i + 1] != 0) { is64 = 0; break; }
        g_is64 = is64;
    }
}
__global__ void k_convert_zero(const void* ei) {
    size_t i = (size_t)blockIdx.x * blockDim.x + threadIdx.x;
    if (i < N_EDGES) {
        if (g_is64) {
            const long long* p = (const long long*)ei;
            g_row[i] = (int)p[i];
            g_col[i] = (int)p[(size_t)N_EDGES + i];
        } else {
            const int* p = (const int*)ei;
            g_row[i] = p[i];
            g_col[i] = p[N_EDGES + i];
        }
    }
    if (i < (size_t)N_NODES * D) g_agg[i] = 0.0f;
}
__global__ void k_prep(const float* __restrict__ W1, const float* __restrict__ W2,
                       const float* __restrict__ NW1, const float* __restrict__ NW2) {
    int i = blockIdx.x * blockDim.x + threadIdx.x;
    if (i < 128 * K1PAD) {
        int n = i / K1PAD, k = i % K1PAD;
        float v = (k < K1) ? W1[(size_t)k * 128 + n] : 0.0f;
        g_W1B[swz(abyte(n, k)) >> 1] = bf16_bits(v);
        return;
    }
    i -= 128 * K1PAD;
    if (i < 128 * 128) {
        int n = i / 128, k = i % 128;
        g_W2B[swz(abyte(n, k)) >> 1] = bf16_bits(W2[(size_t)k * 128 + n]);
        return;
    }
    i -= 128 * 128;
    if (i < 128 * 256) {
        int n = i / 256, k = i % 256;
        g_NW1B[swz(abyte32(n, k)) >> 2] = f2tf32(NW1[(size_t)k * 128 + n]);
        return;
    }
    i -= 128 * 256;
    if (i < 128 * 128) {
        int n = i / 128, k = i % 128;
        g_NW2B[swz(abyte32(n, k)) >> 2] = f2tf32(NW2[(size_t)k * 128 + n]);
    }
}

// ---------------- fused edge kernel: 9 warps, dedicated MMA warp ----------
__global__ __launch_bounds__(288, 1) void k_edge_fused(
    const float* __restrict__ x, const float* __restrict__ ea,
    const float* __restrict__ eb1, const float* __restrict__ eb2,
    const float* __restrict__ eW1raw, const float* __restrict__ eW2raw,
    int nblocks)
{
#if defined(__CUDA_ARCH__) && defined(__CUDA_ARCH_FEAT_SM103_ALL)
    extern __shared__ uint32_t dsm[];
    __shared__ float s_eb1[D], s_eb2[D];
    __shared__ uint32_t s_tmem[1];
    __shared__ __align__(8) unsigned long long s_mbar1, s_mbar2;

    const int tid = threadIdx.x;
    const int wid = tid >> 5;
    const int lane = tid & 31;

    const uint32_t dyn_base = smem_u32(dsm);
    const uint32_t ws1 = (dyn_base + 1023u) & ~1023u;
    const uint32_t ws2 = ws1 + W1B_BYTES;
    const uint32_t wsA = ws2 + W2B_BYTES;
    uint32_t* w1p = dsm + ((ws1 - dyn_base) >> 2);

    {
        uint4* dst = (uint4*)w1p; const uint4* src = (const uint4*)g_W1B;
        for (int i = tid; i < (W1B_BYTES + W2B_BYTES) / 16; i += 288) dst[i] = src[i];
        if (tid < D) { s_eb1[tid] = eb1[tid]; s_eb2[tid] = eb2[tid]; }
        for (int i = tid; i < 128 * 12; i += 288) {
            int row = i / 12, j = i % 12;
            sts8(wsA + swz(abyte(row, 272 + j * 4)), 0u, 0u);
        }
    }
    if (wid == 0) TC_ALLOC(smem_u32(s_tmem), 512);
    if (tid == 0) { MBAR_INIT(smem_u32(&s_mbar1), 1); MBAR_INIT(smem_u32(&s_mbar2), 1); }
    __syncthreads();
    const uint32_t tbase = s_tmem[0];
    const uint32_t mbar1 = smem_u32(&s_mbar1);
    const uint32_t mbar2 = smem_u32(&s_mbar2);
    const uint64_t a1d = mk_desc(wsA);
    const uint64_t w1d = mk_desc(ws1);
    const uint64_t w2d = mk_desc(ws2);

    auto gather = [&](int tile) {
        const int gw = wid;
        const int e0 = tile * TM + gw * 32;
        const int myr = g_row[e0 + lane];
        const int myc = g_col[e0 + lane];
        #pragma unroll 8
        for (int i = 0; i < 32; ++i) {
            const int el = gw * 32 + i;
            const int r = __shfl_sync(0xffffffffu, myr, i);
            const int c = __shfl_sync(0xffffffffu, myc, i);
            float4 v = *(const float4*)(x + (size_t)r * D + lane * 4);
            sts8(wsA + swz(abyte(el, lane * 4)),
                 pack_bf16x2(v.x, v.y), pack_bf16x2(v.z, v.w));
            v = *(const float4*)(x + (size_t)c * D + lane * 4);
            sts8(wsA + swz(abyte(el, 128 + lane * 4)),
                 pack_bf16x2(v.x, v.y), pack_bf16x2(v.z, v.w));
        }
        #pragma unroll
        for (int i = 0; i < 4; ++i) {
            const int el = gw * 32 + i * 8 + (lane >> 2);
            const int e = tile * TM + el;
            float4 v = *(const float4*)(ea + (size_t)e * DE + (lane & 3) * 4);
            sts8(wsA + swz(abyte(el, 256 + (lane & 3) * 4)),
                 pack_bf16x2(v.x, v.y), pack_bf16x2(v.z, v.w));
        }
    };

    auto e2_half = [&](int tile, int c0) {
        const int e = tile * TM + (wid & 3) * 32 + lane;
        float* aggp = g_agg + (size_t)g_row[e] * D;
        uint32_t d0[32], d1[32];
        TC_LD_X32(d0, tbase + TMEM_D2 + c0 * 32);
        TC_LD_X32(d1, tbase + TMEM_D2 + (c0 + 1) * 32);
        TC_WAIT_LD();
        #pragma unroll
        for (int q = 0; q < 8; ++q) {
            float v0 = silu_f(__uint_as_float(d0[q*4+0]) + s_eb2[c0*32+q*4+0]);
            float v1 = silu_f(__uint_as_float(d0[q*4+1]) + s_eb2[c0*32+q*4+1]);
            float v2 = silu_f(__uint_as_float(d0[q*4+2]) + s_eb2[c0*32+q*4+2]);
            float v3 = silu_f(__uint_as_float(d0[q*4+3]) + s_eb2[c0*32+q*4+3]);
            asm volatile("red.global.add.v4.f32 [%0], {%1,%2,%3,%4};"
                         :: "l"(aggp + c0 * 32 + q * 4),
                            "f"(v0), "f"(v1), "f"(v2), "f"(v3) : "memory");
        }
        #pragma unroll
        for (int q = 0; q < 8; ++q) {
            float v0 = silu_f(__uint_as_float(d1[q*4+0]) + s_eb2[(c0+1)*32+q*4+0]);
            float v1 = silu_f(__uint_as_float(d1[q*4+1]) + s_eb2[(c0+1)*32+q*4+1]);
            float v2 = silu_f(__uint_as_float(d1[q*4+2]) + s_eb2[(c0+1)*32+q*4+2]);
            float v3 = silu_f(__uint_as_float(d1[q*4+3]) + s_eb2[(c0+1)*32+q*4+3]);
            asm volatile("red.global.add.v4.f32 [%0], {%1,%2,%3,%4};"
                         :: "l"(aggp + (c0 + 1) * 32 + q * 4),
                            "f"(v0), "f"(v1), "f"(v2), "f"(v3) : "memory");
        }
    };

    // prologue: gather tile0, then MMA1(tile0) -> D1A
    if (wid < 4 && blockIdx.x < NTILES) { gather(blockIdx.x); FENCE_PROXY_ASYNC(); }
    __syncthreads();
    if (wid == 8 && blockIdx.x < NTILES) {
        TC_FENCE_AFTER();
        if (elect_one()) {
            #pragma unroll 1
            for (int s = 0; s < 17; ++s)
                TC_MMA_SS(tbase + TMEM_D1A, a1d + koff(s), w1d + koff(s), s > 0);
            TC_COMMIT(mbar1);
        }
    }

    int ph1 = 0, ph2 = 0, buf = 0;
    bool first = true;
    for (int tile = blockIdx.x; tile < NTILES; tile += nblocks) {
        const bool has_next = (tile + nblocks < NTILES);
        const uint32_t d1base = tbase + (buf ? TMEM_D1B : TMEM_D1A);

        if (wid < 4) {
            // ---- G-warps ----
            MBAR_WAIT(mbar1, ph1);          // MMA1(t) done -> A1 SMEM free
            if (has_next) {
                gather(tile + nblocks); FENCE_PROXY_ASYNC();
                NAMED_ARRIVE(2, 160);
            }
            MBAR_WAIT(mbar2, ph2);          // MMA2(t) done -> D2 ready
            TC_FENCE_AFTER();
            e2_half(tile, 2);
            TC_FENCE_BEFORE();
            NAMED_ARRIVE(4, 160);           // D2 G-half reads done
        } else if (wid < 8) {
            // ---- C-warps: E1 then E2 low half ----
            MBAR_WAIT(mbar1, ph1);          // D1[buf] ready
            TC_FENCE_AFTER();
            #pragma unroll 1
            for (int half = 0; half < 2; ++half) {
                uint32_t d0[32], d1[32], a0[16], a1r[16];
                const int c0 = half * 2;
                TC_LD_X32(d0, d1base + c0 * 32);
                TC_LD_X32(d1, d1base + (c0 + 1) * 32);
                TC_WAIT_LD();
                #pragma unroll
                for (int m = 0; m < 16; ++m) {
                    float v0 = silu_f(__uint_as_float(d0[2*m])   + s_eb1[c0*32 + 2*m]);
                    float v1 = silu_f(__uint_as_float(d0[2*m+1]) + s_eb1[c0*32 + 2*m+1]);
                    a0[m] = pack_bf16x2(v0, v1);
                }
                #pragma unroll
                for (int m = 0; m < 16; ++m) {
                    float v0 = silu_f(__uint_as_float(d1[2*m])   + s_eb1[(c0+1)*32 + 2*m]);
                    float v1 = silu_f(__uint_as_float(d1[2*m+1]) + s_eb1[(c0+1)*32 + 2*m+1]);
                    a1r[m] = pack_bf16x2(v0, v1);
                }
                const uint32_t wo = (uint32_t)(wid & 3) << 21;
                TC_ST_X16(tbase + TMEM_A2 + c0 * 16 + wo, a0);
                TC_ST_X16(tbase + TMEM_A2 + (c0 + 1) * 16 + wo, a1r);
            }
            TC_WAIT_ST();
            TC_FENCE_BEFORE();
            NAMED_ARRIVE(3, 160);           // E1 done: A2 ready, D1[buf] reads done
            MBAR_WAIT(mbar2, ph2);
            TC_FENCE_AFTER();
            e2_half(tile, 0);
            TC_FENCE_BEFORE();
        } else {
            // ---- MMA warp ----
            if (has_next) {
                NAMED_BAR(2, 160);          // gather(t+1) landed in A1
                TC_FENCE_AFTER();
                if (elect_one()) {
                    const uint32_t dnext = tbase + (buf ? TMEM_D1A : TMEM_D1B);
                    #pragma unroll 1
                    for (int s = 0; s < 17; ++s)
                        TC_MMA_SS(dnext, a1d + koff(s), w1d + koff(s), s > 0);
                    TC_COMMIT(mbar1);       // fires mbar1 for iteration t+1
                }
            }
            NAMED_BAR(3, 160);              // E1(t) done: A2 ready
            if (!first) NAMED_BAR(4, 160);  // G-half of E2(t-1) done: D2 free
            TC_FENCE_AFTER();
            if (elect_one()) {
                #pragma unroll 1
                for (int s = 0; s < 8; ++s)
                    TC_MMA_TS(tbase + TMEM_D2, tbase + TMEM_A2 + s * 8,
                              w2d + koff(s), s > 0);
                TC_COMMIT(mbar2);
            }
        }
        ph1 ^= 1; ph2 ^= 1; buf ^= 1; first = false;
    }

    __syncthreads();
    if (wid == 0) { TC_RELINQ(); TC_DEALLOC(tbase, 512); }

#else
    // plain-sm_103 fallback (never selected on GB300)
    const int tid = threadIdx.x;
    if (tid >= TM) return;
    for (int tile = blockIdx.x; tile < NTILES; tile += nblocks) {
        const int e = tile * TM + tid;
        const int r = g_row[e], c = g_col[e];
        float a[K1];
        #pragma unroll 4
        for (int j = 0; j < D; ++j) { a[j] = x[(size_t)r * D + j]; a[D + j] = x[(size_t)c * D + j]; }
        #pragma unroll
        for (int j = 0; j < DE; ++j) a[2 * D + j] = ea[(size_t)e * DE + j];
        float h[D];
        for (int n = 0; n < D; ++n) {
            float s = eb1[n];
            for (int k = 0; k < K1; ++k) s = fmaf(a[k], eW1raw[(size_t)k * D + n], s);
            h[n] = silu_f(s);
        }
        for (int n = 0; n < D; ++n) {
            float s = eb2[n];
            for (int k = 0; k < D; ++k) s = fmaf(h[k], eW2raw[(size_t)k * D + n], s);
            atomicAdd(g_agg + (size_t)r * D + n, silu_f(s));
        }
    }
#endif
}

// ---------------- fused node kernel (tcgen05 tf32, TS mode) ---------------
__global__ __launch_bounds__(128, 1) void k_node_fused(
    const float* __restrict__ x,
    const float* __restrict__ nb1, const float* __restrict__ nb2,
    const float* __restrict__ nW1raw, const float* __restrict__ nW2raw,
    float* __restrict__ out, int nblocks)
{
#if defined(__CUDA_ARCH__) && defined(__CUDA_ARCH_FEAT_SM103_ALL)
    extern __shared__ uint32_t dsm[];
    __shared__ float s_b1[D], s_b2[D];
    __shared__ uint32_t s_tmem[1];
    __shared__ __align__(8) unsigned long long s_mbar;

    const int tid = threadIdx.x;
    const int wid = tid >> 5;
    const int lane = tid & 31;
    const uint32_t woff = (uint32_t)wid << 21;

    const uint32_t dyn_base = smem_u32(dsm);
    const uint32_t ws1 = (dyn_base + 1023u) & ~1023u;
    const uint32_t ws2 = ws1 + NW1_WORDS * 4;
    uint32_t* w1p = dsm + ((ws1 - dyn_base) >> 2);

    {
        uint4* dst = (uint4*)w1p; const uint4* src = (const uint4*)g_NW1B;
        for (int i = tid; i < (NW1_WORDS + NW2_WORDS) / 4; i += 128) dst[i] = src[i];
        if (tid < D) { s_b1[tid] = nb1[tid]; s_b2[tid] = nb2[tid]; }
    }
    if (wid == 0) TC_ALLOC(smem_u32(s_tmem), 512);
    if (tid == 0) MBAR_INIT(smem_u32(&s_mbar), 1);
    __syncthreads();
    const uint32_t tbase = s_tmem[0];
    const uint32_t mbar = smem_u32(&s_mbar);
    const uint64_t w1d = mk_desc(ws1);
    const uint64_t w2d = mk_desc(ws2);

    int ph = 0;
    for (int tile = blockIdx.x; tile < NNT; tile += nblocks) {
        __syncthreads();

        {
            int n = tile * 128 + tid;
            if (n >= N_NODES) n = N_NODES - 1;
            const float4* xr = (const float4*)(x + (size_t)n * D);
            const float4* ar = (const float4*)(g_agg + (size_t)n * D);
            uint32_t a[32];
            #pragma unroll 1
            for (int ch = 0; ch < 4; ++ch) {
                #pragma unroll
                for (int q = 0; q < 8; ++q) {
                    float4 v = xr[ch * 8 + q];
                    a[q*4+0] = f2tf32(v.x); a[q*4+1] = f2tf32(v.y);
                    a[q*4+2] = f2tf32(v.z); a[q*4+3] = f2tf32(v.w);
                }
                TC_ST_X32(tbase + ch * 32 + woff, a);
            }
            #pragma unroll 1
            for (int ch = 0; ch < 4; ++ch) {
                #pragma unroll
                for (int q = 0; q < 8; ++q) {
                    float4 v = ar[ch * 8 + q];
                    a[q*4+0] = f2tf32(v.x); a[q*4+1] = f2tf32(v.y);
                    a[q*4+2] = f2tf32(v.z); a[q*4+3] = f2tf32(v.w);
                }
                TC_ST_X32(tbase + 128 + ch * 32 + woff, a);
            }
        }
        TC_WAIT_ST();
        TC_FENCE_BEFORE();
        __syncthreads();

        if (wid == 0) {
            TC_FENCE_AFTER();
            if (elect_one()) {
                #pragma unroll 1
                for (int s = 0; s < 32; ++s)
                    TC_MMA_TF32_TS(tbase + 256, tbase + s * 8, w1d + koff(s), s > 0);
                TC_COMMIT(mbar);
            }
        }
        MBAR_WAIT(mbar, ph); ph ^= 1;
        TC_FENCE_AFTER();

        #pragma unroll 1
        for (int ch = 0; ch < 4; ++ch) {
            uint32_t dreg[32], areg[32];
            TC_LD_X32(dreg, tbase + 256 + ch * 32);
            TC_WAIT_LD();
            #pragma unroll
            for (int j = 0; j < 32; ++j)
                areg[j] = f2tf32(silu_f(__uint_as_float(dreg[j]) + s_b1[ch * 32 + j]));
            TC_ST_X32(tbase + ch * 32 + woff, areg);
        }
        TC_WAIT_ST();
        TC_FENCE_BEFORE();
        __syncthreads();

        if (wid == 0) {
            TC_FENCE_AFTER();
            if (elect_one()) {
                #pragma unroll 1
                for (int s = 0; s < 16; ++s)
                    TC_MMA_TF32_TS(tbase + 128, tbase + s * 8, w2d + koff(s), s > 0);
                TC_COMMIT(mbar);
            }
        }
        MBAR_WAIT(mbar, ph); ph ^= 1;
        TC_FENCE_AFTER();

        {
            const int n = tile * 128 + wid * 32 + lane;
            const bool valid = (n < N_NODES);
            const float4* xr = (const float4*)(x + (size_t)n * D);
            float4* orow = (float4*)(out + (size_t)n * D);
            #pragma unroll 1
            for (int ch = 0; ch < 4; ++ch) {
                uint32_t dreg[32];
                TC_LD_X32(dreg, tbase + 128 + ch * 32);
                TC_WAIT_LD();
                if (valid) {
                    #pragma unroll
                    for (int q = 0; q < 8; ++q) {
                        float4 xv = xr[ch * 8 + q];
                        float4 o;
                        o.x = xv.x + __uint_as_float(dreg[q*4+0]) + s_b2[ch*32+q*4+0];
                        o.y = xv.y + __uint_as_float(dreg[q*4+1]) + s_b2[ch*32+q*4+1];
                        o.z = xv.z + __uint_as_float(dreg[q*4+2]) + s_b2[ch*32+q*4+2];
                        o.w = xv.w + __uint_as_float(dreg[q*4+3]) + s_b2[ch*32+q*4+3];
                        orow[ch * 8 + q] = o;
                    }
                }
            }
            TC_FENCE_BEFORE();
        }
    }

    __syncthreads();
    if (wid == 0) { TC_RELINQ(); TC_DEALLOC(tbase, 512); }

#else
    const int tid = threadIdx.x;
    for (int n = blockIdx.x * 128 + tid; n < N_NODES; n += nblocks * 128) {
        float t[D];
        for (int o = 0; o < D; ++o) {
            float s = nb1[o];
            for (int k = 0; k < D; ++k) {
                s = fmaf(x[(size_t)n * D + k], nW1raw[(size_t)k * D + o], s);
                s = fmaf(g_agg[(size_t)n * D + k], nW1raw[(size_t)(D + k) * D + o], s);
            }
            t[o] = silu_f(s);
        }
        for (int o = 0; o < D; ++o) {
            float s = nb2[o];
            for (int k = 0; k < D; ++k) s = fmaf(t[k], nW2raw[(size_t)k * D + o], s);
            out[(size_t)n * D + o] = x[(size_t)n * D + o] + s;
        }
    }
#endif
}

// ---------------- launch --------------------------------------------------
extern "C" void kernel_launch(void* const* d_in, const int* in_sizes, int n_in,
                              void* d_out, int out_size)
{
    const float* x   = (const float*)d_in[0];
    const void*  ei  = d_in[1];
    const float* ea  = (const float*)d_in[2];
    const float* eW1 = (const float*)d_in[3];
    const float* eb1 = (const float*)d_in[4];
    const float* eW2 = (const float*)d_in[5];
    const float* eb2 = (const float*)d_in[6];
    const float* nW1 = (const float*)d_in[7];
    const float* nb1 = (const float*)d_in[8];
    const float* nW2 = (const float*)d_in[9];
    const float* nb2 = (const float*)d_in[10];
    float* out = (float*)d_out;

    int sms = 148;
    cudaDeviceGetAttribute(&sms, cudaDevAttrMultiProcessorCount, 0);

    const int s_edge = 1024 + W1B_BYTES + W2B_BYTES + A1B_BYTES;
    const int s_node = 1024 + (NW1_WORDS + NW2_WORDS) * 4;

    cudaFuncSetAttribute(k_edge_fused, cudaFuncAttributeMaxDynamicSharedMemorySize, s_edge);
    cudaFuncSetAttribute(k_node_fused, cudaFuncAttributeMaxDynamicSharedMemorySize, s_node);

    const int prep_elems = 128 * K1PAD + 128 * 128 + 128 * 256 + 128 * 128;
    const size_t cz = (size_t)N_NODES * D;

    k_detect<<<1, 1>>>((const int*)ei);
    k_convert_zero<<<(int)((cz + 255) / 256), 256>>>(ei);
    k_prep<<<(prep_elems + 255) / 256, 256>>>(eW1, eW2, nW1, nW2);
    k_edge_fused<<<sms, 288, s_edge>>>(x, ea, eb1, eb2, eW1, eW2, sms);
    k_node_fused<<<sms, 128, s_node>>>(x, nb1, nb2, nW1, nW2, out, sms);
}

// round 10
// speedup vs baseline: 1.0757x; 1.0757x over previous
#include <cuda_runtime.h>
#include <cuda_bf16.h>
#include <cstdint>

#define N_NODES 50000
#define N_EDGES 800000
#define D 128
#define DE 16
#define K1 272
#define K1PAD 320
#define TM 128
#define NTILES (N_EDGES / TM)           // 6250
#define NNT ((N_NODES + 127) / 128)     // 391

#define W1B_BYTES (128 * K1PAD * 2)   // 81920
#define W2B_BYTES (128 * 128 * 2)     // 32768
#define A1B_BYTES (128 * K1PAD * 2)   // 81920
#define NW1_WORDS (256 * 128)
#define NW2_WORDS (128 * 128)

// edge TMEM
#define TMEM_D1 0
#define TMEM_D2 128
#define TMEM_A2 256

#define IDESC_BF16 0x8200490u
#define IDESC_TF32 0x8200910u

// ---------------- scratch -----------------------------------------------
__device__ int      g_is64;
__device__ int      g_row[N_EDGES];
__device__ int      g_col[N_EDGES];
__device__ float    g_agg[(size_t)N_NODES * D];
__device__ uint16_t g_W1B[W1B_BYTES / 2];
__device__ uint16_t g_W2B[W2B_BYTES / 2];
__device__ uint32_t g_NW1B[NW1_WORDS];
__device__ uint32_t g_NW2B[NW2_WORDS];

// silu via tanh.approx: 1 MUFU + FMA (halves MUFU pressure vs ex2+rcp)
__device__ __forceinline__ float silu_f(float v) {
    float t;
    asm("tanh.approx.f32 %0, %1;" : "=f"(t) : "f"(0.5f * v));
    return v * fmaf(0.5f, t, 0.5f);
}
__device__ __forceinline__ uint32_t smem_u32(const void* p) {
    uint32_t a;
    asm("{ .reg .u64 t; cvta.to.shared.u64 t, %1; cvt.u32.u64 %0, t; }"
        : "=r"(a) : "l"(p));
    return a;
}
__device__ __forceinline__ uint32_t pack_bf16x2(float lo, float hi) {
    uint32_t d;
    asm("cvt.rn.bf16x2.f32 %0, %1, %2;" : "=r"(d) : "f"(hi), "f"(lo));
    return d;
}
__device__ __forceinline__ uint16_t bf16_bits(float v) {
    __nv_bfloat16 b = __float2bfloat16(v);
    return *reinterpret_cast<uint16_t*>(&b);
}
__device__ __forceinline__ uint32_t f2tf32(float f) {
    uint32_t u;
    asm("cvt.rna.tf32.f32 %0, %1;" : "=r"(u) : "f"(f));
    return u;
}
__device__ __forceinline__ void sts8(uint32_t addr, uint32_t a, uint32_t b) {
    asm volatile("st.shared.v2.b32 [%0], {%1, %2};" :: "r"(addr), "r"(a), "r"(b) : "memory");
}
__device__ __forceinline__ uint32_t abyte(int row, int k) {
    return (uint32_t)((((row >> 3) + ((k >> 6) << 4)) << 10) | ((row & 7) << 7) | ((k & 63) << 1));
}
__device__ __forceinline__ uint32_t abyte32(int row, int k) {
    return (uint32_t)((((row >> 3) + ((k >> 5) << 4)) << 10) | ((row & 7) << 7) | ((k & 31) << 2));
}
__device__ __forceinline__ uint32_t swz(uint32_t b) {
    return b ^ ((b >> 3) & 0x70);
}

#if defined(__CUDA_ARCH__) && defined(__CUDA_ARCH_FEAT_SM103_ALL)

__device__ __forceinline__ uint32_t elect_one() {
    uint32_t pred;
    asm volatile("{\n\t.reg .pred p;\n\telect.sync _|p, 0xFFFFFFFF;\n\t"
                 "selp.b32 %0, 1, 0, p;\n\t}" : "=r"(pred));
    return pred;
}

#define TC_ALLOC(smemaddr, n) \
    asm volatile("tcgen05.alloc.cta_group::1.sync.aligned.shared::cta.b32 [%0], %1;" \
                 :: "r"(smemaddr), "r"((uint32_t)(n)) : "memory")
#define TC_RELINQ() \
    asm volatile("tcgen05.relinquish_alloc_permit.cta_group::1.sync.aligned;")
#define TC_DEALLOC(tmem, n) \
    asm volatile("tcgen05.dealloc.cta_group::1.sync.aligned.b32 %0, %1;" \
                 :: "r"(tmem), "r"((uint32_t)(n)))
#define TC_WAIT_ST() asm volatile("tcgen05.wait::st.sync.aligned;" ::: "memory")
#define TC_WAIT_LD() asm volatile("tcgen05.wait::ld.sync.aligned;" ::: "memory")
#define TC_FENCE_BEFORE() asm volatile("tcgen05.fence::before_thread_sync;" ::: "memory")
#define TC_FENCE_AFTER()  asm volatile("tcgen05.fence::after_thread_sync;" ::: "memory")
#define TC_COMMIT(mbar) \
    asm volatile("tcgen05.commit.cta_group::1.mbarrier::arrive::one.shared::cluster.b64 [%0];" \
                 :: "r"(mbar) : "memory")
#define MBAR_INIT(mbar, cnt) \
    asm volatile("mbarrier.init.shared.b64 [%0], %1;" :: "r"(mbar), "r"((uint32_t)(cnt)) : "memory")
#define FENCE_PROXY_ASYNC() \
    asm volatile("fence.proxy.async.shared::cta;" ::: "memory")
#define NAMED_BAR(id, n) \
    asm volatile("bar.sync %0, %1;" :: "r"(id), "r"(n) : "memory")
#define NAMED_ARRIVE(id, n) \
    asm volatile("bar.arrive %0, %1;" :: "r"(id), "r"(n) : "memory")

#define MBAR_WAIT(mbar, ph) do {                                             \
    uint32_t _m = (mbar), _p = (uint32_t)(ph), _d;                           \
    asm volatile("{\n\t.reg .pred p;\n\t"                                    \
        "mbarrier.try_wait.parity.acquire.cta.shared::cta.b64 p, [%1], %2;\n\t" \
        "selp.b32 %0, 1, 0, p;\n\t}" : "=r"(_d) : "r"(_m), "r"(_p) : "memory"); \
    if (!_d) {                                                               \
        asm volatile("{\n\t.reg .pred P1;\n\t"                               \
            "WL_%=:\n\t"                                                     \
            "mbarrier.try_wait.parity.acquire.cta.shared::cta.b64 P1, [%0], %1, 0x989680;\n\t" \
            "@P1 bra.uni WD_%=;\n\t"                                         \
            "bra.uni WL_%=;\n\t"                                             \
            "WD_%=:\n\t}" :: "r"(_m), "r"(_p) : "memory");                   \
    }                                                                        \
} while (0)

#define TC_MMA_SS(dtm, adesc, bdesc, en) do {                                \
    uint32_t _e = (en) ? 1u : 0u;                                            \
    asm volatile("{\n\t.reg .pred p;\n\t"                                    \
        "setp.ne.u32 p, %5, 0;\n\t"                                          \
        "tcgen05.mma.cta_group::1.kind::f16 [%0], %1, %2, %3, {%4, %4, %4, %4}, p;\n\t" \
        "}" :: "r"(dtm), "l"(adesc), "l"(bdesc), "r"(IDESC_BF16),            \
               "r"(0u), "r"(_e) : "memory");                                 \
} while (0)

#define TC_MMA_TS(dtm, atm, bdesc, en) do {                                  \
    uint32_t _e = (en) ? 1u : 0u;                                            \
    asm volatile("{\n\t.reg .pred p;\n\t"                                    \
        "setp.ne.u32 p, %5, 0;\n\t"                                          \
        "tcgen05.mma.cta_group::1.kind::f16 [%0], [%1], %2, %3, {%4, %4, %4, %4}, p;\n\t" \
        "}" :: "r"(dtm), "r"(atm), "l"(bdesc), "r"(IDESC_BF16),              \
               "r"(0u), "r"(_e) : "memory");                                 \
} while (0)

#define TC_MMA_TF32_TS(dtm, atm, bdesc, en) do {                             \
    uint32_t _e = (en) ? 1u : 0u;                                            \
    asm volatile("{\n\t.reg .pred p;\n\t"                                    \
        "setp.ne.u32 p, %5, 0;\n\t"                                          \
        "tcgen05.mma.cta_group::1.kind::tf32 [%0], [%1], %2, %3, {%4, %4, %4, %4}, p;\n\t" \
        "}" :: "r"(dtm), "r"(atm), "l"(bdesc), "r"(IDESC_TF32),              \
               "r"(0u), "r"(_e) : "memory");                                 \
} while (0)

#define TC_ST_X16(tmem_addr, r)                                              \
    asm volatile("tcgen05.st.sync.aligned.32x32b.x16.b32 [%0], "             \
        "{%1, %2, %3, %4, %5, %6, %7, %8, "                                  \
        " %9, %10, %11, %12, %13, %14, %15, %16};"                           \
        :: "r"(tmem_addr),                                                   \
           "r"((r)[0]),  "r"((r)[1]),  "r"((r)[2]),  "r"((r)[3]),            \
           "r"((r)[4]),  "r"((r)[5]),  "r"((r)[6]),  "r"((r)[7]),            \
           "r"((r)[8]),  "r"((r)[9]),  "r"((r)[10]), "r"((r)[11]),           \
           "r"((r)[12]), "r"((r)[13]), "r"((r)[14]), "r"((r)[15])            \
        : "memory")

#define TC_ST_X32(tmem_addr, r)                                              \
    asm volatile("tcgen05.st.sync.aligned.32x32b.x32.b32 [%0], "             \
        "{%1, %2, %3, %4, %5, %6, %7, %8, "                                  \
        " %9, %10, %11, %12, %13, %14, %15, %16, "                           \
        " %17, %18, %19, %20, %21, %22, %23, %24, "                          \
        " %25, %26, %27, %28, %29, %30, %31, %32};"                          \
        :: "r"(tmem_addr),                                                   \
           "r"((r)[0]),  "r"((r)[1]),  "r"((r)[2]),  "r"((r)[3]),            \
           "r"((r)[4]),  "r"((r)[5]),  "r"((r)[6]),  "r"((r)[7]),            \
           "r"((r)[8]),  "r"((r)[9]),  "r"((r)[10]), "r"((r)[11]),           \
           "r"((r)[12]), "r"((r)[13]), "r"((r)[14]), "r"((r)[15]),           \
           "r"((r)[16]), "r"((r)[17]), "r"((r)[18]), "r"((r)[19]),           \
           "r"((r)[20]), "r"((r)[21]), "r"((r)[22]), "r"((r)[23]),           \
           "r"((r)[24]), "r"((r)[25]), "r"((r)[26]), "r"((r)[27]),           \
           "r"((r)[28]), "r"((r)[29]), "r"((r)[30]), "r"((r)[31])            \
        : "memory")

#define TC_LD_X32(r, tmem_addr)                                              \
    asm volatile("tcgen05.ld.sync.aligned.32x32b.x32.b32 "                   \
        "{%0, %1, %2, %3, %4, %5, %6, %7, "                                  \
        " %8, %9, %10, %11, %12, %13, %14, %15, "                            \
        " %16, %17, %18, %19, %20, %21, %22, %23, "                          \
        " %24, %25, %26, %27, %28, %29, %30, %31}, [%32];"                   \
        : "=r"((r)[0]),  "=r"((r)[1]),  "=r"((r)[2]),  "=r"((r)[3]),         \
          "=r"((r)[4]),  "=r"((r)[5]),  "=r"((r)[6]),  "=r"((r)[7]),         \
          "=r"((r)[8]),  "=r"((r)[9]),  "=r"((r)[10]), "=r"((r)[11]),        \
          "=r"((r)[12]), "=r"((r)[13]), "=r"((r)[14]), "=r"((r)[15]),        \
          "=r"((r)[16]), "=r"((r)[17]), "=r"((r)[18]), "=r"((r)[19]),        \
          "=r"((r)[20]), "=r"((r)[21]), "=r"((r)[22]), "=r"((r)[23]),        \
          "=r"((r)[24]), "=r"((r)[25]), "=r"((r)[26]), "=r"((r)[27]),        \
          "=r"((r)[28]), "=r"((r)[29]), "=r"((r)[30]), "=r"((r)[31])         \
        : "r"(tmem_addr))

static constexpr unsigned long long SMEM_DESC_BASE =
    (2ull << 61) | (1ull << 46) | (64ull << 32) | (1ull << 16);
__device__ __forceinline__ uint64_t mk_desc(uint32_t addr) {
    return SMEM_DESC_BASE | ((uint64_t)(addr >> 4) & 0x3FFF);
}
__device__ __forceinline__ uint64_t koff(int s) {
    return (uint64_t)((s >> 2) * 1024 + (s & 3) * 2);
}

#endif // sm_103a device helpers

// ---------------- small kernels ------------------------------------------
__global__ void k_detect(const int* ei32) {
    if (blockIdx.x == 0 && threadIdx.x == 0) {
        int is64 = 1;
        #pragma unroll 1
        for (int i = 0; i < 64; ++i)
            if (ei32[2 * i + 1] != 0) { is64 = 0; break; }
        g_is64 = is64;
    }
}
__global__ void k_convert_zero(const void* ei) {
    size_t i = (size_t)blockIdx.x * blockDim.x + threadIdx.x;
    if (i < N_EDGES) {
        if (g_is64) {
            const long long* p = (const long long*)ei;
            g_row[i] = (int)p[i];
            g_col[i] = (int)p[(size_t)N_EDGES + i];
        } else {
            const int* p = (const int*)ei;
            g_row[i] = p[i];
            g_col[i] = p[N_EDGES + i];
        }
    }
    if (i < (size_t)N_NODES * D) g_agg[i] = 0.0f;
}
__global__ void k_prep(const float* __restrict__ W1, const float* __restrict__ W2,
                       const float* __restrict__ NW1, const float* __restrict__ NW2) {
    int i = blockIdx.x * blockDim.x + threadIdx.x;
    if (i < 128 * K1PAD) {
        int n = i / K1PAD, k = i % K1PAD;
        float v = (k < K1) ? W1[(size_t)k * 128 + n] : 0.0f;
        g_W1B[swz(abyte(n, k)) >> 1] = bf16_bits(v);
        return;
    }
    i -= 128 * K1PAD;
    if (i < 128 * 128) {
        int n = i / 128, k = i % 128;
        g_W2B[swz(abyte(n, k)) >> 1] = bf16_bits(W2[(size_t)k * 128 + n]);
        return;
    }
    i -= 128 * 128;
    if (i < 128 * 256) {
        int n = i / 256, k = i % 256;
        g_NW1B[swz(abyte32(n, k)) >> 2] = f2tf32(NW1[(size_t)k * 128 + n]);
        return;
    }
    i -= 128 * 256;
    if (i < 128 * 128) {
        int n = i / 128, k = i % 128;
        g_NW2B[swz(abyte32(n, k)) >> 2] = f2tf32(NW2[(size_t)k * 128 + n]);
    }
}

// ---------------- fused edge kernel (R8 structure + tanh silu) ------------
__global__ __launch_bounds__(256, 1) void k_edge_fused(
    const float* __restrict__ x, const float* __restrict__ ea,
    const float* __restrict__ eb1, const float* __restrict__ eb2,
    const float* __restrict__ eW1raw, const float* __restrict__ eW2raw,
    int nblocks)
{
#if defined(__CUDA_ARCH__) && defined(__CUDA_ARCH_FEAT_SM103_ALL)
    extern __shared__ uint32_t dsm[];
    __shared__ float s_eb1[D], s_eb2[D];
    __shared__ uint32_t s_tmem[1];
    __shared__ __align__(8) unsigned long long s_mbar1, s_mbar2;

    const int tid = threadIdx.x;
    const int wid = tid >> 5;
    const int lane = tid & 31;

    const uint32_t dyn_base = smem_u32(dsm);
    const uint32_t ws1 = (dyn_base + 1023u) & ~1023u;
    const uint32_t ws2 = ws1 + W1B_BYTES;
    const uint32_t wsA = ws2 + W2B_BYTES;
    uint32_t* w1p = dsm + ((ws1 - dyn_base) >> 2);

    {
        uint4* dst = (uint4*)w1p; const uint4* src = (const uint4*)g_W1B;
        for (int i = tid; i < (W1B_BYTES + W2B_BYTES) / 16; i += 256) dst[i] = src[i];
        if (tid < D) { s_eb1[tid] = eb1[tid]; s_eb2[tid] = eb2[tid]; }
        for (int i = tid; i < 128 * 12; i += 256) {
            int row = i / 12, j = i % 12;
            sts8(wsA + swz(abyte(row, 272 + j * 4)), 0u, 0u);
        }
    }
    if (wid == 0) TC_ALLOC(smem_u32(s_tmem), 512);
    if (tid == 0) { MBAR_INIT(smem_u32(&s_mbar1), 1); MBAR_INIT(smem_u32(&s_mbar2), 1); }
    __syncthreads();
    const uint32_t tbase = s_tmem[0];
    const uint32_t mbar1 = smem_u32(&s_mbar1);
    const uint32_t mbar2 = smem_u32(&s_mbar2);
    const uint64_t a1d = mk_desc(wsA);
    const uint64_t w1d = mk_desc(ws1);
    const uint64_t w2d = mk_desc(ws2);

    auto gather = [&](int tile) {
        const int gw = wid;
        const int e0 = tile * TM + gw * 32;
        const int myr = g_row[e0 + lane];
        const int myc = g_col[e0 + lane];
        #pragma unroll 8
        for (int i = 0; i < 32; ++i) {
            const int el = gw * 32 + i;
            const int r = __shfl_sync(0xffffffffu, myr, i);
            const int c = __shfl_sync(0xffffffffu, myc, i);
            float4 v = *(const float4*)(x + (size_t)r * D + lane * 4);
            sts8(wsA + swz(abyte(el, lane * 4)),
                 pack_bf16x2(v.x, v.y), pack_bf16x2(v.z, v.w));
            v = *(const float4*)(x + (size_t)c * D + lane * 4);
            sts8(wsA + swz(abyte(el, 128 + lane * 4)),
                 pack_bf16x2(v.x, v.y), pack_bf16x2(v.z, v.w));
        }
        #pragma unroll
        for (int i = 0; i < 4; ++i) {
            const int el = gw * 32 + i * 8 + (lane >> 2);
            const int e = tile * TM + el;
            float4 v = *(const float4*)(ea + (size_t)e * DE + (lane & 3) * 4);
            sts8(wsA + swz(abyte(el, 256 + (lane & 3) * 4)),
                 pack_bf16x2(v.x, v.y), pack_bf16x2(v.z, v.w));
        }
    };

    auto e2_half = [&](int tile, int c0) {
        const int e = tile * TM + (wid & 3) * 32 + lane;
        float* aggp = g_agg + (size_t)g_row[e] * D;
        uint32_t d0[32], d1[32];
        TC_LD_X32(d0, tbase + TMEM_D2 + c0 * 32);
        TC_LD_X32(d1, tbase + TMEM_D2 + (c0 + 1) * 32);
        TC_WAIT_LD();
        #pragma unroll
        for (int q = 0; q < 8; ++q) {
            float v0 = silu_f(__uint_as_float(d0[q*4+0]) + s_eb2[c0*32+q*4+0]);
            float v1 = silu_f(__uint_as_float(d0[q*4+1]) + s_eb2[c0*32+q*4+1]);
            float v2 = silu_f(__uint_as_float(d0[q*4+2]) + s_eb2[c0*32+q*4+2]);
            float v3 = silu_f(__uint_as_float(d0[q*4+3]) + s_eb2[c0*32+q*4+3]);
            asm volatile("red.global.add.v4.f32 [%0], {%1,%2,%3,%4};"
                         :: "l"(aggp + c0 * 32 + q * 4),
                            "f"(v0), "f"(v1), "f"(v2), "f"(v3) : "memory");
        }
        #pragma unroll
        for (int q = 0; q < 8; ++q) {
            float v0 = silu_f(__uint_as_float(d1[q*4+0]) + s_eb2[(c0+1)*32+q*4+0]);
            float v1 = silu_f(__uint_as_float(d1[q*4+1]) + s_eb2[(c0+1)*32+q*4+1]);
            float v2 = silu_f(__uint_as_float(d1[q*4+2]) + s_eb2[(c0+1)*32+q*4+2]);
            float v3 = silu_f(__uint_as_float(d1[q*4+3]) + s_eb2[(c0+1)*32+q*4+3]);
            asm volatile("red.global.add.v4.f32 [%0], {%1,%2,%3,%4};"
                         :: "l"(aggp + (c0 + 1) * 32 + q * 4),
                            "f"(v0), "f"(v1), "f"(v2), "f"(v3) : "memory");
        }
    };

    // prologue: gather tile0, then issue MMA1(tile0)
    if (wid < 4 && blockIdx.x < NTILES) { gather(blockIdx.x); FENCE_PROXY_ASYNC(); }
    __syncthreads();
    if (wid == 4 && blockIdx.x < NTILES) {
        TC_FENCE_AFTER();
        if (elect_one()) {
            #pragma unroll 1
            for (int s = 0; s < 17; ++s)
                TC_MMA_SS(tbase + TMEM_D1, a1d + koff(s), w1d + koff(s), s > 0);
            TC_COMMIT(mbar1);
        }
    }

    int ph1 = 0, ph2 = 0;
    for (int tile = blockIdx.x; tile < NTILES; tile += nblocks) {
        const bool has_next = (tile + nblocks < NTILES);

        if (wid < 4) {
            MBAR_WAIT(mbar1, ph1);
            if (has_next) {
                gather(tile + nblocks); FENCE_PROXY_ASYNC();
                NAMED_ARRIVE(2, 160);
            }
            MBAR_WAIT(mbar2, ph2);
            TC_FENCE_AFTER();
            e2_half(tile, 2);
            TC_FENCE_BEFORE();
        } else {
            MBAR_WAIT(mbar1, ph1);
            TC_FENCE_AFTER();

            // E1: D1 -> bias+silu -> A2
            #pragma unroll 1
            for (int half = 0; half < 2; ++half) {
                uint32_t d0[32], d1[32], a0[16], a1r[16];
                const int c0 = half * 2;
                TC_LD_X32(d0, tbase + TMEM_D1 + c0 * 32);
                TC_LD_X32(d1, tbase + TMEM_D1 + (c0 + 1) * 32);
                TC_WAIT_LD();
                #pragma unroll
                for (int m = 0; m < 16; ++m) {
                    float v0 = silu_f(__uint_as_float(d0[2*m])   + s_eb1[c0*32 + 2*m]);
                    float v1 = silu_f(__uint_as_float(d0[2*m+1]) + s_eb1[c0*32 + 2*m+1]);
                    a0[m] = pack_bf16x2(v0, v1);
                }
                #pragma unroll
                for (int m = 0; m < 16; ++m) {
                    float v0 = silu_f(__uint_as_float(d1[2*m])   + s_eb1[(c0+1)*32 + 2*m]);
                    float v1 = silu_f(__uint_as_float(d1[2*m+1]) + s_eb1[(c0+1)*32 + 2*m+1]);
                    a1r[m] = pack_bf16x2(v0, v1);
                }
                const uint32_t wo = (uint32_t)(wid & 3) << 21;
                TC_ST_X16(tbase + TMEM_A2 + c0 * 16 + wo, a0);
                TC_ST_X16(tbase + TMEM_A2 + (c0 + 1) * 16 + wo, a1r);
            }
            TC_WAIT_ST();
            TC_FENCE_BEFORE();
            NAMED_BAR(1, 128);     // E1 done: A2 ready, D1 free

            if (wid == 4) {
                TC_FENCE_AFTER();
                if (elect_one()) {
                    #pragma unroll 1
                    for (int s = 0; s < 8; ++s)
                        TC_MMA_TS(tbase + TMEM_D2, tbase + TMEM_A2 + s * 8,
                                  w2d + koff(s), s > 0);
                    TC_COMMIT(mbar2);
                }
                if (has_next) {
                    NAMED_BAR(2, 160);   // gather(t+1) complete
                    if (elect_one()) {
                        #pragma unroll 1
                        for (int s = 0; s < 17; ++s)
                            TC_MMA_SS(tbase + TMEM_D1, a1d + koff(s), w1d + koff(s), s > 0);
                        TC_COMMIT(mbar1);
                    }
                }
            }
            MBAR_WAIT(mbar2, ph2);
            TC_FENCE_AFTER();
            e2_half(tile, 0);
            TC_FENCE_BEFORE();
        }
        ph1 ^= 1; ph2 ^= 1;
    }

    __syncthreads();
    if (wid == 0) { TC_RELINQ(); TC_DEALLOC(tbase, 512); }

#else
    // plain-sm_103 fallback (never selected on GB300)
    const int tid = threadIdx.x;
    if (tid >= TM) return;
    for (int tile = blockIdx.x; tile < NTILES; tile += nblocks) {
        const int e = tile * TM + tid;
        const int r = g_row[e], c = g_col[e];
        float a[K1];
        #pragma unroll 4
        for (int j = 0; j < D; ++j) { a[j] = x[(size_t)r * D + j]; a[D + j] = x[(size_t)c * D + j]; }
        #pragma unroll
        for (int j = 0; j < DE; ++j) a[2 * D + j] = ea[(size_t)e * DE + j];
        float h[D];
        for (int n = 0; n < D; ++n) {
            float s = eb1[n];
            for (int k = 0; k < K1; ++k) s = fmaf(a[k], eW1raw[(size_t)k * D + n], s);
            h[n] = silu_f(s);
        }
        for (int n = 0; n < D; ++n) {
            float s = eb2[n];
            for (int k = 0; k < D; ++k) s = fmaf(h[k], eW2raw[(size_t)k * D + n], s);
            atomicAdd(g_agg + (size_t)r * D + n, silu_f(s));
        }
    }
#endif
}

// ---------------- fused node kernel (tcgen05 tf32, TS mode) ---------------
__global__ __launch_bounds__(128, 1) void k_node_fused(
    const float* __restrict__ x,
    const float* __restrict__ nb1, const float* __restrict__ nb2,
    const float* __restrict__ nW1raw, const float* __restrict__ nW2raw,
    float* __restrict__ out, int nblocks)
{
#if defined(__CUDA_ARCH__) && defined(__CUDA_ARCH_FEAT_SM103_ALL)
    extern __shared__ uint32_t dsm[];
    __shared__ float s_b1[D], s_b2[D];
    __shared__ uint32_t s_tmem[1];
    __shared__ __align__(8) unsigned long long s_mbar;

    const int tid = threadIdx.x;
    const int wid = tid >> 5;
    const int lane = tid & 31;
    const uint32_t woff = (uint32_t)wid << 21;

    const uint32_t dyn_base = smem_u32(dsm);
    const uint32_t ws1 = (dyn_base + 1023u) & ~1023u;
    const uint32_t ws2 = ws1 + NW1_WORDS * 4;
    uint32_t* w1p = dsm + ((ws1 - dyn_base) >> 2);

    {
        uint4* dst = (uint4*)w1p; const uint4* src = (const uint4*)g_NW1B;
        for (int i = tid; i < (NW1_WORDS + NW2_WORDS) / 4; i += 128) dst[i] = src[i];
        if (tid < D) { s_b1[tid] = nb1[tid]; s_b2[tid] = nb2[tid]; }
    }
    if (wid == 0) TC_ALLOC(smem_u32(s_tmem), 512);
    if (tid == 0) MBAR_INIT(smem_u32(&s_mbar), 1);
    __syncthreads();
    const uint32_t tbase = s_tmem[0];
    const uint32_t mbar = smem_u32(&s_mbar);
    const uint64_t w1d = mk_desc(ws1);
    const uint64_t w2d = mk_desc(ws2);

    int ph = 0;
    for (int tile = blockIdx.x; tile < NNT; tile += nblocks) {
        __syncthreads();

        {
            int n = tile * 128 + tid;
            if (n >= N_NODES) n = N_NODES - 1;
            const float4* xr = (const float4*)(x + (size_t)n * D);
            const float4* ar = (const float4*)(g_agg + (size_t)n * D);
            uint32_t a[32];
            #pragma unroll 1
            for (int ch = 0; ch < 4; ++ch) {
                #pragma unroll
                for (int q = 0; q < 8; ++q) {
                    float4 v = xr[ch * 8 + q];
                    a[q*4+0] = f2tf32(v.x); a[q*4+1] = f2tf32(v.y);
                    a[q*4+2] = f2tf32(v.z); a[q*4+3] = f2tf32(v.w);
                }
                TC_ST_X32(tbase + ch * 32 + woff, a);
            }
            #pragma unroll 1
            for (int ch = 0; ch < 4; ++ch) {
                #pragma unroll
                for (int q = 0; q < 8; ++q) {
                    float4 v = ar[ch * 8 + q];
                    a[q*4+0] = f2tf32(v.x); a[q*4+1] = f2tf32(v.y);
                    a[q*4+2] = f2tf32(v.z); a[q*4+3] = f2tf32(v.w);
                }
                TC_ST_X32(tbase + 128 + ch * 32 + woff, a);
            }
        }
        TC_WAIT_ST();
        TC_FENCE_BEFORE();
        __syncthreads();

        if (wid == 0) {
            TC_FENCE_AFTER();
            if (elect_one()) {
                #pragma unroll 1
                for (int s = 0; s < 32; ++s)
                    TC_MMA_TF32_TS(tbase + 256, tbase + s * 8, w1d + koff(s), s > 0);
                TC_COMMIT(mbar);
            }
        }
        MBAR_WAIT(mbar, ph); ph ^= 1;
        TC_FENCE_AFTER();

        #pragma unroll 1
        for (int ch = 0; ch < 4; ++ch) {
            uint32_t dreg[32], areg[32];
            TC_LD_X32(dreg, tbase + 256 + ch * 32);
            TC_WAIT_LD();
            #pragma unroll
            for (int j = 0; j < 32; ++j)
                areg[j] = f2tf32(silu_f(__uint_as_float(dreg[j]) + s_b1[ch * 32 + j]));
            TC_ST_X32(tbase + ch * 32 + woff, areg);
        }
        TC_WAIT_ST();
        TC_FENCE_BEFORE();
        __syncthreads();

        if (wid == 0) {
            TC_FENCE_AFTER();
            if (elect_one()) {
                #pragma unroll 1
                for (int s = 0; s < 16; ++s)
                    TC_MMA_TF32_TS(tbase + 128, tbase + s * 8, w2d + koff(s), s > 0);
                TC_COMMIT(mbar);
            }
        }
        MBAR_WAIT(mbar, ph); ph ^= 1;
        TC_FENCE_AFTER();

        {
            const int n = tile * 128 + wid * 32 + lane;
            const bool valid = (n < N_NODES);
            const float4* xr = (const float4*)(x + (size_t)n * D);
            float4* orow = (float4*)(out + (size_t)n * D);
            #pragma unroll 1
            for (int ch = 0; ch < 4; ++ch) {
                uint32_t dreg[32];
                TC_LD_X32(dreg, tbase + 128 + ch * 32);
                TC_WAIT_LD();
                if (valid) {
                    #pragma unroll
                    for (int q = 0; q < 8; ++q) {
                        float4 xv = xr[ch * 8 + q];
                        float4 o;
                        o.x = xv.x + __uint_as_float(dreg[q*4+0]) + s_b2[ch*32+q*4+0];
                        o.y = xv.y + __uint_as_float(dreg[q*4+1]) + s_b2[ch*32+q*4+1];
                        o.z = xv.z + __uint_as_float(dreg[q*4+2]) + s_b2[ch*32+q*4+2];
                        o.w = xv.w + __uint_as_float(dreg[q*4+3]) + s_b2[ch*32+q*4+3];
                        orow[ch * 8 + q] = o;
                    }
                }
            }
            TC_FENCE_BEFORE();
        }
    }

    __syncthreads();
    if (wid == 0) { TC_RELINQ(); TC_DEALLOC(tbase, 512); }

#else
    const int tid = threadIdx.x;
    for (int n = blockIdx.x * 128 + tid; n < N_NODES; n += nblocks * 128) {
        float t[D];
        for (int o = 0; o < D; ++o) {
            float s = nb1[o];
            for (int k = 0; k < D; ++k) {
                s = fmaf(x[(size_t)n * D + k], nW1raw[(size_t)k * D + o], s);
                s = fmaf(g_agg[(size_t)n * D + k], nW1raw[(size_t)(D + k) * D + o], s);
            }
            t[o] = silu_f(s);
        }
        for (int o = 0; o < D; ++o) {
            float s = nb2[o];
            for (int k = 0; k < D; ++k) s = fmaf(t[k], nW2raw[(size_t)k * D + o], s);
            out[(size_t)n * D + o] = x[(size_t)n * D + o] + s;
        }
    }
#endif
}

// ---------------- launch --------------------------------------------------
extern "C" void kernel_launch(void* const* d_in, const int* in_sizes, int n_in,
                              void* d_out, int out_size)
{
    const float* x   = (const float*)d_in[0];
    const void*  ei  = d_in[1];
    const float* ea  = (const float*)d_in[2];
    const float* eW1 = (const float*)d_in[3];
    const float* eb1 = (const float*)d_in[4];
    const float* eW2 = (const float*)d_in[5];
    const float* eb2 = (const float*)d_in[6];
    const float* nW1 = (const float*)d_in[7];
    const float* nb1 = (const float*)d_in[8];
    const float* nW2 = (const float*)d_in[9];
    const float* nb2 = (const float*)d_in[10];
    float* out = (float*)d_out;

    int sms = 148;
    cudaDeviceGetAttribute(&sms, cudaDevAttrMultiProcessorCount, 0);

    const int s_edge = 1024 + W1B_BYTES + W2B_BYTES + A1B_BYTES;
    const int s_node = 1024 + (NW1_WORDS + NW2_WORDS) * 4;

    cudaFuncSetAttribute(k_edge_fused, cudaFuncAttributeMaxDynamicSharedMemorySize, s_edge);
    cudaFuncSetAttribute(k_node_fused, cudaFuncAttributeMaxDynamicSharedMemorySize, s_node);

    const int prep_elems = 128 * K1PAD + 128 * 128 + 128 * 256 + 128 * 128;
    const size_t cz = (size_t)N_NODES * D;

    k_detect<<<1, 1>>>((const int*)ei);
    k_convert_zero<<<(int)((cz + 255) / 256), 256>>>(ei);
    k_prep<<<(prep_elems + 255) / 256, 256>>>(eW1, eW2, nW1, nW2);
    k_edge_fused<<<sms, 256, s_edge>>>(x, ea, eb1, eb2, eW1, eW2, sms);
    k_node_fused<<<sms, 128, s_node>>>(x, nb1, nb2, nW1, nW2, out, sms);
}

// round 12
// speedup vs baseline: 1.2161x; 1.1305x over previous
#include <cuda_runtime.h>
#include <cuda_bf16.h>
#include <cstdint>

#define N_NODES 50000
#define N_EDGES 800000
#define D 128
#define DE 16
#define K1 272
#define K1PAD 320
#define TM 128
#define NTILES (N_EDGES / TM)           // 6250
#define NNT ((N_NODES + 127) / 128)     // 391

#define W1B_BYTES (128 * K1PAD * 2)   // 81920
#define W2B_BYTES (128 * 128 * 2)     // 32768
#define A1B_BYTES (128 * K1PAD * 2)   // 81920
#define NW1_WORDS (256 * 128)
#define NW2_WORDS (128 * 128)

// edge TMEM
#define TMEM_D1 0
#define TMEM_D2 128
#define TMEM_A2 256

#define IDESC_BF16 0x8200490u
#define IDESC_TF32 0x8200910u

// ---------------- scratch -----------------------------------------------
__device__ int      g_is64;
__device__ int      g_row[N_EDGES];
__device__ int      g_col[N_EDGES];
__device__ float    g_agg[(size_t)N_NODES * D];
__device__ uint16_t g_W1B[W1B_BYTES / 2];
__device__ uint16_t g_W2B[W2B_BYTES / 2];
__device__ uint32_t g_NW1B[NW1_WORDS];
__device__ uint32_t g_NW2B[NW2_WORDS];

__device__ __forceinline__ float silu_f(float v) {
    float t;
    asm("tanh.approx.f32 %0, %1;" : "=f"(t) : "f"(0.5f * v));
    return v * fmaf(0.5f, t, 0.5f);
}
__device__ __forceinline__ uint32_t smem_u32(const void* p) {
    uint32_t a;
    asm("{ .reg .u64 t; cvta.to.shared.u64 t, %1; cvt.u32.u64 %0, t; }"
        : "=r"(a) : "l"(p));
    return a;
}
__device__ __forceinline__ uint32_t pack_bf16x2(float lo, float hi) {
    uint32_t d;
    asm("cvt.rn.bf16x2.f32 %0, %1, %2;" : "=r"(d) : "f"(hi), "f"(lo));
    return d;
}
__device__ __forceinline__ uint16_t bf16_bits(float v) {
    __nv_bfloat16 b = __float2bfloat16(v);
    return *reinterpret_cast<uint16_t*>(&b);
}
__device__ __forceinline__ uint32_t f2tf32(float f) {
    uint32_t u;
    asm("cvt.rna.tf32.f32 %0, %1;" : "=r"(u) : "f"(f));
    return u;
}
__device__ __forceinline__ void sts8(uint32_t addr, uint32_t a, uint32_t b) {
    asm volatile("st.shared.v2.b32 [%0], {%1, %2};" :: "r"(addr), "r"(a), "r"(b) : "memory");
}
__device__ __forceinline__ uint32_t abyte(int row, int k) {
    return (uint32_t)((((row >> 3) + ((k >> 6) << 4)) << 10) | ((row & 7) << 7) | ((k & 63) << 1));
}
__device__ __forceinline__ uint32_t abyte32(int row, int k) {
    return (uint32_t)((((row >> 3) + ((k >> 5) << 4)) << 10) | ((row & 7) << 7) | ((k & 31) << 2));
}
__device__ __forceinline__ uint32_t swz(uint32_t b) {
    return b ^ ((b >> 3) & 0x70);
}

#if defined(__CUDA_ARCH__) && defined(__CUDA_ARCH_FEAT_SM103_ALL)

__device__ __forceinline__ uint32_t elect_one() {
    uint32_t pred;
    asm volatile("{\n\t.reg .pred p;\n\telect.sync _|p, 0xFFFFFFFF;\n\t"
                 "selp.b32 %0, 1, 0, p;\n\t}" : "=r"(pred));
    return pred;
}

#define TC_ALLOC(smemaddr, n) \
    asm volatile("tcgen05.alloc.cta_group::1.sync.aligned.shared::cta.b32 [%0], %1;" \
                 :: "r"(smemaddr), "r"((uint32_t)(n)) : "memory")
#define TC_RELINQ() \
    asm volatile("tcgen05.relinquish_alloc_permit.cta_group::1.sync.aligned;")
#define TC_DEALLOC(tmem, n) \
    asm volatile("tcgen05.dealloc.cta_group::1.sync.aligned.b32 %0, %1;" \
                 :: "r"(tmem), "r"((uint32_t)(n)))
#define TC_WAIT_ST() asm volatile("tcgen05.wait::st.sync.aligned;" ::: "memory")
#define TC_WAIT_LD() asm volatile("tcgen05.wait::ld.sync.aligned;" ::: "memory")
#define TC_FENCE_BEFORE() asm volatile("tcgen05.fence::before_thread_sync;" ::: "memory")
#define TC_FENCE_AFTER()  asm volatile("tcgen05.fence::after_thread_sync;" ::: "memory")
#define TC_COMMIT(mbar) \
    asm volatile("tcgen05.commit.cta_group::1.mbarrier::arrive::one.shared::cluster.b64 [%0];" \
                 :: "r"(mbar) : "memory")
#define MBAR_INIT(mbar, cnt) \
    asm volatile("mbarrier.init.shared.b64 [%0], %1;" :: "r"(mbar), "r"((uint32_t)(cnt)) : "memory")
#define FENCE_PROXY_ASYNC() \
    asm volatile("fence.proxy.async.shared::cta;" ::: "memory")
#define NAMED_BAR(id, n) \
    asm volatile("bar.sync %0, %1;" :: "r"(id), "r"(n) : "memory")
#define NAMED_ARRIVE(id, n) \
    asm volatile("bar.arrive %0, %1;" :: "r"(id), "r"(n) : "memory")

#define MBAR_WAIT(mbar, ph) do {                                             \
    uint32_t _m = (mbar), _p = (uint32_t)(ph), _d;                           \
    asm volatile("{\n\t.reg .pred p;\n\t"                                    \
        "mbarrier.try_wait.parity.acquire.cta.shared::cta.b64 p, [%1], %2;\n\t" \
        "selp.b32 %0, 1, 0, p;\n\t}" : "=r"(_d) : "r"(_m), "r"(_p) : "memory"); \
    if (!_d) {                                                               \
        asm volatile("{\n\t.reg .pred P1;\n\t"                               \
            "WL_%=:\n\t"                                                     \
            "mbarrier.try_wait.parity.acquire.cta.shared::cta.b64 P1, [%0], %1, 0x989680;\n\t" \
            "@P1 bra.uni WD_%=;\n\t"                                         \
            "bra.uni WL_%=;\n\t"                                             \
            "WD_%=:\n\t}" :: "r"(_m), "r"(_p) : "memory");                   \
    }                                                                        \
} while (0)

#define TC_MMA_SS(dtm, adesc, bdesc, en) do {                                \
    uint32_t _e = (en) ? 1u : 0u;                                            \
    asm volatile("{\n\t.reg .pred p;\n\t"                                    \
        "setp.ne.u32 p, %5, 0;\n\t"                                          \
        "tcgen05.mma.cta_group::1.kind::f16 [%0], %1, %2, %3, {%4, %4, %4, %4}, p;\n\t" \
        "}" :: "r"(dtm), "l"(adesc), "l"(bdesc), "r"(IDESC_BF16),            \
               "r"(0u), "r"(_e) : "memory");                                 \
} while (0)

#define TC_MMA_TS(dtm, atm, bdesc, en) do {                                  \
    uint32_t _e = (en) ? 1u : 0u;                                            \
    asm volatile("{\n\t.reg .pred p;\n\t"                                    \
        "setp.ne.u32 p, %5, 0;\n\t"                                          \
        "tcgen05.mma.cta_group::1.kind::f16 [%0], [%1], %2, %3, {%4, %4, %4, %4}, p;\n\t" \
        "}" :: "r"(dtm), "r"(atm), "l"(bdesc), "r"(IDESC_BF16),              \
               "r"(0u), "r"(_e) : "memory");                                 \
} while (0)

#define TC_MMA_TF32_TS(dtm, atm, bdesc, en) do {                             \
    uint32_t _e = (en) ? 1u : 0u;                                            \
    asm volatile("{\n\t.reg .pred p;\n\t"                                    \
        "setp.ne.u32 p, %5, 0;\n\t"                                          \
        "tcgen05.mma.cta_group::1.kind::tf32 [%0], [%1], %2, %3, {%4, %4, %4, %4}, p;\n\t" \
        "}" :: "r"(dtm), "r"(atm), "l"(bdesc), "r"(IDESC_TF32),              \
               "r"(0u), "r"(_e) : "memory");                                 \
} while (0)

#define TC_ST_X16(tmem_addr, r)                                              \
    asm volatile("tcgen05.st.sync.aligned.32x32b.x16.b32 [%0], "             \
        "{%1, %2, %3, %4, %5, %6, %7, %8, "                                  \
        " %9, %10, %11, %12, %13, %14, %15, %16};"                           \
        :: "r"(tmem_addr),                                                   \
           "r"((r)[0]),  "r"((r)[1]),  "r"((r)[2]),  "r"((r)[3]),            \
           "r"((r)[4]),  "r"((r)[5]),  "r"((r)[6]),  "r"((r)[7]),            \
           "r"((r)[8]),  "r"((r)[9]),  "r"((r)[10]), "r"((r)[11]),           \
           "r"((r)[12]), "r"((r)[13]), "r"((r)[14]), "r"((r)[15])            \
        : "memory")

#define TC_ST_X32(tmem_addr, r)                                              \
    asm volatile("tcgen05.st.sync.aligned.32x32b.x32.b32 [%0], "             \
        "{%1, %2, %3, %4, %5, %6, %7, %8, "                                  \
        " %9, %10, %11, %12, %13, %14, %15, %16, "                           \
        " %17, %18, %19, %20, %21, %22, %23, %24, "                          \
        " %25, %26, %27, %28, %29, %30, %31, %32};"                          \
        :: "r"(tmem_addr),                                                   \
           "r"((r)[0]),  "r"((r)[1]),  "r"((r)[2]),  "r"((r)[3]),            \
           "r"((r)[4]),  "r"((r)[5]),  "r"((r)[6]),  "r"((r)[7]),            \
           "r"((r)[8]),  "r"((r)[9]),  "r"((r)[10]), "r"((r)[11]),           \
           "r"((r)[12]), "r"((r)[13]), "r"((r)[14]), "r"((r)[15]),           \
           "r"((r)[16]), "r"((r)[17]), "r"((r)[18]), "r"((r)[19]),           \
           "r"((r)[20]), "r"((r)[21]), "r"((r)[22]), "r"((r)[23]),           \
           "r"((r)[24]), "r"((r)[25]), "r"((r)[26]), "r"((r)[27]),           \
           "r"((r)[28]), "r"((r)[29]), "r"((r)[30]), "r"((r)[31])            \
        : "memory")

#define TC_LD_X32(r, tmem_addr)                                              \
    asm volatile("tcgen05.ld.sync.aligned.32x32b.x32.b32 "                   \
        "{%0, %1, %2, %3, %4, %5, %6, %7, "                                  \
        " %8, %9, %10, %11, %12, %13, %14, %15, "                            \
        " %16, %17, %18, %19, %20, %21, %22, %23, "                          \
        " %24, %25, %26, %27, %28, %29, %30, %31}, [%32];"                   \
        : "=r"((r)[0]),  "=r"((r)[1]),  "=r"((r)[2]),  "=r"((r)[3]),         \
          "=r"((r)[4]),  "=r"((r)[5]),  "=r"((r)[6]),  "=r"((r)[7]),         \
          "=r"((r)[8]),  "=r"((r)[9]),  "=r"((r)[10]), "=r"((r)[11]),        \
          "=r"((r)[12]), "=r"((r)[13]), "=r"((r)[14]), "=r"((r)[15]),        \
          "=r"((r)[16]), "=r"((r)[17]), "=r"((r)[18]), "=r"((r)[19]),        \
          "=r"((r)[20]), "=r"((r)[21]), "=r"((r)[22]), "=r"((r)[23]),        \
          "=r"((r)[24]), "=r"((r)[25]), "=r"((r)[26]), "=r"((r)[27]),        \
          "=r"((r)[28]), "=r"((r)[29]), "=r"((r)[30]), "=r"((r)[31])         \
        : "r"(tmem_addr))

static constexpr unsigned long long SMEM_DESC_BASE =
    (2ull << 61) | (1ull << 46) | (64ull << 32) | (1ull << 16);
__device__ __forceinline__ uint64_t mk_desc(uint32_t addr) {
    return SMEM_DESC_BASE | ((uint64_t)(addr >> 4) & 0x3FFF);
}
__device__ __forceinline__ uint64_t koff(int s) {
    return (uint64_t)((s >> 2) * 1024 + (s & 3) * 2);
}

#endif // sm_103a device helpers

// ---------------- small kernels ------------------------------------------
__global__ void k_detect(const int* ei32) {
    if (blockIdx.x == 0 && threadIdx.x == 0) {
        int is64 = 1;
        #pragma unroll 1
        for (int i = 0; i < 64; ++i)
            if (ei32[2 * i + 1] != 0) { is64 = 0; break; }
        g_is64 = is64;
    }
}
__global__ void k_convert_zero(const void* ei) {
    size_t i = (size_t)blockIdx.x * blockDim.x + threadIdx.x;
    if (i < N_EDGES) {
        if (g_is64) {
            const long long* p = (const long long*)ei;
            g_row[i] = (int)p[i];
            g_col[i] = (int)p[(size_t)N_EDGES + i];
        } else {
            const int* p = (const int*)ei;
            g_row[i] = p[i];
            g_col[i] = p[N_EDGES + i];
        }
    }
    if (i < (size_t)N_NODES * D) g_agg[i] = 0.0f;
}
__global__ void k_prep(const float* __restrict__ W1, const float* __restrict__ W2,
                       const float* __restrict__ NW1, const float* __restrict__ NW2) {
    int i = blockIdx.x * blockDim.x + threadIdx.x;
    if (i < 128 * K1PAD) {
        int n = i / K1PAD, k = i % K1PAD;
        float v = (k < K1) ? W1[(size_t)k * 128 + n] : 0.0f;
        g_W1B[swz(abyte(n, k)) >> 1] = bf16_bits(v);
        return;
    }
    i -= 128 * K1PAD;
    if (i < 128 * 128) {
        int n = i / 128, k = i % 128;
        g_W2B[swz(abyte(n, k)) >> 1] = bf16_bits(W2[(size_t)k * 128 + n]);
        return;
    }
    i -= 128 * 128;
    if (i < 128 * 256) {
        int n = i / 256, k = i % 256;
        g_NW1B[swz(abyte32(n, k)) >> 2] = f2tf32(NW1[(size_t)k * 128 + n]);
        return;
    }
    i -= 128 * 256;
    if (i < 128 * 128) {
        int n = i / 128, k = i % 128;
        g_NW2B[swz(abyte32(n, k)) >> 2] = f2tf32(NW2[(size_t)k * 128 + n]);
    }
}

// ---------------- fused edge kernel (R10 + E1 split across 8 warps) -------
__global__ __launch_bounds__(256, 1) void k_edge_fused(
    const float* __restrict__ x, const float* __restrict__ ea,
    const float* __restrict__ eb1, const float* __restrict__ eb2,
    const float* __restrict__ eW1raw, const float* __restrict__ eW2raw,
    int nblocks)
{
#if defined(__CUDA_ARCH__) && defined(__CUDA_ARCH_FEAT_SM103_ALL)
    extern __shared__ uint32_t dsm[];
    __shared__ float s_eb1[D], s_eb2[D];
    __shared__ uint32_t s_tmem[1];
    __shared__ __align__(8) unsigned long long s_mbar1, s_mbar2;

    const int tid = threadIdx.x;
    const int wid = tid >> 5;
    const int lane = tid & 31;

    const uint32_t dyn_base = smem_u32(dsm);
    const uint32_t ws1 = (dyn_base + 1023u) & ~1023u;
    const uint32_t ws2 = ws1 + W1B_BYTES;
    const uint32_t wsA = ws2 + W2B_BYTES;
    uint32_t* w1p = dsm + ((ws1 - dyn_base) >> 2);

    {
        uint4* dst = (uint4*)w1p; const uint4* src = (const uint4*)g_W1B;
        for (int i = tid; i < (W1B_BYTES + W2B_BYTES) / 16; i += 256) dst[i] = src[i];
        if (tid < D) { s_eb1[tid] = eb1[tid]; s_eb2[tid] = eb2[tid]; }
        for (int i = tid; i < 128 * 12; i += 256) {
            int row = i / 12, j = i % 12;
            sts8(wsA + swz(abyte(row, 272 + j * 4)), 0u, 0u);
        }
    }
    if (wid == 0) TC_ALLOC(smem_u32(s_tmem), 512);
    if (tid == 0) { MBAR_INIT(smem_u32(&s_mbar1), 1); MBAR_INIT(smem_u32(&s_mbar2), 1); }
    __syncthreads();
    const uint32_t tbase = s_tmem[0];
    const uint32_t mbar1 = smem_u32(&s_mbar1);
    const uint32_t mbar2 = smem_u32(&s_mbar2);
    const uint64_t a1d = mk_desc(wsA);
    const uint64_t w1d = mk_desc(ws1);
    const uint64_t w2d = mk_desc(ws2);

    auto gather = [&](int tile) {
        const int gw = wid;
        const int e0 = tile * TM + gw * 32;
        const int myr = g_row[e0 + lane];
        const int myc = g_col[e0 + lane];
        #pragma unroll 16
        for (int i = 0; i < 32; ++i) {
            const int el = gw * 32 + i;
            const int r = __shfl_sync(0xffffffffu, myr, i);
            const int c = __shfl_sync(0xffffffffu, myc, i);
            float4 v = *(const float4*)(x + (size_t)r * D + lane * 4);
            sts8(wsA + swz(abyte(el, lane * 4)),
                 pack_bf16x2(v.x, v.y), pack_bf16x2(v.z, v.w));
            v = *(const float4*)(x + (size_t)c * D + lane * 4);
            sts8(wsA + swz(abyte(el, 128 + lane * 4)),
                 pack_bf16x2(v.x, v.y), pack_bf16x2(v.z, v.w));
        }
        #pragma unroll
        for (int i = 0; i < 4; ++i) {
            const int el = gw * 32 + i * 8 + (lane >> 2);
            const int e = tile * TM + el;
            float4 v = *(const float4*)(ea + (size_t)e * DE + (lane & 3) * 4);
            sts8(wsA + swz(abyte(el, 256 + (lane & 3) * 4)),
                 pack_bf16x2(v.x, v.y), pack_bf16x2(v.z, v.w));
        }
    };

    // E1 half: D1 chunks c0, c0+1 -> bias+silu -> A2 cols (bf16)
    // Each warp reads/writes ONLY its own subpartition (wid & 3).
    auto e1_half = [&](int c0) {
        uint32_t d0[32], d1[32], a0[16], a1r[16];
        TC_LD_X32(d0, tbase + TMEM_D1 + c0 * 32);
        TC_LD_X32(d1, tbase + TMEM_D1 + (c0 + 1) * 32);
        TC_WAIT_LD();
        #pragma unroll
        for (int m = 0; m < 16; ++m) {
            float v0 = silu_f(__uint_as_float(d0[2*m])   + s_eb1[c0*32 + 2*m]);
            float v1 = silu_f(__uint_as_float(d0[2*m+1]) + s_eb1[c0*32 + 2*m+1]);
            a0[m] = pack_bf16x2(v0, v1);
        }
        #pragma unroll
        for (int m = 0; m < 16; ++m) {
            float v0 = silu_f(__uint_as_float(d1[2*m])   + s_eb1[(c0+1)*32 + 2*m]);
            float v1 = silu_f(__uint_as_float(d1[2*m+1]) + s_eb1[(c0+1)*32 + 2*m+1]);
            a1r[m] = pack_bf16x2(v0, v1);
        }
        const uint32_t wo = (uint32_t)(wid & 3) << 21;
        TC_ST_X16(tbase + TMEM_A2 + c0 * 16 + wo, a0);
        TC_ST_X16(tbase + TMEM_A2 + (c0 + 1) * 16 + wo, a1r);
        TC_WAIT_ST();
    };

    auto e2_half = [&](int tile, int c0) {
        const int e = tile * TM + (wid & 3) * 32 + lane;
        float* aggp = g_agg + (size_t)g_row[e] * D;
        uint32_t d0[32], d1[32];
        TC_LD_X32(d0, tbase + TMEM_D2 + c0 * 32);
        TC_LD_X32(d1, tbase + TMEM_D2 + (c0 + 1) * 32);
        TC_WAIT_LD();
        #pragma unroll
        for (int q = 0; q < 8; ++q) {
            float v0 = silu_f(__uint_as_float(d0[q*4+0]) + s_eb2[c0*32+q*4+0]);
            float v1 = silu_f(__uint_as_float(d0[q*4+1]) + s_eb2[c0*32+q*4+1]);
            float v2 = silu_f(__uint_as_float(d0[q*4+2]) + s_eb2[c0*32+q*4+2]);
            float v3 = silu_f(__uint_as_float(d0[q*4+3]) + s_eb2[c0*32+q*4+3]);
            asm volatile("red.global.add.v4.f32 [%0], {%1,%2,%3,%4};"
                         :: "l"(aggp + c0 * 32 + q * 4),
                            "f"(v0), "f"(v1), "f"(v2), "f"(v3) : "memory");
        }
        #pragma unroll
        for (int q = 0; q < 8; ++q) {
            float v0 = silu_f(__uint_as_float(d1[q*4+0]) + s_eb2[(c0+1)*32+q*4+0]);
            float v1 = silu_f(__uint_as_float(d1[q*4+1]) + s_eb2[(c0+1)*32+q*4+1]);
            float v2 = silu_f(__uint_as_float(d1[q*4+2]) + s_eb2[(c0+1)*32+q*4+2]);
            float v3 = silu_f(__uint_as_float(d1[q*4+3]) + s_eb2[(c0+1)*32+q*4+3]);
            asm volatile("red.global.add.v4.f32 [%0], {%1,%2,%3,%4};"
                         :: "l"(aggp + (c0 + 1) * 32 + q * 4),
                            "f"(v0), "f"(v1), "f"(v2), "f"(v3) : "memory");
        }
    };

    // prologue: gather tile0, then issue MMA1(tile0)
    if (wid < 4 && blockIdx.x < NTILES) { gather(blockIdx.x); FENCE_PROXY_ASYNC(); }
    __syncthreads();
    if (wid == 4 && blockIdx.x < NTILES) {
        TC_FENCE_AFTER();
        if (elect_one()) {
            #pragma unroll 1
            for (int s = 0; s < 17; ++s)
                TC_MMA_SS(tbase + TMEM_D1, a1d + koff(s), w1d + koff(s), s > 0);
            TC_COMMIT(mbar1);
        }
    }

    int ph1 = 0, ph2 = 0;
    for (int tile = blockIdx.x; tile < NTILES; tile += nblocks) {
        const bool has_next = (tile + nblocks < NTILES);

        if (wid < 4) {
            // ---- G-warps: E1 high half, then gather, then E2 high half ----
            MBAR_WAIT(mbar1, ph1);
            TC_FENCE_AFTER();
            e1_half(2);
            TC_FENCE_BEFORE();
            NAMED_ARRIVE(1, 256);          // A2 high half ready, D1 reads done
            if (has_next) {
                gather(tile + nblocks); FENCE_PROXY_ASYNC();
                NAMED_ARRIVE(2, 160);
            }
            MBAR_WAIT(mbar2, ph2);
            TC_FENCE_AFTER();
            e2_half(tile, 2);
            TC_FENCE_BEFORE();
        } else {
            // ---- C-warps: E1 low half, MMA issue (warp 4), E2 low half ----
            MBAR_WAIT(mbar1, ph1);
            TC_FENCE_AFTER();
            e1_half(0);
            TC_FENCE_BEFORE();
            NAMED_BAR(1, 256);             // both E1 halves done: A2 ready, D1 free

            if (wid == 4) {
                TC_FENCE_AFTER();
                if (elect_one()) {
                    #pragma unroll 1
                    for (int s = 0; s < 8; ++s)
                        TC_MMA_TS(tbase + TMEM_D2, tbase + TMEM_A2 + s * 8,
                                  w2d + koff(s), s > 0);
                    TC_COMMIT(mbar2);
                }
                if (has_next) {
                    NAMED_BAR(2, 160);     // gather(t+1) complete
                    if (elect_one()) {
                        #pragma unroll 1
                        for (int s = 0; s < 17; ++s)
                            TC_MMA_SS(tbase + TMEM_D1, a1d + koff(s), w1d + koff(s), s > 0);
                        TC_COMMIT(mbar1);
                    }
                }
            }
            MBAR_WAIT(mbar2, ph2);
            TC_FENCE_AFTER();
            e2_half(tile, 0);
            TC_FENCE_BEFORE();
        }
        ph1 ^= 1; ph2 ^= 1;
    }

    __syncthreads();
    if (wid == 0) { TC_RELINQ(); TC_DEALLOC(tbase, 512); }

#else
    // plain-sm_103 fallback (never selected on GB300)
    const int tid = threadIdx.x;
    if (tid >= TM) return;
    for (int tile = blockIdx.x; tile < NTILES; tile += nblocks) {
        const int e = tile * TM + tid;
        const int r = g_row[e], c = g_col[e];
        float a[K1];
        #pragma unroll 4
        for (int j = 0; j < D; ++j) { a[j] = x[(size_t)r * D + j]; a[D + j] = x[(size_t)c * D + j]; }
        #pragma unroll
        for (int j = 0; j < DE; ++j) a[2 * D + j] = ea[(size_t)e * DE + j];
        float h[D];
        for (int n = 0; n < D; ++n) {
            float s = eb1[n];
            for (int k = 0; k < K1; ++k) s = fmaf(a[k], eW1raw[(size_t)k * D + n], s);
            h[n] = silu_f(s);
        }
        for (int n = 0; n < D; ++n) {
            float s = eb2[n];
            for (int k = 0; k < D; ++k) s = fmaf(h[k], eW2raw[(size_t)k * D + n], s);
            atomicAdd(g_agg + (size_t)r * D + n, silu_f(s));
        }
    }
#endif
}

// ---------------- fused node kernel (tcgen05 tf32, TS mode) ---------------
__global__ __launch_bounds__(128, 1) void k_node_fused(
    const float* __restrict__ x,
    const float* __restrict__ nb1, const float* __restrict__ nb2,
    const float* __restrict__ nW1raw, const float* __restrict__ nW2raw,
    float* __restrict__ out, int nblocks)
{
#if defined(__CUDA_ARCH__) && defined(__CUDA_ARCH_FEAT_SM103_ALL)
    extern __shared__ uint32_t dsm[];
    __shared__ float s_b1[D], s_b2[D];
    __shared__ uint32_t s_tmem[1];
    __shared__ __align__(8) unsigned long long s_mbar;

    const int tid = threadIdx.x;
    const int wid = tid >> 5;
    const int lane = tid & 31;
    const uint32_t woff = (uint32_t)wid << 21;

    const uint32_t dyn_base = smem_u32(dsm);
    const uint32_t ws1 = (dyn_base + 1023u) & ~1023u;
    const uint32_t ws2 = ws1 + NW1_WORDS * 4;
    uint32_t* w1p = dsm + ((ws1 - dyn_base) >> 2);

    {
        uint4* dst = (uint4*)w1p; const uint4* src = (const uint4*)g_NW1B;
        for (int i = tid; i < (NW1_WORDS + NW2_WORDS) / 4; i += 128) dst[i] = src[i];
        if (tid < D) { s_b1[tid] = nb1[tid]; s_b2[tid] = nb2[tid]; }
    }
    if (wid == 0) TC_ALLOC(smem_u32(s_tmem), 512);
    if (tid == 0) MBAR_INIT(smem_u32(&s_mbar), 1);
    __syncthreads();
    const uint32_t tbase = s_tmem[0];
    const uint32_t mbar = smem_u32(&s_mbar);
    const uint64_t w1d = mk_desc(ws1);
    const uint64_t w2d = mk_desc(ws2);

    int ph = 0;
    for (int tile = blockIdx.x; tile < NNT; tile += nblocks) {
        __syncthreads();

        {
            int n = tile * 128 + tid;
            if (n >= N_NODES) n = N_NODES - 1;
            const float4* xr = (const float4*)(x + (size_t)n * D);
            const float4* ar = (const float4*)(g_agg + (size_t)n * D);
            uint32_t a[32];
            #pragma unroll 1
            for (int ch = 0; ch < 4; ++ch) {
                #pragma unroll
                for (int q = 0; q < 8; ++q) {
                    float4 v = xr[ch * 8 + q];
                    a[q*4+0] = f2tf32(v.x); a[q*4+1] = f2tf32(v.y);
                    a[q*4+2] = f2tf32(v.z); a[q*4+3] = f2tf32(v.w);
                }
                TC_ST_X32(tbase + ch * 32 + woff, a);
            }
            #pragma unroll 1
            for (int ch = 0; ch < 4; ++ch) {
                #pragma unroll
                for (int q = 0; q < 8; ++q) {
                    float4 v = ar[ch * 8 + q];
                    a[q*4+0] = f2tf32(v.x); a[q*4+1] = f2tf32(v.y);
                    a[q*4+2] = f2tf32(v.z); a[q*4+3] = f2tf32(v.w);
                }
                TC_ST_X32(tbase + 128 + ch * 32 + woff, a);
            }
        }
        TC_WAIT_ST();
        TC_FENCE_BEFORE();
        __syncthreads();

        if (wid == 0) {
            TC_FENCE_AFTER();
            if (elect_one()) {
                #pragma unroll 1
                for (int s = 0; s < 32; ++s)
                    TC_MMA_TF32_TS(tbase + 256, tbase + s * 8, w1d + koff(s), s > 0);
                TC_COMMIT(mbar);
            }
        }
        MBAR_WAIT(mbar, ph); ph ^= 1;
        TC_FENCE_AFTER();

        #pragma unroll 1
        for (int ch = 0; ch < 4; ++ch) {
            uint32_t dreg[32], areg[32];
            TC_LD_X32(dreg, tbase + 256 + ch * 32);
            TC_WAIT_LD();
            #pragma unroll
            for (int j = 0; j < 32; ++j)
                areg[j] = f2tf32(silu_f(__uint_as_float(dreg[j]) + s_b1[ch * 32 + j]));
            TC_ST_X32(tbase + ch * 32 + woff, areg);
        }
        TC_WAIT_ST();
        TC_FENCE_BEFORE();
        __syncthreads();

        if (wid == 0) {
            TC_FENCE_AFTER();
            if (elect_one()) {
                #pragma unroll 1
                for (int s = 0; s < 16; ++s)
                    TC_MMA_TF32_TS(tbase + 128, tbase + s * 8, w2d + koff(s), s > 0);
                TC_COMMIT(mbar);
            }
        }
        MBAR_WAIT(mbar, ph); ph ^= 1;
        TC_FENCE_AFTER();

        {
            const int n = tile * 128 + wid * 32 + lane;
            const bool valid = (n < N_NODES);
            const float4* xr = (const float4*)(x + (size_t)n * D);
            float4* orow = (float4*)(out + (size_t)n * D);
            #pragma unroll 1
            for (int ch = 0; ch < 4; ++ch) {
                uint32_t dreg[32];
                TC_LD_X32(dreg, tbase + 128 + ch * 32);
                TC_WAIT_LD();
                if (valid) {
                    #pragma unroll
                    for (int q = 0; q < 8; ++q) {
                        float4 xv = xr[ch * 8 + q];
                        float4 o;
                        o.x = xv.x + __uint_as_float(dreg[q*4+0]) + s_b2[ch*32+q*4+0];
                        o.y = xv.y + __uint_as_float(dreg[q*4+1]) + s_b2[ch*32+q*4+1];
                        o.z = xv.z + __uint_as_float(dreg[q*4+2]) + s_b2[ch*32+q*4+2];
                        o.w = xv.w + __uint_as_float(dreg[q*4+3]) + s_b2[ch*32+q*4+3];
                        orow[ch * 8 + q] = o;
                    }
                }
            }
            TC_FENCE_BEFORE();
        }
    }

    __syncthreads();
    if (wid == 0) { TC_RELINQ(); TC_DEALLOC(tbase, 512); }

#else
    const int tid = threadIdx.x;
    for (int n = blockIdx.x * 128 + tid; n < N_NODES; n += nblocks * 128) {
        float t[D];
        for (int o = 0; o < D; ++o) {
            float s = nb1[o];
            for (int k = 0; k < D; ++k) {
                s = fmaf(x[(size_t)n * D + k], nW1raw[(size_t)k * D + o], s);
                s = fmaf(g_agg[(size_t)n * D + k], nW1raw[(size_t)(D + k) * D + o], s);
            }
            t[o] = silu_f(s);
        }
        for (int o = 0; o < D; ++o) {
            float s = nb2[o];
            for (int k = 0; k < D; ++k) s = fmaf(t[k], nW2raw[(size_t)k * D + o], s);
            out[(size_t)n * D + o] = x[(size_t)n * D + o] + s;
        }
    }
#endif
}

// ---------------- launch --------------------------------------------------
extern "C" void kernel_launch(void* const* d_in, const int* in_sizes, int n_in,
                              void* d_out, int out_size)
{
    const float* x   = (const float*)d_in[0];
    const void*  ei  = d_in[1];
    const float* ea  = (const float*)d_in[2];
    const float* eW1 = (const float*)d_in[3];
    const float* eb1 = (const float*)d_in[4];
    const float* eW2 = (const float*)d_in[5];
    const float* eb2 = (const float*)d_in[6];
    const float* nW1 = (const float*)d_in[7];
    const float* nb1 = (const float*)d_in[8];
    const float* nW2 = (const float*)d_in[9];
    const float* nb2 = (const float*)d_in[10];
    float* out = (float*)d_out;

    int sms = 148;
    cudaDeviceGetAttribute(&sms, cudaDevAttrMultiProcessorCount, 0);

    const int s_edge = 1024 + W1B_BYTES + W2B_BYTES + A1B_BYTES;
    const int s_node = 1024 + (NW1_WORDS + NW2_WORDS) * 4;

    cudaFuncSetAttribute(k_edge_fused, cudaFuncAttributeMaxDynamicSharedMemorySize, s_edge);
    cudaFuncSetAttribute(k_node_fused, cudaFuncAttributeMaxDynamicSharedMemorySize, s_node);

    const int prep_elems = 128 * K1PAD + 128 * 128 + 128 * 256 + 128 * 128;
    const size_t cz = (size_t)N_NODES * D;

    k_detect<<<1, 1>>>((const int*)ei);
    k_convert_zero<<<(int)((cz + 255) / 256), 256>>>(ei);
    k_prep<<<(prep_elems + 255) / 256, 256>>>(eW1, eW2, nW1, nW2);
    k_edge_fused<<<sms, 256, s_edge>>>(x, ea, eb1, eb2, eW1, eW2, sms);
    k_node_fused<<<sms, 128, s_node>>>(x, nb1, nb2, nW1, nW2, out, sms);
}

// round 13
// speedup vs baseline: 1.2574x; 1.0339x over previous
#include <cuda_runtime.h>
#include <cuda_bf16.h>
#include <cstdint>

#define N_NODES 50000
#define N_EDGES 800000
#define D 128
#define DE 16
#define K1 272
#define K1PAD 320
#define TM 128
#define NTILES (N_EDGES / TM)           // 6250
#define NNT ((N_NODES + 127) / 128)     // 391

#define W1B_BYTES (128 * K1PAD * 2)   // 81920
#define W2B_BYTES (128 * 128 * 2)     // 32768
#define A1B_BYTES (128 * K1PAD * 2)   // 81920
#define NW1_WORDS (256 * 128)
#define NW2_WORDS (128 * 128)

// edge TMEM
#define TMEM_D1 0
#define TMEM_D2 128
#define TMEM_A2 256

#define IDESC_BF16 0x8200490u
#define IDESC_TF32 0x8200910u

// ---------------- scratch -----------------------------------------------
__device__ int      g_is64;
__device__ int      g_row[N_EDGES];
__device__ int      g_col[N_EDGES];
__device__ float    g_agg[(size_t)N_NODES * D];
__device__ uint16_t g_xb[(size_t)N_NODES * D];   // bf16 copy of x (12.8MB, L2-resident)
__device__ uint16_t g_W1B[W1B_BYTES / 2];
__device__ uint16_t g_W2B[W2B_BYTES / 2];
__device__ uint32_t g_NW1B[NW1_WORDS];
__device__ uint32_t g_NW2B[NW2_WORDS];

__device__ __forceinline__ float silu_f(float v) {
    float t;
    asm("tanh.approx.f32 %0, %1;" : "=f"(t) : "f"(0.5f * v));
    return v * fmaf(0.5f, t, 0.5f);
}
__device__ __forceinline__ uint32_t smem_u32(const void* p) {
    uint32_t a;
    asm("{ .reg .u64 t; cvta.to.shared.u64 t, %1; cvt.u32.u64 %0, t; }"
        : "=r"(a) : "l"(p));
    return a;
}
__device__ __forceinline__ uint32_t pack_bf16x2(float lo, float hi) {
    uint32_t d;
    asm("cvt.rn.bf16x2.f32 %0, %1, %2;" : "=r"(d) : "f"(hi), "f"(lo));
    return d;
}
__device__ __forceinline__ uint16_t bf16_bits(float v) {
    __nv_bfloat16 b = __float2bfloat16(v);
    return *reinterpret_cast<uint16_t*>(&b);
}
__device__ __forceinline__ uint32_t f2tf32(float f) {
    uint32_t u;
    asm("cvt.rna.tf32.f32 %0, %1;" : "=r"(u) : "f"(f));
    return u;
}
__device__ __forceinline__ void sts8(uint32_t addr, uint32_t a, uint32_t b) {
    asm volatile("st.shared.v2.b32 [%0], {%1, %2};" :: "r"(addr), "r"(a), "r"(b) : "memory");
}
__device__ __forceinline__ uint32_t abyte(int row, int k) {
    return (uint32_t)((((row >> 3) + ((k >> 6) << 4)) << 10) | ((row & 7) << 7) | ((k & 63) << 1));
}
__device__ __forceinline__ uint32_t abyte32(int row, int k) {
    return (uint32_t)((((row >> 3) + ((k >> 5) << 4)) << 10) | ((row & 7) << 7) | ((k & 31) << 2));
}
__device__ __forceinline__ uint32_t swz(uint32_t b) {
    return b ^ ((b >> 3) & 0x70);
}

#if defined(__CUDA_ARCH__) && defined(__CUDA_ARCH_FEAT_SM103_ALL)

__device__ __forceinline__ uint32_t elect_one() {
    uint32_t pred;
    asm volatile("{\n\t.reg .pred p;\n\telect.sync _|p, 0xFFFFFFFF;\n\t"
                 "selp.b32 %0, 1, 0, p;\n\t}" : "=r"(pred));
    return pred;
}

#define TC_ALLOC(smemaddr, n) \
    asm volatile("tcgen05.alloc.cta_group::1.sync.aligned.shared::cta.b32 [%0], %1;" \
                 :: "r"(smemaddr), "r"((uint32_t)(n)) : "memory")
#define TC_RELINQ() \
    asm volatile("tcgen05.relinquish_alloc_permit.cta_group::1.sync.aligned;")
#define TC_DEALLOC(tmem, n) \
    asm volatile("tcgen05.dealloc.cta_group::1.sync.aligned.b32 %0, %1;" \
                 :: "r"(tmem), "r"((uint32_t)(n)))
#define TC_WAIT_ST() asm volatile("tcgen05.wait::st.sync.aligned;" ::: "memory")
#define TC_WAIT_LD() asm volatile("tcgen05.wait::ld.sync.aligned;" ::: "memory")
#define TC_FENCE_BEFORE() asm volatile("tcgen05.fence::before_thread_sync;" ::: "memory")
#define TC_FENCE_AFTER()  asm volatile("tcgen05.fence::after_thread_sync;" ::: "memory")
#define TC_COMMIT(mbar) \
    asm volatile("tcgen05.commit.cta_group::1.mbarrier::arrive::one.shared::cluster.b64 [%0];" \
                 :: "r"(mbar) : "memory")
#define MBAR_INIT(mbar, cnt) \
    asm volatile("mbarrier.init.shared.b64 [%0], %1;" :: "r"(mbar), "r"((uint32_t)(cnt)) : "memory")
#define FENCE_PROXY_ASYNC() \
    asm volatile("fence.proxy.async.shared::cta;" ::: "memory")
#define NAMED_BAR(id, n) \
    asm volatile("bar.sync %0, %1;" :: "r"(id), "r"(n) : "memory")
#define NAMED_ARRIVE(id, n) \
    asm volatile("bar.arrive %0, %1;" :: "r"(id), "r"(n) : "memory")

#define MBAR_WAIT(mbar, ph) do {                                             \
    uint32_t _m = (mbar), _p = (uint32_t)(ph), _d;                           \
    asm volatile("{\n\t.reg .pred p;\n\t"                                    \
        "mbarrier.try_wait.parity.acquire.cta.shared::cta.b64 p, [%1], %2;\n\t" \
        "selp.b32 %0, 1, 0, p;\n\t}" : "=r"(_d) : "r"(_m), "r"(_p) : "memory"); \
    if (!_d) {                                                               \
        asm volatile("{\n\t.reg .pred P1;\n\t"                               \
            "WL_%=:\n\t"                                                     \
            "mbarrier.try_wait.parity.acquire.cta.shared::cta.b64 P1, [%0], %1, 0x989680;\n\t" \
            "@P1 bra.uni WD_%=;\n\t"                                         \
            "bra.uni WL_%=;\n\t"                                             \
            "WD_%=:\n\t}" :: "r"(_m), "r"(_p) : "memory");                   \
    }                                                                        \
} while (0)

#define TC_MMA_SS(dtm, adesc, bdesc, en) do {                                \
    uint32_t _e = (en) ? 1u : 0u;                                            \
    asm volatile("{\n\t.reg .pred p;\n\t"                                    \
        "setp.ne.u32 p, %5, 0;\n\t"                                          \
        "tcgen05.mma.cta_group::1.kind::f16 [%0], %1, %2, %3, {%4, %4, %4, %4}, p;\n\t" \
        "}" :: "r"(dtm), "l"(adesc), "l"(bdesc), "r"(IDESC_BF16),            \
               "r"(0u), "r"(_e) : "memory");                                 \
} while (0)

#define TC_MMA_TS(dtm, atm, bdesc, en) do {                                  \
    uint32_t _e = (en) ? 1u : 0u;                                            \
    asm volatile("{\n\t.reg .pred p;\n\t"                                    \
        "setp.ne.u32 p, %5, 0;\n\t"                                          \
        "tcgen05.mma.cta_group::1.kind::f16 [%0], [%1], %2, %3, {%4, %4, %4, %4}, p;\n\t" \
        "}" :: "r"(dtm), "r"(atm), "l"(bdesc), "r"(IDESC_BF16),              \
               "r"(0u), "r"(_e) : "memory");                                 \
} while (0)

#define TC_MMA_TF32_TS(dtm, atm, bdesc, en) do {                             \
    uint32_t _e = (en) ? 1u : 0u;                                            \
    asm volatile("{\n\t.reg .pred p;\n\t"                                    \
        "setp.ne.u32 p, %5, 0;\n\t"                                          \
        "tcgen05.mma.cta_group::1.kind::tf32 [%0], [%1], %2, %3, {%4, %4, %4, %4}, p;\n\t" \
        "}" :: "r"(dtm), "r"(atm), "l"(bdesc), "r"(IDESC_TF32),              \
               "r"(0u), "r"(_e) : "memory");                                 \
} while (0)

#define TC_ST_X16(tmem_addr, r)                                              \
    asm volatile("tcgen05.st.sync.aligned.32x32b.x16.b32 [%0], "             \
        "{%1, %2, %3, %4, %5, %6, %7, %8, "                                  \
        " %9, %10, %11, %12, %13, %14, %15, %16};"                           \
        :: "r"(tmem_addr),                                                   \
           "r"((r)[0]),  "r"((r)[1]),  "r"((r)[2]),  "r"((r)[3]),            \
           "r"((r)[4]),  "r"((r)[5]),  "r"((r)[6]),  "r"((r)[7]),            \
           "r"((r)[8]),  "r"((r)[9]),  "r"((r)[10]), "r"((r)[11]),           \
           "r"((r)[12]), "r"((r)[13]), "r"((r)[14]), "r"((r)[15])            \
        : "memory")

#define TC_ST_X32(tmem_addr, r)                                              \
    asm volatile("tcgen05.st.sync.aligned.32x32b.x32.b32 [%0], "             \
        "{%1, %2, %3, %4, %5, %6, %7, %8, "                                  \
        " %9, %10, %11, %12, %13, %14, %15, %16, "                           \
        " %17, %18, %19, %20, %21, %22, %23, %24, "                          \
        " %25, %26, %27, %28, %29, %30, %31, %32};"                          \
        :: "r"(tmem_addr),                                                   \
           "r"((r)[0]),  "r"((r)[1]),  "r"((r)[2]),  "r"((r)[3]),            \
           "r"((r)[4]),  "r"((r)[5]),  "r"((r)[6]),  "r"((r)[7]),            \
           "r"((r)[8]),  "r"((r)[9]),  "r"((r)[10]), "r"((r)[11]),           \
           "r"((r)[12]), "r"((r)[13]), "r"((r)[14]), "r"((r)[15]),           \
           "r"((r)[16]), "r"((r)[17]), "r"((r)[18]), "r"((r)[19]),           \
           "r"((r)[20]), "r"((r)[21]), "r"((r)[22]), "r"((r)[23]),           \
           "r"((r)[24]), "r"((r)[25]), "r"((r)[26]), "r"((r)[27]),           \
           "r"((r)[28]), "r"((r)[29]), "r"((r)[30]), "r"((r)[31])            \
        : "memory")

#define TC_LD_X32(r, tmem_addr)                                              \
    asm volatile("tcgen05.ld.sync.aligned.32x32b.x32.b32 "                   \
        "{%0, %1, %2, %3, %4, %5, %6, %7, "                                  \
        " %8, %9, %10, %11, %12, %13, %14, %15, "                            \
        " %16, %17, %18, %19, %20, %21, %22, %23, "                          \
        " %24, %25, %26, %27, %28, %29, %30, %31}, [%32];"                   \
        : "=r"((r)[0]),  "=r"((r)[1]),  "=r"((r)[2]),  "=r"((r)[3]),         \
          "=r"((r)[4]),  "=r"((r)[5]),  "=r"((r)[6]),  "=r"((r)[7]),         \
          "=r"((r)[8]),  "=r"((r)[9]),  "=r"((r)[10]), "=r"((r)[11]),        \
          "=r"((r)[12]), "=r"((r)[13]), "=r"((r)[14]), "=r"((r)[15]),        \
          "=r"((r)[16]), "=r"((r)[17]), "=r"((r)[18]), "=r"((r)[19]),        \
          "=r"((r)[20]), "=r"((r)[21]), "=r"((r)[22]), "=r"((r)[23]),        \
          "=r"((r)[24]), "=r"((r)[25]), "=r"((r)[26]), "=r"((r)[27]),        \
          "=r"((r)[28]), "=r"((r)[29]), "=r"((r)[30]), "=r"((r)[31])         \
        : "r"(tmem_addr))

static constexpr unsigned long long SMEM_DESC_BASE =
    (2ull << 61) | (1ull << 46) | (64ull << 32) | (1ull << 16);
__device__ __forceinline__ uint64_t mk_desc(uint32_t addr) {
    return SMEM_DESC_BASE | ((uint64_t)(addr >> 4) & 0x3FFF);
}
__device__ __forceinline__ uint64_t koff(int s) {
    return (uint64_t)((s >> 2) * 1024 + (s & 3) * 2);
}

#endif // sm_103a device helpers

// ---------------- small kernels ------------------------------------------
__global__ void k_detect(const int* ei32) {
    if (blockIdx.x == 0 && threadIdx.x == 0) {
        int is64 = 1;
        #pragma unroll 1
        for (int i = 0; i < 64; ++i)
            if (ei32[2 * i + 1] != 0) { is64 = 0; break; }
        g_is64 = is64;
    }
}
// convert indices, zero agg, AND pre-convert x to bf16
__global__ void k_convert_zero(const void* ei, const float* __restrict__ x) {
    size_t i = (size_t)blockIdx.x * blockDim.x + threadIdx.x;
    if (i < N_EDGES) {
        if (g_is64) {
            const long long* p = (const long long*)ei;
            g_row[i] = (int)p[i];
            g_col[i] = (int)p[(size_t)N_EDGES + i];
        } else {
            const int* p = (const int*)ei;
            g_row[i] = p[i];
            g_col[i] = p[N_EDGES + i];
        }
    }
    if (i < (size_t)N_NODES * D) {
        g_agg[i] = 0.0f;
        g_xb[i] = bf16_bits(x[i]);
    }
}
__global__ void k_prep(const float* __restrict__ W1, const float* __restrict__ W2,
                       const float* __restrict__ NW1, const float* __restrict__ NW2) {
    int i = blockIdx.x * blockDim.x + threadIdx.x;
    if (i < 128 * K1PAD) {
        int n = i / K1PAD, k = i % K1PAD;
        float v = (k < K1) ? W1[(size_t)k * 128 + n] : 0.0f;
        g_W1B[swz(abyte(n, k)) >> 1] = bf16_bits(v);
        return;
    }
    i -= 128 * K1PAD;
    if (i < 128 * 128) {
        int n = i / 128, k = i % 128;
        g_W2B[swz(abyte(n, k)) >> 1] = bf16_bits(W2[(size_t)k * 128 + n]);
        return;
    }
    i -= 128 * 128;
    if (i < 128 * 256) {
        int n = i / 256, k = i % 256;
        g_NW1B[swz(abyte32(n, k)) >> 2] = f2tf32(NW1[(size_t)k * 128 + n]);
        return;
    }
    i -= 128 * 256;
    if (i < 128 * 128) {
        int n = i / 128, k = i % 128;
        g_NW2B[swz(abyte32(n, k)) >> 2] = f2tf32(NW2[(size_t)k * 128 + n]);
    }
}

// ---------------- fused edge kernel (bf16-x gather) -----------------------
__global__ __launch_bounds__(256, 1) void k_edge_fused(
    const float* __restrict__ x, const float* __restrict__ ea,
    const float* __restrict__ eb1, const float* __restrict__ eb2,
    const float* __restrict__ eW1raw, const float* __restrict__ eW2raw,
    int nblocks)
{
#if defined(__CUDA_ARCH__) && defined(__CUDA_ARCH_FEAT_SM103_ALL)
    extern __shared__ uint32_t dsm[];
    __shared__ float s_eb1[D], s_eb2[D];
    __shared__ uint32_t s_tmem[1];
    __shared__ __align__(8) unsigned long long s_mbar1, s_mbar2;

    const int tid = threadIdx.x;
    const int wid = tid >> 5;
    const int lane = tid & 31;

    const uint32_t dyn_base = smem_u32(dsm);
    const uint32_t ws1 = (dyn_base + 1023u) & ~1023u;
    const uint32_t ws2 = ws1 + W1B_BYTES;
    const uint32_t wsA = ws2 + W2B_BYTES;
    uint32_t* w1p = dsm + ((ws1 - dyn_base) >> 2);

    {
        uint4* dst = (uint4*)w1p; const uint4* src = (const uint4*)g_W1B;
        for (int i = tid; i < (W1B_BYTES + W2B_BYTES) / 16; i += 256) dst[i] = src[i];
        if (tid < D) { s_eb1[tid] = eb1[tid]; s_eb2[tid] = eb2[tid]; }
        for (int i = tid; i < 128 * 12; i += 256) {
            int row = i / 12, j = i % 12;
            sts8(wsA + swz(abyte(row, 272 + j * 4)), 0u, 0u);
        }
    }
    if (wid == 0) TC_ALLOC(smem_u32(s_tmem), 512);
    if (tid == 0) { MBAR_INIT(smem_u32(&s_mbar1), 1); MBAR_INIT(smem_u32(&s_mbar2), 1); }
    __syncthreads();
    const uint32_t tbase = s_tmem[0];
    const uint32_t mbar1 = smem_u32(&s_mbar1);
    const uint32_t mbar2 = smem_u32(&s_mbar2);
    const uint64_t a1d = mk_desc(wsA);
    const uint64_t w1d = mk_desc(ws1);
    const uint64_t w2d = mk_desc(ws2);

    // gather from pre-converted bf16 x: 1 LDG.64 per lane per row
    auto gather = [&](int tile) {
        const int gw = wid;
        const int e0 = tile * TM + gw * 32;
        const int myr = g_row[e0 + lane];
        const int myc = g_col[e0 + lane];
        #pragma unroll 16
        for (int i = 0; i < 32; ++i) {
            const int el = gw * 32 + i;
            const int r = __shfl_sync(0xffffffffu, myr, i);
            const int c = __shfl_sync(0xffffffffu, myc, i);
            uint2 v = *(const uint2*)(g_xb + (size_t)r * D + lane * 4);
            sts8(wsA + swz(abyte(el, lane * 4)), v.x, v.y);
            v = *(const uint2*)(g_xb + (size_t)c * D + lane * 4);
            sts8(wsA + swz(abyte(el, 128 + lane * 4)), v.x, v.y);
        }
        #pragma unroll
        for (int i = 0; i < 4; ++i) {
            const int el = gw * 32 + i * 8 + (lane >> 2);
            const int e = tile * TM + el;
            float4 v = *(const float4*)(ea + (size_t)e * DE + (lane & 3) * 4);
            sts8(wsA + swz(abyte(el, 256 + (lane & 3) * 4)),
                 pack_bf16x2(v.x, v.y), pack_bf16x2(v.z, v.w));
        }
    };

    auto e1_half = [&](int c0) {
        uint32_t d0[32], d1[32], a0[16], a1r[16];
        TC_LD_X32(d0, tbase + TMEM_D1 + c0 * 32);
        TC_LD_X32(d1, tbase + TMEM_D1 + (c0 + 1) * 32);
        TC_WAIT_LD();
        #pragma unroll
        for (int m = 0; m < 16; ++m) {
            float v0 = silu_f(__uint_as_float(d0[2*m])   + s_eb1[c0*32 + 2*m]);
            float v1 = silu_f(__uint_as_float(d0[2*m+1]) + s_eb1[c0*32 + 2*m+1]);
            a0[m] = pack_bf16x2(v0, v1);
        }
        #pragma unroll
        for (int m = 0; m < 16; ++m) {
            float v0 = silu_f(__uint_as_float(d1[2*m])   + s_eb1[(c0+1)*32 + 2*m]);
            float v1 = silu_f(__uint_as_float(d1[2*m+1]) + s_eb1[(c0+1)*32 + 2*m+1]);
            a1r[m] = pack_bf16x2(v0, v1);
        }
        const uint32_t wo = (uint32_t)(wid & 3) << 21;
        TC_ST_X16(tbase + TMEM_A2 + c0 * 16 + wo, a0);
        TC_ST_X16(tbase + TMEM_A2 + (c0 + 1) * 16 + wo, a1r);
        TC_WAIT_ST();
    };

    auto e2_half = [&](int tile, int c0) {
        const int e = tile * TM + (wid & 3) * 32 + lane;
        float* aggp = g_agg + (size_t)g_row[e] * D;
        uint32_t d0[32], d1[32];
        TC_LD_X32(d0, tbase + TMEM_D2 + c0 * 32);
        TC_LD_X32(d1, tbase + TMEM_D2 + (c0 + 1) * 32);
        TC_WAIT_LD();
        #pragma unroll
        for (int q = 0; q < 8; ++q) {
            float v0 = silu_f(__uint_as_float(d0[q*4+0]) + s_eb2[c0*32+q*4+0]);
            float v1 = silu_f(__uint_as_float(d0[q*4+1]) + s_eb2[c0*32+q*4+1]);
            float v2 = silu_f(__uint_as_float(d0[q*4+2]) + s_eb2[c0*32+q*4+2]);
            float v3 = silu_f(__uint_as_float(d0[q*4+3]) + s_eb2[c0*32+q*4+3]);
            asm volatile("red.global.add.v4.f32 [%0], {%1,%2,%3,%4};"
                         :: "l"(aggp + c0 * 32 + q * 4),
                            "f"(v0), "f"(v1), "f"(v2), "f"(v3) : "memory");
        }
        #pragma unroll
        for (int q = 0; q < 8; ++q) {
            float v0 = silu_f(__uint_as_float(d1[q*4+0]) + s_eb2[(c0+1)*32+q*4+0]);
            float v1 = silu_f(__uint_as_float(d1[q*4+1]) + s_eb2[(c0+1)*32+q*4+1]);
            float v2 = silu_f(__uint_as_float(d1[q*4+2]) + s_eb2[(c0+1)*32+q*4+2]);
            float v3 = silu_f(__uint_as_float(d1[q*4+3]) + s_eb2[(c0+1)*32+q*4+3]);
            asm volatile("red.global.add.v4.f32 [%0], {%1,%2,%3,%4};"
                         :: "l"(aggp + (c0 + 1) * 32 + q * 4),
                            "f"(v0), "f"(v1), "f"(v2), "f"(v3) : "memory");
        }
    };

    // prologue
    if (wid < 4 && blockIdx.x < NTILES) { gather(blockIdx.x); FENCE_PROXY_ASYNC(); }
    __syncthreads();
    if (wid == 4 && blockIdx.x < NTILES) {
        TC_FENCE_AFTER();
        if (elect_one()) {
            #pragma unroll 1
            for (int s = 0; s < 17; ++s)
                TC_MMA_SS(tbase + TMEM_D1, a1d + koff(s), w1d + koff(s), s > 0);
            TC_COMMIT(mbar1);
        }
    }

    int ph1 = 0, ph2 = 0;
    for (int tile = blockIdx.x; tile < NTILES; tile += nblocks) {
        const bool has_next = (tile + nblocks < NTILES);

        if (wid < 4) {
            MBAR_WAIT(mbar1, ph1);
            TC_FENCE_AFTER();
            e1_half(2);
            TC_FENCE_BEFORE();
            NAMED_ARRIVE(1, 256);
            if (has_next) {
                gather(tile + nblocks); FENCE_PROXY_ASYNC();
                NAMED_ARRIVE(2, 160);
            }
            MBAR_WAIT(mbar2, ph2);
            TC_FENCE_AFTER();
            e2_half(tile, 2);
            TC_FENCE_BEFORE();
        } else {
            MBAR_WAIT(mbar1, ph1);
            TC_FENCE_AFTER();
            e1_half(0);
            TC_FENCE_BEFORE();
            NAMED_BAR(1, 256);

            if (wid == 4) {
                TC_FENCE_AFTER();
                if (elect_one()) {
                    #pragma unroll 1
                    for (int s = 0; s < 8; ++s)
                        TC_MMA_TS(tbase + TMEM_D2, tbase + TMEM_A2 + s * 8,
                                  w2d + koff(s), s > 0);
                    TC_COMMIT(mbar2);
                }
                if (has_next) {
                    NAMED_BAR(2, 160);
                    if (elect_one()) {
                        #pragma unroll 1
                        for (int s = 0; s < 17; ++s)
                            TC_MMA_SS(tbase + TMEM_D1, a1d + koff(s), w1d + koff(s), s > 0);
                        TC_COMMIT(mbar1);
                    }
                }
            }
            MBAR_WAIT(mbar2, ph2);
            TC_FENCE_AFTER();
            e2_half(tile, 0);
            TC_FENCE_BEFORE();
        }
        ph1 ^= 1; ph2 ^= 1;
    }

    __syncthreads();
    if (wid == 0) { TC_RELINQ(); TC_DEALLOC(tbase, 512); }

#else
    // plain-sm_103 fallback (never selected on GB300)
    const int tid = threadIdx.x;
    if (tid >= TM) return;
    for (int tile = blockIdx.x; tile < NTILES; tile += nblocks) {
        const int e = tile * TM + tid;
        const int r = g_row[e], c = g_col[e];
        float a[K1];
        #pragma unroll 4
        for (int j = 0; j < D; ++j) { a[j] = x[(size_t)r * D + j]; a[D + j] = x[(size_t)c * D + j]; }
        #pragma unroll
        for (int j = 0; j < DE; ++j) a[2 * D + j] = ea[(size_t)e * DE + j];
        float h[D];
        for (int n = 0; n < D; ++n) {
            float s = eb1[n];
            for (int k = 0; k < K1; ++k) s = fmaf(a[k], eW1raw[(size_t)k * D + n], s);
            h[n] = silu_f(s);
        }
        for (int n = 0; n < D; ++n) {
            float s = eb2[n];
            for (int k = 0; k < D; ++k) s = fmaf(h[k], eW2raw[(size_t)k * D + n], s);
            atomicAdd(g_agg + (size_t)r * D + n, silu_f(s));
        }
    }
#endif
}

// ---------------- fused node kernel (tcgen05 tf32, TS mode) ---------------
__global__ __launch_bounds__(128, 1) void k_node_fused(
    const float* __restrict__ x,
    const float* __restrict__ nb1, const float* __restrict__ nb2,
    const float* __restrict__ nW1raw, const float* __restrict__ nW2raw,
    float* __restrict__ out, int nblocks)
{
#if defined(__CUDA_ARCH__) && defined(__CUDA_ARCH_FEAT_SM103_ALL)
    extern __shared__ uint32_t dsm[];
    __shared__ float s_b1[D], s_b2[D];
    __shared__ uint32_t s_tmem[1];
    __shared__ __align__(8) unsigned long long s_mbar;

    const int tid = threadIdx.x;
    const int wid = tid >> 5;
    const int lane = tid & 31;
    const uint32_t woff = (uint32_t)wid << 21;

    const uint32_t dyn_base = smem_u32(dsm);
    const uint32_t ws1 = (dyn_base + 1023u) & ~1023u;
    const uint32_t ws2 = ws1 + NW1_WORDS * 4;
    uint32_t* w1p = dsm + ((ws1 - dyn_base) >> 2);

    {
        uint4* dst = (uint4*)w1p; const uint4* src = (const uint4*)g_NW1B;
        for (int i = tid; i < (NW1_WORDS + NW2_WORDS) / 4; i += 128) dst[i] = src[i];
        if (tid < D) { s_b1[tid] = nb1[tid]; s_b2[tid] = nb2[tid]; }
    }
    if (wid == 0) TC_ALLOC(smem_u32(s_tmem), 512);
    if (tid == 0) MBAR_INIT(smem_u32(&s_mbar), 1);
    __syncthreads();
    const uint32_t tbase = s_tmem[0];
    const uint32_t mbar = smem_u32(&s_mbar);
    const uint64_t w1d = mk_desc(ws1);
    const uint64_t w2d = mk_desc(ws2);

    int ph = 0;
    for (int tile = blockIdx.x; tile < NNT; tile += nblocks) {
        __syncthreads();

        {
            int n = tile * 128 + tid;
            if (n >= N_NODES) n = N_NODES - 1;
            const float4* xr = (const float4*)(x + (size_t)n * D);
            const float4* ar = (const float4*)(g_agg + (size_t)n * D);
            uint32_t a[32];
            #pragma unroll 1
            for (int ch = 0; ch < 4; ++ch) {
                #pragma unroll
                for (int q = 0; q < 8; ++q) {
                    float4 v = xr[ch * 8 + q];
                    a[q*4+0] = f2tf32(v.x); a[q*4+1] = f2tf32(v.y);
                    a[q*4+2] = f2tf32(v.z); a[q*4+3] = f2tf32(v.w);
                }
                TC_ST_X32(tbase + ch * 32 + woff, a);
            }
            #pragma unroll 1
            for (int ch = 0; ch < 4; ++ch) {
                #pragma unroll
                for (int q = 0; q < 8; ++q) {
                    float4 v = ar[ch * 8 + q];
                    a[q*4+0] = f2tf32(v.x); a[q*4+1] = f2tf32(v.y);
                    a[q*4+2] = f2tf32(v.z); a[q*4+3] = f2tf32(v.w);
                }
                TC_ST_X32(tbase + 128 + ch * 32 + woff, a);
            }
        }
        TC_WAIT_ST();
        TC_FENCE_BEFORE();
        __syncthreads();

        if (wid == 0) {
            TC_FENCE_AFTER();
            if (elect_one()) {
                #pragma unroll 1
                for (int s = 0; s < 32; ++s)
                    TC_MMA_TF32_TS(tbase + 256, tbase + s * 8, w1d + koff(s), s > 0);
                TC_COMMIT(mbar);
            }
        }
        MBAR_WAIT(mbar, ph); ph ^= 1;
        TC_FENCE_AFTER();

        #pragma unroll 1
        for (int ch = 0; ch < 4; ++ch) {
            uint32_t dreg[32], areg[32];
            TC_LD_X32(dreg, tbase + 256 + ch * 32);
            TC_WAIT_LD();
            #pragma unroll
            for (int j = 0; j < 32; ++j)
                areg[j] = f2tf32(silu_f(__uint_as_float(dreg[j]) + s_b1[ch * 32 + j]));
            TC_ST_X32(tbase + ch * 32 + woff, areg);
        }
        TC_WAIT_ST();
        TC_FENCE_BEFORE();
        __syncthreads();

        if (wid == 0) {
            TC_FENCE_AFTER();
            if (elect_one()) {
                #pragma unroll 1
                for (int s = 0; s < 16; ++s)
                    TC_MMA_TF32_TS(tbase + 128, tbase + s * 8, w2d + koff(s), s > 0);
                TC_COMMIT(mbar);
            }
        }
        MBAR_WAIT(mbar, ph); ph ^= 1;
        TC_FENCE_AFTER();

        {
            const int n = tile * 128 + wid * 32 + lane;
            const bool valid = (n < N_NODES);
            const float4* xr = (const float4*)(x + (size_t)n * D);
            float4* orow = (float4*)(out + (size_t)n * D);
            #pragma unroll 1
            for (int ch = 0; ch < 4; ++ch) {
                uint32_t dreg[32];
                TC_LD_X32(dreg, tbase + 128 + ch * 32);
                TC_WAIT_LD();
                if (valid) {
                    #pragma unroll
                    for (int q = 0; q < 8; ++q) {
                        float4 xv = xr[ch * 8 + q];
                        float4 o;
                        o.x = xv.x + __uint_as_float(dreg[q*4+0]) + s_b2[ch*32+q*4+0];
                        o.y = xv.y + __uint_as_float(dreg[q*4+1]) + s_b2[ch*32+q*4+1];
                        o.z = xv.z + __uint_as_float(dreg[q*4+2]) + s_b2[ch*32+q*4+2];
                        o.w = xv.w + __uint_as_float(dreg[q*4+3]) + s_b2[ch*32+q*4+3];
                        orow[ch * 8 + q] = o;
                    }
                }
            }
            TC_FENCE_BEFORE();
        }
    }

    __syncthreads();
    if (wid == 0) { TC_RELINQ(); TC_DEALLOC(tbase, 512); }

#else
    const int tid = threadIdx.x;
    for (int n = blockIdx.x * 128 + tid; n < N_NODES; n += nblocks * 128) {
        float t[D];
        for (int o = 0; o < D; ++o) {
            float s = nb1[o];
            for (int k = 0; k < D; ++k) {
                s = fmaf(x[(size_t)n * D + k], nW1raw[(size_t)k * D + o], s);
                s = fmaf(g_agg[(size_t)n * D + k], nW1raw[(size_t)(D + k) * D + o], s);
            }
            t[o] = silu_f(s);
        }
        for (int o = 0; o < D; ++o) {
            float s = nb2[o];
            for (int k = 0; k < D; ++k) s = fmaf(t[k], nW2raw[(size_t)k * D + o], s);
            out[(size_t)n * D + o] = x[(size_t)n * D + o] + s;
        }
    }
#endif
}

// ---------------- launch --------------------------------------------------
extern "C" void kernel_launch(void* const* d_in, const int* in_sizes, int n_in,
                              void* d_out, int out_size)
{
    const float* x   = (const float*)d_in[0];
    const void*  ei  = d_in[1];
    const float* ea  = (const float*)d_in[2];
    const float* eW1 = (const float*)d_in[3];
    const float* eb1 = (const float*)d_in[4];
    const float* eW2 = (const float*)d_in[5];
    const float* eb2 = (const float*)d_in[6];
    const float* nW1 = (const float*)d_in[7];
    const float* nb1 = (const float*)d_in[8];
    const float* nW2 = (const float*)d_in[9];
    const float* nb2 = (const float*)d_in[10];
    float* out = (float*)d_out;

    int sms = 148;
    cudaDeviceGetAttribute(&sms, cudaDevAttrMultiProcessorCount, 0);

    const int s_edge = 1024 + W1B_BYTES + W2B_BYTES + A1B_BYTES;
    const int s_node = 1024 + (NW1_WORDS + NW2_WORDS) * 4;

    cudaFuncSetAttribute(k_edge_fused, cudaFuncAttributeMaxDynamicSharedMemorySize, s_edge);
    cudaFuncSetAttribute(k_node_fused, cudaFuncAttributeMaxDynamicSharedMemorySize, s_node);

    const int prep_elems = 128 * K1PAD + 128 * 128 + 128 * 256 + 128 * 128;
    const size_t cz = (size_t)N_NODES * D;

    k_detect<<<1, 1>>>((const int*)ei);
    k_convert_zero<<<(int)((cz + 255) / 256), 256>>>(ei, x);
    k_prep<<<(prep_elems + 255) / 256, 256>>>(eW1, eW2, nW1, nW2);
    k_edge_fused<<<sms, 256, s_edge>>>(x, ea, eb1, eb2, eW1, eW2, sms);
    k_node_fused<<<sms, 128, s_node>>>(x, nb1, nb2, nW1, nW2, out, sms);
}

// round 14
// speedup vs baseline: 1.3592x; 1.0810x over previous
#include <cuda_runtime.h>
#include <cuda_bf16.h>
#include <cstdint>

#define N_NODES 50000
#define N_EDGES 800000
#define D 128
#define DE 16
#define K1 272
#define K1PAD 320
#define TM 128
#define NTILES (N_EDGES / TM)           // 6250
#define NNT ((N_NODES + 127) / 128)     // 391

#define W1B_BYTES (128 * K1PAD * 2)   // 81920
#define W2B_BYTES (128 * 128 * 2)     // 32768
#define A1B_BYTES (128 * K1PAD * 2)   // 81920
#define NW1_WORDS (256 * 128)
#define NW2_WORDS (128 * 128)

// edge TMEM
#define TMEM_D1 0
#define TMEM_D2 128
#define TMEM_A2 256

#define IDESC_BF16 0x8200490u
#define IDESC_TF32 0x8200910u

// ---------------- scratch -----------------------------------------------
__device__ int      g_is64;
__device__ int      g_row[N_EDGES];
__device__ int      g_col[N_EDGES];
__device__ float    g_agg[(size_t)N_NODES * D];
__device__ uint16_t g_xb[(size_t)N_NODES * D];   // bf16 x copy (12.8MB, L2-resident)
__device__ uint16_t g_W1B[W1B_BYTES / 2];
__device__ uint16_t g_W2B[W2B_BYTES / 2];
__device__ uint32_t g_NW1B[NW1_WORDS];
__device__ uint32_t g_NW2B[NW2_WORDS];

__device__ __forceinline__ float silu_f(float v) {
    float t;
    asm("tanh.approx.f32 %0, %1;" : "=f"(t) : "f"(0.5f * v));
    return v * fmaf(0.5f, t, 0.5f);
}
__device__ __forceinline__ uint32_t smem_u32(const void* p) {
    uint32_t a;
    asm("{ .reg .u64 t; cvta.to.shared.u64 t, %1; cvt.u32.u64 %0, t; }"
        : "=r"(a) : "l"(p));
    return a;
}
__device__ __forceinline__ uint32_t pack_bf16x2(float lo, float hi) {
    uint32_t d;
    asm("cvt.rn.bf16x2.f32 %0, %1, %2;" : "=r"(d) : "f"(hi), "f"(lo));
    return d;
}
__device__ __forceinline__ uint16_t bf16_bits(float v) {
    __nv_bfloat16 b = __float2bfloat16(v);
    return *reinterpret_cast<uint16_t*>(&b);
}
__device__ __forceinline__ uint32_t f2tf32(float f) {
    uint32_t u;
    asm("cvt.rna.tf32.f32 %0, %1;" : "=r"(u) : "f"(f));
    return u;
}
__device__ __forceinline__ void sts8(uint32_t addr, uint32_t a, uint32_t b) {
    asm volatile("st.shared.v2.b32 [%0], {%1, %2};" :: "r"(addr), "r"(a), "r"(b) : "memory");
}
__device__ __forceinline__ uint32_t abyte(int row, int k) {
    return (uint32_t)((((row >> 3) + ((k >> 6) << 4)) << 10) | ((row & 7) << 7) | ((k & 63) << 1));
}
__device__ __forceinline__ uint32_t abyte32(int row, int k) {
    return (uint32_t)((((row >> 3) + ((k >> 5) << 4)) << 10) | ((row & 7) << 7) | ((k & 31) << 2));
}
__device__ __forceinline__ uint32_t swz(uint32_t b) {
    return b ^ ((b >> 3) & 0x70);
}

#if defined(__CUDA_ARCH__) && defined(__CUDA_ARCH_FEAT_SM103_ALL)

__device__ __forceinline__ uint32_t elect_one() {
    uint32_t pred;
    asm volatile("{\n\t.reg .pred p;\n\telect.sync _|p, 0xFFFFFFFF;\n\t"
                 "selp.b32 %0, 1, 0, p;\n\t}" : "=r"(pred));
    return pred;
}

#define TC_ALLOC(smemaddr, n) \
    asm volatile("tcgen05.alloc.cta_group::1.sync.aligned.shared::cta.b32 [%0], %1;" \
                 :: "r"(smemaddr), "r"((uint32_t)(n)) : "memory")
#define TC_RELINQ() \
    asm volatile("tcgen05.relinquish_alloc_permit.cta_group::1.sync.aligned;")
#define TC_DEALLOC(tmem, n) \
    asm volatile("tcgen05.dealloc.cta_group::1.sync.aligned.b32 %0, %1;" \
                 :: "r"(tmem), "r"((uint32_t)(n)))
#define TC_WAIT_ST() asm volatile("tcgen05.wait::st.sync.aligned;" ::: "memory")
#define TC_WAIT_LD() asm volatile("tcgen05.wait::ld.sync.aligned;" ::: "memory")
#define TC_FENCE_BEFORE() asm volatile("tcgen05.fence::before_thread_sync;" ::: "memory")
#define TC_FENCE_AFTER()  asm volatile("tcgen05.fence::after_thread_sync;" ::: "memory")
#define TC_COMMIT(mbar) \
    asm volatile("tcgen05.commit.cta_group::1.mbarrier::arrive::one.shared::cluster.b64 [%0];" \
                 :: "r"(mbar) : "memory")
#define MBAR_INIT(mbar, cnt) \
    asm volatile("mbarrier.init.shared.b64 [%0], %1;" :: "r"(mbar), "r"((uint32_t)(cnt)) : "memory")
#define FENCE_PROXY_ASYNC() \
    asm volatile("fence.proxy.async.shared::cta;" ::: "memory")
#define NAMED_BAR(id, n) \
    asm volatile("bar.sync %0, %1;" :: "r"(id), "r"(n) : "memory")
#define NAMED_ARRIVE(id, n) \
    asm volatile("bar.arrive %0, %1;" :: "r"(id), "r"(n) : "memory")

#define MBAR_WAIT(mbar, ph) do {                                             \
    uint32_t _m = (mbar), _p = (uint32_t)(ph), _d;                           \
    asm volatile("{\n\t.reg .pred p;\n\t"                                    \
        "mbarrier.try_wait.parity.acquire.cta.shared::cta.b64 p, [%1], %2;\n\t" \
        "selp.b32 %0, 1, 0, p;\n\t}" : "=r"(_d) : "r"(_m), "r"(_p) : "memory"); \
    if (!_d) {                                                               \
        asm volatile("{\n\t.reg .pred P1;\n\t"                               \
            "WL_%=:\n\t"                                                     \
            "mbarrier.try_wait.parity.acquire.cta.shared::cta.b64 P1, [%0], %1, 0x989680;\n\t" \
            "@P1 bra.uni WD_%=;\n\t"                                         \
            "bra.uni WL_%=;\n\t"                                             \
            "WD_%=:\n\t}" :: "r"(_m), "r"(_p) : "memory");                   \
    }                                                                        \
} while (0)

#define TC_MMA_SS(dtm, adesc, bdesc, en) do {                                \
    uint32_t _e = (en) ? 1u : 0u;                                            \
    asm volatile("{\n\t.reg .pred p;\n\t"                                    \
        "setp.ne.u32 p, %5, 0;\n\t"                                          \
        "tcgen05.mma.cta_group::1.kind::f16 [%0], %1, %2, %3, {%4, %4, %4, %4}, p;\n\t" \
        "}" :: "r"(dtm), "l"(adesc), "l"(bdesc), "r"(IDESC_BF16),            \
               "r"(0u), "r"(_e) : "memory");                                 \
} while (0)

#define TC_MMA_TS(dtm, atm, bdesc, en) do {                                  \
    uint32_t _e = (en) ? 1u : 0u;                                            \
    asm volatile("{\n\t.reg .pred p;\n\t"                                    \
        "setp.ne.u32 p, %5, 0;\n\t"                                          \
        "tcgen05.mma.cta_group::1.kind::f16 [%0], [%1], %2, %3, {%4, %4, %4, %4}, p;\n\t" \
        "}" :: "r"(dtm), "r"(atm), "l"(bdesc), "r"(IDESC_BF16),              \
               "r"(0u), "r"(_e) : "memory");                                 \
} while (0)

#define TC_MMA_TF32_TS(dtm, atm, bdesc, en) do {                             \
    uint32_t _e = (en) ? 1u : 0u;                                            \
    asm volatile("{\n\t.reg .pred p;\n\t"                                    \
        "setp.ne.u32 p, %5, 0;\n\t"                                          \
        "tcgen05.mma.cta_group::1.kind::tf32 [%0], [%1], %2, %3, {%4, %4, %4, %4}, p;\n\t" \
        "}" :: "r"(dtm), "r"(atm), "l"(bdesc), "r"(IDESC_TF32),              \
               "r"(0u), "r"(_e) : "memory");                                 \
} while (0)

#define TC_ST_X16(tmem_addr, r)                                              \
    asm volatile("tcgen05.st.sync.aligned.32x32b.x16.b32 [%0], "             \
        "{%1, %2, %3, %4, %5, %6, %7, %8, "                                  \
        " %9, %10, %11, %12, %13, %14, %15, %16};"                           \
        :: "r"(tmem_addr),                                                   \
           "r"((r)[0]),  "r"((r)[1]),  "r"((r)[2]),  "r"((r)[3]),            \
           "r"((r)[4]),  "r"((r)[5]),  "r"((r)[6]),  "r"((r)[7]),            \
           "r"((r)[8]),  "r"((r)[9]),  "r"((r)[10]), "r"((r)[11]),           \
           "r"((r)[12]), "r"((r)[13]), "r"((r)[14]), "r"((r)[15])            \
        : "memory")

#define TC_ST_X32(tmem_addr, r)                                              \
    asm volatile("tcgen05.st.sync.aligned.32x32b.x32.b32 [%0], "             \
        "{%1, %2, %3, %4, %5, %6, %7, %8, "                                  \
        " %9, %10, %11, %12, %13, %14, %15, %16, "                           \
        " %17, %18, %19, %20, %21, %22, %23, %24, "                          \
        " %25, %26, %27, %28, %29, %30, %31, %32};"                          \
        :: "r"(tmem_addr),                                                   \
           "r"((r)[0]),  "r"((r)[1]),  "r"((r)[2]),  "r"((r)[3]),            \
           "r"((r)[4]),  "r"((r)[5]),  "r"((r)[6]),  "r"((r)[7]),            \
           "r"((r)[8]),  "r"((r)[9]),  "r"((r)[10]), "r"((r)[11]),           \
           "r"((r)[12]), "r"((r)[13]), "r"((r)[14]), "r"((r)[15]),           \
           "r"((r)[16]), "r"((r)[17]), "r"((r)[18]), "r"((r)[19]),           \
           "r"((r)[20]), "r"((r)[21]), "r"((r)[22]), "r"((r)[23]),           \
           "r"((r)[24]), "r"((r)[25]), "r"((r)[26]), "r"((r)[27]),           \
           "r"((r)[28]), "r"((r)[29]), "r"((r)[30]), "r"((r)[31])            \
        : "memory")

#define TC_LD_X32(r, tmem_addr)                                              \
    asm volatile("tcgen05.ld.sync.aligned.32x32b.x32.b32 "                   \
        "{%0, %1, %2, %3, %4, %5, %6, %7, "                                  \
        " %8, %9, %10, %11, %12, %13, %14, %15, "                            \
        " %16, %17, %18, %19, %20, %21, %22, %23, "                          \
        " %24, %25, %26, %27, %28, %29, %30, %31}, [%32];"                   \
        : "=r"((r)[0]),  "=r"((r)[1]),  "=r"((r)[2]),  "=r"((r)[3]),         \
          "=r"((r)[4]),  "=r"((r)[5]),  "=r"((r)[6]),  "=r"((r)[7]),         \
          "=r"((r)[8]),  "=r"((r)[9]),  "=r"((r)[10]), "=r"((r)[11]),        \
          "=r"((r)[12]), "=r"((r)[13]), "=r"((r)[14]), "=r"((r)[15]),        \
          "=r"((r)[16]), "=r"((r)[17]), "=r"((r)[18]), "=r"((r)[19]),        \
          "=r"((r)[20]), "=r"((r)[21]), "=r"((r)[22]), "=r"((r)[23]),        \
          "=r"((r)[24]), "=r"((r)[25]), "=r"((r)[26]), "=r"((r)[27]),        \
          "=r"((r)[28]), "=r"((r)[29]), "=r"((r)[30]), "=r"((r)[31])         \
        : "r"(tmem_addr))

static constexpr unsigned long long SMEM_DESC_BASE =
    (2ull << 61) | (1ull << 46) | (64ull << 32) | (1ull << 16);
__device__ __forceinline__ uint64_t mk_desc(uint32_t addr) {
    return SMEM_DESC_BASE | ((uint64_t)(addr >> 4) & 0x3FFF);
}
__device__ __forceinline__ uint64_t koff(int s) {
    return (uint64_t)((s >> 2) * 1024 + (s & 3) * 2);
}

#endif // sm_103a device helpers

// ---------------- small kernels ------------------------------------------
__global__ void k_detect(const int* ei32) {
    if (blockIdx.x == 0 && threadIdx.x == 0) {
        int is64 = 1;
        #pragma unroll 1
        for (int i = 0; i < 64; ++i)
            if (ei32[2 * i + 1] != 0) { is64 = 0; break; }
        g_is64 = is64;
    }
}
__global__ void k_convert_zero(const void* ei, const float* __restrict__ x) {
    size_t i = (size_t)blockIdx.x * blockDim.x + threadIdx.x;
    if (i < N_EDGES) {
        if (g_is64) {
            const long long* p = (const long long*)ei;
            g_row[i] = (int)p[i];
            g_col[i] = (int)p[(size_t)N_EDGES + i];
        } else {
            const int* p = (const int*)ei;
            g_row[i] = p[i];
            g_col[i] = p[N_EDGES + i];
        }
    }
    if (i < (size_t)N_NODES * D) {
        g_agg[i] = 0.0f;
        g_xb[i] = bf16_bits(x[i]);
    }
}
__global__ void k_prep(const float* __restrict__ W1, const float* __restrict__ W2,
                       const float* __restrict__ NW1, const float* __restrict__ NW2) {
    int i = blockIdx.x * blockDim.x + threadIdx.x;
    if (i < 128 * K1PAD) {
        int n = i / K1PAD, k = i % K1PAD;
        float v = (k < K1) ? W1[(size_t)k * 128 + n] : 0.0f;
        g_W1B[swz(abyte(n, k)) >> 1] = bf16_bits(v);
        return;
    }
    i -= 128 * K1PAD;
    if (i < 128 * 128) {
        int n = i / 128, k = i % 128;
        g_W2B[swz(abyte(n, k)) >> 1] = bf16_bits(W2[(size_t)k * 128 + n]);
        return;
    }
    i -= 128 * 128;
    if (i < 128 * 256) {
        int n = i / 256, k = i % 256;
        g_NW1B[swz(abyte32(n, k)) >> 2] = f2tf32(NW1[(size_t)k * 128 + n]);
        return;
    }
    i -= 128 * 256;
    if (i < 128 * 128) {
        int n = i / 128, k = i % 128;
        g_NW2B[swz(abyte32(n, k)) >> 2] = f2tf32(NW2[(size_t)k * 128 + n]);
    }
}

// ---------------- fused edge kernel: 512 threads, 1 chunk per warp --------
__global__ __launch_bounds__(512, 1) void k_edge_fused(
    const float* __restrict__ x, const float* __restrict__ ea,
    const float* __restrict__ eb1, const float* __restrict__ eb2,
    const float* __restrict__ eW1raw, const float* __restrict__ eW2raw,
    int nblocks)
{
#if defined(__CUDA_ARCH__) && defined(__CUDA_ARCH_FEAT_SM103_ALL)
    extern __shared__ uint32_t dsm[];
    __shared__ float s_eb1[D], s_eb2[D];
    __shared__ uint32_t s_tmem[1];
    __shared__ __align__(8) unsigned long long s_mbar1, s_mbar2;

    const int tid = threadIdx.x;
    const int wid = tid >> 5;          // 0..15
    const int lane = tid & 31;
    const int chunk = wid >> 2;        // D-column chunk 0..3
    const int sub = wid & 3;           // TMEM subpartition
    const uint32_t subo = (uint32_t)sub << 21;

    const uint32_t dyn_base = smem_u32(dsm);
    const uint32_t ws1 = (dyn_base + 1023u) & ~1023u;
    const uint32_t ws2 = ws1 + W1B_BYTES;
    const uint32_t wsA = ws2 + W2B_BYTES;
    uint32_t* w1p = dsm + ((ws1 - dyn_base) >> 2);

    {
        uint4* dst = (uint4*)w1p; const uint4* src = (const uint4*)g_W1B;
        for (int i = tid; i < (W1B_BYTES + W2B_BYTES) / 16; i += 512) dst[i] = src[i];
        if (tid < D) { s_eb1[tid] = eb1[tid]; s_eb2[tid] = eb2[tid]; }
        for (int i = tid; i < 128 * 12; i += 512) {
            int row = i / 12, j = i % 12;
            sts8(wsA + swz(abyte(row, 272 + j * 4)), 0u, 0u);
        }
    }
    if (wid == 0) TC_ALLOC(smem_u32(s_tmem), 512);
    if (tid == 0) { MBAR_INIT(smem_u32(&s_mbar1), 1); MBAR_INIT(smem_u32(&s_mbar2), 1); }
    __syncthreads();
    const uint32_t tbase = s_tmem[0];
    const uint32_t mbar1 = smem_u32(&s_mbar1);
    const uint32_t mbar2 = smem_u32(&s_mbar2);
    const uint64_t a1d = mk_desc(wsA);
    const uint64_t w1d = mk_desc(ws1);
    const uint64_t w2d = mk_desc(ws2);

    // gather: warp gw (0..7) fills A1 rows gw*16 .. gw*16+15
    auto gather = [&](int tile) {
        const int gw = wid;
        const int e0 = tile * TM + gw * 16;
        const int myr = g_row[e0 + (lane & 15)];
        const int myc = g_col[e0 + (lane & 15)];
        #pragma unroll 16
        for (int i = 0; i < 16; ++i) {
            const int el = gw * 16 + i;
            const int r = __shfl_sync(0xffffffffu, myr, i);
            const int c = __shfl_sync(0xffffffffu, myc, i);
            uint2 v = *(const uint2*)(g_xb + (size_t)r * D + lane * 4);
            sts8(wsA + swz(abyte(el, lane * 4)), v.x, v.y);
            v = *(const uint2*)(g_xb + (size_t)c * D + lane * 4);
            sts8(wsA + swz(abyte(el, 128 + lane * 4)), v.x, v.y);
        }
        #pragma unroll
        for (int i = 0; i < 2; ++i) {
            const int el = gw * 16 + i * 8 + (lane >> 2);
            const int e = tile * TM + el;
            float4 v = *(const float4*)(ea + (size_t)e * DE + (lane & 3) * 4);
            sts8(wsA + swz(abyte(el, 256 + (lane & 3) * 4)),
                 pack_bf16x2(v.x, v.y), pack_bf16x2(v.z, v.w));
        }
    };

    // E1 one chunk: D1[chunk] -> bias+silu -> A2[chunk] (this warp's subpartition)
    auto e1_one = [&]() {
        uint32_t dreg[32], areg[16];
        TC_LD_X32(dreg, tbase + TMEM_D1 + chunk * 32);
        TC_WAIT_LD();
        #pragma unroll
        for (int m = 0; m < 16; ++m) {
            float v0 = silu_f(__uint_as_float(dreg[2*m])   + s_eb1[chunk*32 + 2*m]);
            float v1 = silu_f(__uint_as_float(dreg[2*m+1]) + s_eb1[chunk*32 + 2*m+1]);
            areg[m] = pack_bf16x2(v0, v1);
        }
        TC_ST_X16(tbase + TMEM_A2 + chunk * 16 + subo, areg);
        TC_WAIT_ST();
    };

    // E2 one chunk: D2[chunk] -> bias+silu -> scatter
    auto e2_one = [&](int tile) {
        const int e = tile * TM + sub * 32 + lane;
        float* aggp = g_agg + (size_t)g_row[e] * D;
        uint32_t dreg[32];
        TC_LD_X32(dreg, tbase + TMEM_D2 + chunk * 32);
        TC_WAIT_LD();
        #pragma unroll
        for (int q = 0; q < 8; ++q) {
            float v0 = silu_f(__uint_as_float(dreg[q*4+0]) + s_eb2[chunk*32+q*4+0]);
            float v1 = silu_f(__uint_as_float(dreg[q*4+1]) + s_eb2[chunk*32+q*4+1]);
            float v2 = silu_f(__uint_as_float(dreg[q*4+2]) + s_eb2[chunk*32+q*4+2]);
            float v3 = silu_f(__uint_as_float(dreg[q*4+3]) + s_eb2[chunk*32+q*4+3]);
            asm volatile("red.global.add.v4.f32 [%0], {%1,%2,%3,%4};"
                         :: "l"(aggp + chunk * 32 + q * 4),
                            "f"(v0), "f"(v1), "f"(v2), "f"(v3) : "memory");
        }
    };

    // prologue
    if (wid < 8 && blockIdx.x < NTILES) { gather(blockIdx.x); FENCE_PROXY_ASYNC(); }
    __syncthreads();
    if (wid == 8 && blockIdx.x < NTILES) {
        TC_FENCE_AFTER();
        if (elect_one()) {
            #pragma unroll 1
            for (int s = 0; s < 17; ++s)
                TC_MMA_SS(tbase + TMEM_D1, a1d + koff(s), w1d + koff(s), s > 0);
            TC_COMMIT(mbar1);
        }
    }

    int ph1 = 0, ph2 = 0;
    for (int tile = blockIdx.x; tile < NTILES; tile += nblocks) {
        const bool has_next = (tile + nblocks < NTILES);

        if (wid < 8) {
            // ---- G-warps: E1(chunk), gather(t+1), E2(chunk) ----
            MBAR_WAIT(mbar1, ph1);
            TC_FENCE_AFTER();
            e1_one();
            TC_FENCE_BEFORE();
            NAMED_ARRIVE(1, 512);
            if (has_next) {
                gather(tile + nblocks); FENCE_PROXY_ASYNC();
                NAMED_ARRIVE(2, 288);
            }
            MBAR_WAIT(mbar2, ph2);
            TC_FENCE_AFTER();
            e2_one(tile);
            TC_FENCE_BEFORE();
        } else {
            // ---- C-warps (8..15): E1(chunk), MMA issue (warp 8), E2(chunk) ----
            MBAR_WAIT(mbar1, ph1);
            TC_FENCE_AFTER();
            e1_one();
            TC_FENCE_BEFORE();

            if (wid == 8) {
                NAMED_BAR(1, 512);          // all E1 done: A2 ready, D1 free
                TC_FENCE_AFTER();
                if (elect_one()) {
                    #pragma unroll 1
                    for (int s = 0; s < 8; ++s)
                        TC_MMA_TS(tbase + TMEM_D2, tbase + TMEM_A2 + s * 8,
                                  w2d + koff(s), s > 0);
                    TC_COMMIT(mbar2);
                }
                if (has_next) {
                    NAMED_BAR(2, 288);      // gather(t+1) complete
                    if (elect_one()) {
                        #pragma unroll 1
                        for (int s = 0; s < 17; ++s)
                            TC_MMA_SS(tbase + TMEM_D1, a1d + koff(s), w1d + koff(s), s > 0);
                        TC_COMMIT(mbar1);
                    }
                }
            } else {
                NAMED_ARRIVE(1, 512);
            }
            MBAR_WAIT(mbar2, ph2);
            TC_FENCE_AFTER();
            e2_one(tile);
            TC_FENCE_BEFORE();
        }
        ph1 ^= 1; ph2 ^= 1;
    }

    __syncthreads();
    if (wid == 0) { TC_RELINQ(); TC_DEALLOC(tbase, 512); }

#else
    // plain-sm_103 fallback (never selected on GB300)
    const int tid = threadIdx.x;
    if (tid >= TM) return;
    for (int tile = blockIdx.x; tile < NTILES; tile += nblocks) {
        const int e = tile * TM + tid;
        const int r = g_row[e], c = g_col[e];
        float a[K1];
        #pragma unroll 4
        for (int j = 0; j < D; ++j) { a[j] = x[(size_t)r * D + j]; a[D + j] = x[(size_t)c * D + j]; }
        #pragma unroll
        for (int j = 0; j < DE; ++j) a[2 * D + j] = ea[(size_t)e * DE + j];
        float h[D];
        for (int n = 0; n < D; ++n) {
            float s = eb1[n];
            for (int k = 0; k < K1; ++k) s = fmaf(a[k], eW1raw[(size_t)k * D + n], s);
            h[n] = silu_f(s);
        }
        for (int n = 0; n < D; ++n) {
            float s = eb2[n];
            for (int k = 0; k < D; ++k) s = fmaf(h[k], eW2raw[(size_t)k * D + n], s);
            atomicAdd(g_agg + (size_t)r * D + n, silu_f(s));
        }
    }
#endif
}

// ---------------- fused node kernel (tcgen05 tf32, TS mode) ---------------
__global__ __launch_bounds__(128, 1) void k_node_fused(
    const float* __restrict__ x,
    const float* __restrict__ nb1, const float* __restrict__ nb2,
    const float* __restrict__ nW1raw, const float* __restrict__ nW2raw,
    float* __restrict__ out, int nblocks)
{
#if defined(__CUDA_ARCH__) && defined(__CUDA_ARCH_FEAT_SM103_ALL)
    extern __shared__ uint32_t dsm[];
    __shared__ float s_b1[D], s_b2[D];
    __shared__ uint32_t s_tmem[1];
    __shared__ __align__(8) unsigned long long s_mbar;

    const int tid = threadIdx.x;
    const int wid = tid >> 5;
    const int lane = tid & 31;
    const uint32_t woff = (uint32_t)wid << 21;

    const uint32_t dyn_base = smem_u32(dsm);
    const uint32_t ws1 = (dyn_base + 1023u) & ~1023u;
    const uint32_t ws2 = ws1 + NW1_WORDS * 4;
    uint32_t* w1p = dsm + ((ws1 - dyn_base) >> 2);

    {
        uint4* dst = (uint4*)w1p; const uint4* src = (const uint4*)g_NW1B;
        for (int i = tid; i < (NW1_WORDS + NW2_WORDS) / 4; i += 128) dst[i] = src[i];
        if (tid < D) { s_b1[tid] = nb1[tid]; s_b2[tid] = nb2[tid]; }
    }
    if (wid == 0) TC_ALLOC(smem_u32(s_tmem), 512);
    if (tid == 0) MBAR_INIT(smem_u32(&s_mbar), 1);
    __syncthreads();
    const uint32_t tbase = s_tmem[0];
    const uint32_t mbar = smem_u32(&s_mbar);
    const uint64_t w1d = mk_desc(ws1);
    const uint64_t w2d = mk_desc(ws2);

    int ph = 0;
    for (int tile = blockIdx.x; tile < NNT; tile += nblocks) {
        __syncthreads();

        {
            int n = tile * 128 + tid;
            if (n >= N_NODES) n = N_NODES - 1;
            const float4* xr = (const float4*)(x + (size_t)n * D);
            const float4* ar = (const float4*)(g_agg + (size_t)n * D);
            uint32_t a[32];
            #pragma unroll 1
            for (int ch = 0; ch < 4; ++ch) {
                #pragma unroll
                for (int q = 0; q < 8; ++q) {
                    float4 v = xr[ch * 8 + q];
                    a[q*4+0] = f2tf32(v.x); a[q*4+1] = f2tf32(v.y);
                    a[q*4+2] = f2tf32(v.z); a[q*4+3] = f2tf32(v.w);
                }
                TC_ST_X32(tbase + ch * 32 + woff, a);
            }
            #pragma unroll 1
            for (int ch = 0; ch < 4; ++ch) {
                #pragma unroll
                for (int q = 0; q < 8; ++q) {
                    float4 v = ar[ch * 8 + q];
                    a[q*4+0] = f2tf32(v.x); a[q*4+1] = f2tf32(v.y);
                    a[q*4+2] = f2tf32(v.z); a[q*4+3] = f2tf32(v.w);
                }
                TC_ST_X32(tbase + 128 + ch * 32 + woff, a);
            }
        }
        TC_WAIT_ST();
        TC_FENCE_BEFORE();
        __syncthreads();

        if (wid == 0) {
            TC_FENCE_AFTER();
            if (elect_one()) {
                #pragma unroll 1
                for (int s = 0; s < 32; ++s)
                    TC_MMA_TF32_TS(tbase + 256, tbase + s * 8, w1d + koff(s), s > 0);
                TC_COMMIT(mbar);
            }
        }
        MBAR_WAIT(mbar, ph); ph ^= 1;
        TC_FENCE_AFTER();

        #pragma unroll 1
        for (int ch = 0; ch < 4; ++ch) {
            uint32_t dreg[32], areg[32];
            TC_LD_X32(dreg, tbase + 256 + ch * 32);
            TC_WAIT_LD();
            #pragma unroll
            for (int j = 0; j < 32; ++j)
                areg[j] = f2tf32(silu_f(__uint_as_float(dreg[j]) + s_b1[ch * 32 + j]));
            TC_ST_X32(tbase + ch * 32 + woff, areg);
        }
        TC_WAIT_ST();
        TC_FENCE_BEFORE();
        __syncthreads();

        if (wid == 0) {
            TC_FENCE_AFTER();
            if (elect_one()) {
                #pragma unroll 1
                for (int s = 0; s < 16; ++s)
                    TC_MMA_TF32_TS(tbase + 128, tbase + s * 8, w2d + koff(s), s > 0);
                TC_COMMIT(mbar);
            }
        }
        MBAR_WAIT(mbar, ph); ph ^= 1;
        TC_FENCE_AFTER();

        {
            const int n = tile * 128 + wid * 32 + lane;
            const bool valid = (n < N_NODES);
            const float4* xr = (const float4*)(x + (size_t)n * D);
            float4* orow = (float4*)(out + (size_t)n * D);
            #pragma unroll 1
            for (int ch = 0; ch < 4; ++ch) {
                uint32_t dreg[32];
                TC_LD_X32(dreg, tbase + 128 + ch * 32);
                TC_WAIT_LD();
                if (valid) {
                    #pragma unroll
                    for (int q = 0; q < 8; ++q) {
                        float4 xv = xr[ch * 8 + q];
                        float4 o;
                        o.x = xv.x + __uint_as_float(dreg[q*4+0]) + s_b2[ch*32+q*4+0];
                        o.y = xv.y + __uint_as_float(dreg[q*4+1]) + s_b2[ch*32+q*4+1];
                        o.z = xv.z + __uint_as_float(dreg[q*4+2]) + s_b2[ch*32+q*4+2];
                        o.w = xv.w + __uint_as_float(dreg[q*4+3]) + s_b2[ch*32+q*4+3];
                        orow[ch * 8 + q] = o;
                    }
                }
            }
            TC_FENCE_BEFORE();
        }
    }

    __syncthreads();
    if (wid == 0) { TC_RELINQ(); TC_DEALLOC(tbase, 512); }

#else
    const int tid = threadIdx.x;
    for (int n = blockIdx.x * 128 + tid; n < N_NODES; n += nblocks * 128) {
        float t[D];
        for (int o = 0; o < D; ++o) {
            float s = nb1[o];
            for (int k = 0; k < D; ++k) {
                s = fmaf(x[(size_t)n * D + k], nW1raw[(size_t)k * D + o], s);
                s = fmaf(g_agg[(size_t)n * D + k], nW1raw[(size_t)(D + k) * D + o], s);
            }
            t[o] = silu_f(s);
        }
        for (int o = 0; o < D; ++o) {
            float s = nb2[o];
            for (int k = 0; k < D; ++k) s = fmaf(t[k], nW2raw[(size_t)k * D + o], s);
            out[(size_t)n * D + o] = x[(size_t)n * D + o] + s;
        }
    }
#endif
}

// ---------------- launch --------------------------------------------------
extern "C" void kernel_launch(void* const* d_in, const int* in_sizes, int n_in,
                              void* d_out, int out_size)
{
    const float* x   = (const float*)d_in[0];
    const void*  ei  = d_in[1];
    const float* ea  = (const float*)d_in[2];
    const float* eW1 = (const float*)d_in[3];
    const float* eb1 = (const float*)d_in[4];
    const float* eW2 = (const float*)d_in[5];
    const float* eb2 = (const float*)d_in[6];
    const float* nW1 = (const float*)d_in[7];
    const float* nb1 = (const float*)d_in[8];
    const float* nW2 = (const float*)d_in[9];
    const float* nb2 = (const float*)d_in[10];
    float* out = (float*)d_out;

    int sms = 148;
    cudaDeviceGetAttribute(&sms, cudaDevAttrMultiProcessorCount, 0);

    const int s_edge = 1024 + W1B_BYTES + W2B_BYTES + A1B_BYTES;
    const int s_node = 1024 + (NW1_WORDS + NW2_WORDS) * 4;

    cudaFuncSetAttribute(k_edge_fused, cudaFuncAttributeMaxDynamicSharedMemorySize, s_edge);
    cudaFuncSetAttribute(k_node_fused, cudaFuncAttributeMaxDynamicSharedMemorySize, s_node);

    const int prep_elems = 128 * K1PAD + 128 * 128 + 128 * 256 + 128 * 128;
    const size_t cz = (size_t)N_NODES * D;

    k_detect<<<1, 1>>>((const int*)ei);
    k_convert_zero<<<(int)((cz + 255) / 256), 256>>>(ei, x);
    k_prep<<<(prep_elems + 255) / 256, 256>>>(eW1, eW2, nW1, nW2);
    k_edge_fused<<<sms, 512, s_edge>>>(x, ea, eb1, eb2, eW1, eW2, sms);
    k_node_fused<<<sms, 128, s_node>>>(x, nb1, nb2, nW1, nW2, out, sms);
}

// round 15
// speedup vs baseline: 1.5064x; 1.1083x over previous
#include <cuda_runtime.h>
#include <cuda_bf16.h>
#include <cstdint>

#define N_NODES 50000
#define N_EDGES 800000
#define D 128
#define DE 16
#define K1 272
#define K1PAD 320
#define TM 128
#define NTILES (N_EDGES / TM)           // 6250
#define NNT ((N_NODES + 127) / 128)     // 391

#define W1B_BYTES (128 * K1PAD * 2)   // 81920
#define W2B_BYTES (128 * 128 * 2)     // 32768
#define A1B_BYTES (128 * K1PAD * 2)   // 81920
#define NW1_WORDS (256 * 128)
#define NW2_WORDS (128 * 128)

// edge TMEM
#define TMEM_D1 0
#define TMEM_D2 128
#define TMEM_A2 256

#define IDESC_BF16 0x8200490u
#define IDESC_TF32 0x8200910u

// ---------------- scratch -----------------------------------------------
__device__ int      g_is64;
__device__ int      g_row[N_EDGES];
__device__ int      g_col[N_EDGES];
__device__ float    g_agg[(size_t)N_NODES * D];
__device__ uint16_t g_xb[(size_t)N_NODES * D];   // bf16 x copy (12.8MB, L2-resident)
__device__ uint16_t g_W1B[W1B_BYTES / 2];
__device__ uint16_t g_W2B[W2B_BYTES / 2];
__device__ uint32_t g_NW1B[NW1_WORDS];
__device__ uint32_t g_NW2B[NW2_WORDS];

__device__ __forceinline__ float silu_f(float v) {
    float t;
    asm("tanh.approx.f32 %0, %1;" : "=f"(t) : "f"(0.5f * v));
    return v * fmaf(0.5f, t, 0.5f);
}
__device__ __forceinline__ uint32_t smem_u32(const void* p) {
    uint32_t a;
    asm("{ .reg .u64 t; cvta.to.shared.u64 t, %1; cvt.u32.u64 %0, t; }"
        : "=r"(a) : "l"(p));
    return a;
}
__device__ __forceinline__ uint32_t pack_bf16x2(float lo, float hi) {
    uint32_t d;
    asm("cvt.rn.bf16x2.f32 %0, %1, %2;" : "=r"(d) : "f"(hi), "f"(lo));
    return d;
}
__device__ __forceinline__ uint16_t bf16_bits(float v) {
    __nv_bfloat16 b = __float2bfloat16(v);
    return *reinterpret_cast<uint16_t*>(&b);
}
__device__ __forceinline__ uint32_t f2tf32(float f) {
    uint32_t u;
    asm("cvt.rna.tf32.f32 %0, %1;" : "=r"(u) : "f"(f));
    return u;
}
__device__ __forceinline__ void sts8(uint32_t addr, uint32_t a, uint32_t b) {
    asm volatile("st.shared.v2.b32 [%0], {%1, %2};" :: "r"(addr), "r"(a), "r"(b) : "memory");
}
__device__ __forceinline__ uint32_t abyte(int row, int k) {
    return (uint32_t)((((row >> 3) + ((k >> 6) << 4)) << 10) | ((row & 7) << 7) | ((k & 63) << 1));
}
__device__ __forceinline__ uint32_t abyte32(int row, int k) {
    return (uint32_t)((((row >> 3) + ((k >> 5) << 4)) << 10) | ((row & 7) << 7) | ((k & 31) << 2));
}
__device__ __forceinline__ uint32_t swz(uint32_t b) {
    return b ^ ((b >> 3) & 0x70);
}

#if defined(__CUDA_ARCH__) && defined(__CUDA_ARCH_FEAT_SM103_ALL)

__device__ __forceinline__ uint32_t elect_one() {
    uint32_t pred;
    asm volatile("{\n\t.reg .pred p;\n\telect.sync _|p, 0xFFFFFFFF;\n\t"
                 "selp.b32 %0, 1, 0, p;\n\t}" : "=r"(pred));
    return pred;
}

#define TC_ALLOC(smemaddr, n) \
    asm volatile("tcgen05.alloc.cta_group::1.sync.aligned.shared::cta.b32 [%0], %1;" \
                 :: "r"(smemaddr), "r"((uint32_t)(n)) : "memory")
#define TC_RELINQ() \
    asm volatile("tcgen05.relinquish_alloc_permit.cta_group::1.sync.aligned;")
#define TC_DEALLOC(tmem, n) \
    asm volatile("tcgen05.dealloc.cta_group::1.sync.aligned.b32 %0, %1;" \
                 :: "r"(tmem), "r"((uint32_t)(n)))
#define TC_WAIT_ST() asm volatile("tcgen05.wait::st.sync.aligned;" ::: "memory")
#define TC_WAIT_LD() asm volatile("tcgen05.wait::ld.sync.aligned;" ::: "memory")
#define TC_FENCE_BEFORE() asm volatile("tcgen05.fence::before_thread_sync;" ::: "memory")
#define TC_FENCE_AFTER()  asm volatile("tcgen05.fence::after_thread_sync;" ::: "memory")
#define TC_COMMIT(mbar) \
    asm volatile("tcgen05.commit.cta_group::1.mbarrier::arrive::one.shared::cluster.b64 [%0];" \
                 :: "r"(mbar) : "memory")
#define MBAR_INIT(mbar, cnt) \
    asm volatile("mbarrier.init.shared.b64 [%0], %1;" :: "r"(mbar), "r"((uint32_t)(cnt)) : "memory")
#define FENCE_PROXY_ASYNC() \
    asm volatile("fence.proxy.async.shared::cta;" ::: "memory")
#define NAMED_BAR(id, n) \
    asm volatile("bar.sync %0, %1;" :: "r"(id), "r"(n) : "memory")
#define NAMED_ARRIVE(id, n) \
    asm volatile("bar.arrive %0, %1;" :: "r"(id), "r"(n) : "memory")

#define MBAR_WAIT(mbar, ph) do {                                             \
    uint32_t _m = (mbar), _p = (uint32_t)(ph), _d;                           \
    asm volatile("{\n\t.reg .pred p;\n\t"                                    \
        "mbarrier.try_wait.parity.acquire.cta.shared::cta.b64 p, [%1], %2;\n\t" \
        "selp.b32 %0, 1, 0, p;\n\t}" : "=r"(_d) : "r"(_m), "r"(_p) : "memory"); \
    if (!_d) {                                                               \
        asm volatile("{\n\t.reg .pred P1;\n\t"                               \
            "WL_%=:\n\t"                                                     \
            "mbarrier.try_wait.parity.acquire.cta.shared::cta.b64 P1, [%0], %1, 0x989680;\n\t" \
            "@P1 bra.uni WD_%=;\n\t"                                         \
            "bra.uni WL_%=;\n\t"                                             \
            "WD_%=:\n\t}" :: "r"(_m), "r"(_p) : "memory");                   \
    }                                                                        \
} while (0)

#define TC_MMA_SS(dtm, adesc, bdesc, en) do {                                \
    uint32_t _e = (en) ? 1u : 0u;                                            \
    asm volatile("{\n\t.reg .pred p;\n\t"                                    \
        "setp.ne.u32 p, %5, 0;\n\t"                                          \
        "tcgen05.mma.cta_group::1.kind::f16 [%0], %1, %2, %3, {%4, %4, %4, %4}, p;\n\t" \
        "}" :: "r"(dtm), "l"(adesc), "l"(bdesc), "r"(IDESC_BF16),            \
               "r"(0u), "r"(_e) : "memory");                                 \
} while (0)

#define TC_MMA_TS(dtm, atm, bdesc, en) do {                                  \
    uint32_t _e = (en) ? 1u : 0u;                                            \
    asm volatile("{\n\t.reg .pred p;\n\t"                                    \
        "setp.ne.u32 p, %5, 0;\n\t"                                          \
        "tcgen05.mma.cta_group::1.kind::f16 [%0], [%1], %2, %3, {%4, %4, %4, %4}, p;\n\t" \
        "}" :: "r"(dtm), "r"(atm), "l"(bdesc), "r"(IDESC_BF16),              \
               "r"(0u), "r"(_e) : "memory");                                 \
} while (0)

#define TC_MMA_TF32_TS(dtm, atm, bdesc, en) do {                             \
    uint32_t _e = (en) ? 1u : 0u;                                            \
    asm volatile("{\n\t.reg .pred p;\n\t"                                    \
        "setp.ne.u32 p, %5, 0;\n\t"                                          \
        "tcgen05.mma.cta_group::1.kind::tf32 [%0], [%1], %2, %3, {%4, %4, %4, %4}, p;\n\t" \
        "}" :: "r"(dtm), "r"(atm), "l"(bdesc), "r"(IDESC_TF32),              \
               "r"(0u), "r"(_e) : "memory");                                 \
} while (0)

#define TC_ST_X16(tmem_addr, r)                                              \
    asm volatile("tcgen05.st.sync.aligned.32x32b.x16.b32 [%0], "             \
        "{%1, %2, %3, %4, %5, %6, %7, %8, "                                  \
        " %9, %10, %11, %12, %13, %14, %15, %16};"                           \
        :: "r"(tmem_addr),                                                   \
           "r"((r)[0]),  "r"((r)[1]),  "r"((r)[2]),  "r"((r)[3]),            \
           "r"((r)[4]),  "r"((r)[5]),  "r"((r)[6]),  "r"((r)[7]),            \
           "r"((r)[8]),  "r"((r)[9]),  "r"((r)[10]), "r"((r)[11]),           \
           "r"((r)[12]), "r"((r)[13]), "r"((r)[14]), "r"((r)[15])            \
        : "memory")

#define TC_ST_X32(tmem_addr, r)                                              \
    asm volatile("tcgen05.st.sync.aligned.32x32b.x32.b32 [%0], "             \
        "{%1, %2, %3, %4, %5, %6, %7, %8, "                                  \
        " %9, %10, %11, %12, %13, %14, %15, %16, "                           \
        " %17, %18, %19, %20, %21, %22, %23, %24, "                          \
        " %25, %26, %27, %28, %29, %30, %31, %32};"                          \
        :: "r"(tmem_addr),                                                   \
           "r"((r)[0]),  "r"((r)[1]),  "r"((r)[2]),  "r"((r)[3]),            \
           "r"((r)[4]),  "r"((r)[5]),  "r"((r)[6]),  "r"((r)[7]),            \
           "r"((r)[8]),  "r"((r)[9]),  "r"((r)[10]), "r"((r)[11]),           \
           "r"((r)[12]), "r"((r)[13]), "r"((r)[14]), "r"((r)[15]),           \
           "r"((r)[16]), "r"((r)[17]), "r"((r)[18]), "r"((r)[19]),           \
           "r"((r)[20]), "r"((r)[21]), "r"((r)[22]), "r"((r)[23]),           \
           "r"((r)[24]), "r"((r)[25]), "r"((r)[26]), "r"((r)[27]),           \
           "r"((r)[28]), "r"((r)[29]), "r"((r)[30]), "r"((r)[31])            \
        : "memory")

#define TC_LD_X32(r, tmem_addr)                                              \
    asm volatile("tcgen05.ld.sync.aligned.32x32b.x32.b32 "                   \
        "{%0, %1, %2, %3, %4, %5, %6, %7, "                                  \
        " %8, %9, %10, %11, %12, %13, %14, %15, "                            \
        " %16, %17, %18, %19, %20, %21, %22, %23, "                          \
        " %24, %25, %26, %27, %28, %29, %30, %31}, [%32];"                   \
        : "=r"((r)[0]),  "=r"((r)[1]),  "=r"((r)[2]),  "=r"((r)[3]),         \
          "=r"((r)[4]),  "=r"((r)[5]),  "=r"((r)[6]),  "=r"((r)[7]),         \
          "=r"((r)[8]),  "=r"((r)[9]),  "=r"((r)[10]), "=r"((r)[11]),        \
          "=r"((r)[12]), "=r"((r)[13]), "=r"((r)[14]), "=r"((r)[15]),        \
          "=r"((r)[16]), "=r"((r)[17]), "=r"((r)[18]), "=r"((r)[19]),        \
          "=r"((r)[20]), "=r"((r)[21]), "=r"((r)[22]), "=r"((r)[23]),        \
          "=r"((r)[24]), "=r"((r)[25]), "=r"((r)[26]), "=r"((r)[27]),        \
          "=r"((r)[28]), "=r"((r)[29]), "=r"((r)[30]), "=r"((r)[31])         \
        : "r"(tmem_addr))

static constexpr unsigned long long SMEM_DESC_BASE =
    (2ull << 61) | (1ull << 46) | (64ull << 32) | (1ull << 16);
__device__ __forceinline__ uint64_t mk_desc(uint32_t addr) {
    return SMEM_DESC_BASE | ((uint64_t)(addr >> 4) & 0x3FFF);
}
__device__ __forceinline__ uint64_t koff(int s) {
    return (uint64_t)((s >> 2) * 1024 + (s & 3) * 2);
}

#endif // sm_103a device helpers

// ---------------- small kernels ------------------------------------------
__global__ void k_detect(const int* ei32) {
    if (blockIdx.x == 0 && threadIdx.x == 0) {
        int is64 = 1;
        #pragma unroll 1
        for (int i = 0; i < 64; ++i)
            if (ei32[2 * i + 1] != 0) { is64 = 0; break; }
        g_is64 = is64;
    }
}
// indices + zero agg + bf16 x + all weight prep in ONE kernel
__global__ void k_convert_prep(const void* ei, const float* __restrict__ x,
                               const float* __restrict__ W1, const float* __restrict__ W2,
                               const float* __restrict__ NW1, const float* __restrict__ NW2) {
    size_t i = (size_t)blockIdx.x * blockDim.x + threadIdx.x;
    if (i < N_EDGES) {
        if (g_is64) {
            const long long* p = (const long long*)ei;
            g_row[i] = (int)p[i];
            g_col[i] = (int)p[(size_t)N_EDGES + i];
        } else {
            const int* p = (const int*)ei;
            g_row[i] = p[i];
            g_col[i] = p[N_EDGES + i];
        }
    }
    if (i < (size_t)N_NODES * D) {
        g_agg[i] = 0.0f;
        g_xb[i] = bf16_bits(x[i]);
    }
    int j = (int)i;
    if (j < 128 * K1PAD) {
        int n = j / K1PAD, k = j % K1PAD;
        float v = (k < K1) ? W1[(size_t)k * 128 + n] : 0.0f;
        g_W1B[swz(abyte(n, k)) >> 1] = bf16_bits(v);
        return;
    }
    j -= 128 * K1PAD;
    if (j < 128 * 128) {
        int n = j / 128, k = j % 128;
        g_W2B[swz(abyte(n, k)) >> 1] = bf16_bits(W2[(size_t)k * 128 + n]);
        return;
    }
    j -= 128 * 128;
    if (j < 128 * 256) {
        int n = j / 256, k = j % 256;
        g_NW1B[swz(abyte32(n, k)) >> 2] = f2tf32(NW1[(size_t)k * 128 + n]);
        return;
    }
    j -= 128 * 256;
    if (j >= 0 && j < 128 * 128) {
        int n = j / 128, k = j % 128;
        g_NW2B[swz(abyte32(n, k)) >> 2] = f2tf32(NW2[(size_t)k * 128 + n]);
    }
}

// ---------------- fused edge kernel: gather-first G-warps -----------------
__global__ __launch_bounds__(512, 1) void k_edge_fused(
    const float* __restrict__ x, const float* __restrict__ ea,
    const float* __restrict__ eb1, const float* __restrict__ eb2,
    const float* __restrict__ eW1raw, const float* __restrict__ eW2raw,
    int nblocks)
{
#if defined(__CUDA_ARCH__) && defined(__CUDA_ARCH_FEAT_SM103_ALL)
    extern __shared__ uint32_t dsm[];
    __shared__ float s_eb1[D], s_eb2[D];
    __shared__ uint32_t s_tmem[1];
    __shared__ __align__(8) unsigned long long s_mbar1, s_mbar2;

    const int tid = threadIdx.x;
    const int wid = tid >> 5;          // 0..15
    const int lane = tid & 31;
    const int chunk = wid >> 2;        // e2 D-column chunk (0..3) for this warp
    const int sub = wid & 3;           // TMEM subpartition for e2

    const uint32_t dyn_base = smem_u32(dsm);
    const uint32_t ws1 = (dyn_base + 1023u) & ~1023u;
    const uint32_t ws2 = ws1 + W1B_BYTES;
    const uint32_t wsA = ws2 + W2B_BYTES;
    uint32_t* w1p = dsm + ((ws1 - dyn_base) >> 2);

    {
        uint4* dst = (uint4*)w1p; const uint4* src = (const uint4*)g_W1B;
        for (int i = tid; i < (W1B_BYTES + W2B_BYTES) / 16; i += 512) dst[i] = src[i];
        if (tid < D) { s_eb1[tid] = eb1[tid]; s_eb2[tid] = eb2[tid]; }
        for (int i = tid; i < 128 * 12; i += 512) {
            int row = i / 12, j = i % 12;
            sts8(wsA + swz(abyte(row, 272 + j * 4)), 0u, 0u);
        }
    }
    if (wid == 0) TC_ALLOC(smem_u32(s_tmem), 512);
    if (tid == 0) { MBAR_INIT(smem_u32(&s_mbar1), 1); MBAR_INIT(smem_u32(&s_mbar2), 1); }
    __syncthreads();
    const uint32_t tbase = s_tmem[0];
    const uint32_t mbar1 = smem_u32(&s_mbar1);
    const uint32_t mbar2 = smem_u32(&s_mbar2);
    const uint64_t a1d = mk_desc(wsA);
    const uint64_t w1d = mk_desc(ws1);
    const uint64_t w2d = mk_desc(ws2);

    // gather: warp gw (0..7) fills A1 rows gw*16 .. gw*16+15 from bf16 x
    auto gather = [&](int tile) {
        const int gw = wid;
        const int e0 = tile * TM + gw * 16;
        const int myr = g_row[e0 + (lane & 15)];
        const int myc = g_col[e0 + (lane & 15)];
        #pragma unroll 16
        for (int i = 0; i < 16; ++i) {
            const int el = gw * 16 + i;
            const int r = __shfl_sync(0xffffffffu, myr, i);
            const int c = __shfl_sync(0xffffffffu, myc, i);
            uint2 v = *(const uint2*)(g_xb + (size_t)r * D + lane * 4);
            sts8(wsA + swz(abyte(el, lane * 4)), v.x, v.y);
            v = *(const uint2*)(g_xb + (size_t)c * D + lane * 4);
            sts8(wsA + swz(abyte(el, 128 + lane * 4)), v.x, v.y);
        }
        #pragma unroll
        for (int i = 0; i < 2; ++i) {
            const int el = gw * 16 + i * 8 + (lane >> 2);
            const int e = tile * TM + el;
            float4 v = *(const float4*)(ea + (size_t)e * DE + (lane & 3) * 4);
            sts8(wsA + swz(abyte(el, 256 + (lane & 3) * 4)),
                 pack_bf16x2(v.x, v.y), pack_bf16x2(v.z, v.w));
        }
    };

    // E1 on C-warps only: warp 8+cw handles sub=cw&3, chunks {cpair*2, cpair*2+1}
    auto e1_two = [&](int cpair, int csub) {
        const uint32_t so = (uint32_t)csub << 21;
        #pragma unroll 1
        for (int h = 0; h < 2; ++h) {
            const int ch = cpair * 2 + h;
            uint32_t dreg[32], areg[16];
            TC_LD_X32(dreg, tbase + TMEM_D1 + ch * 32);
            TC_WAIT_LD();
            #pragma unroll
            for (int m = 0; m < 16; ++m) {
                float v0 = silu_f(__uint_as_float(dreg[2*m])   + s_eb1[ch*32 + 2*m]);
                float v1 = silu_f(__uint_as_float(dreg[2*m+1]) + s_eb1[ch*32 + 2*m+1]);
                areg[m] = pack_bf16x2(v0, v1);
            }
            TC_ST_X16(tbase + TMEM_A2 + ch * 16 + so, areg);
        }
        TC_WAIT_ST();
    };

    // E2 one chunk per warp (all 16 warps)
    auto e2_one = [&](int tile) {
        const int e = tile * TM + sub * 32 + lane;
        float* aggp = g_agg + (size_t)g_row[e] * D;
        uint32_t dreg[32];
        TC_LD_X32(dreg, tbase + TMEM_D2 + chunk * 32);
        TC_WAIT_LD();
        #pragma unroll
        for (int q = 0; q < 8; ++q) {
            float v0 = silu_f(__uint_as_float(dreg[q*4+0]) + s_eb2[chunk*32+q*4+0]);
            float v1 = silu_f(__uint_as_float(dreg[q*4+1]) + s_eb2[chunk*32+q*4+1]);
            float v2 = silu_f(__uint_as_float(dreg[q*4+2]) + s_eb2[chunk*32+q*4+2]);
            float v3 = silu_f(__uint_as_float(dreg[q*4+3]) + s_eb2[chunk*32+q*4+3]);
            asm volatile("red.global.add.v4.f32 [%0], {%1,%2,%3,%4};"
                         :: "l"(aggp + chunk * 32 + q * 4),
                            "f"(v0), "f"(v1), "f"(v2), "f"(v3) : "memory");
        }
    };

    // ---- prologue: gather tile0; warp8 issues MMA1(tile0); G banks bar1 arrival
    if (wid < 8 && blockIdx.x < NTILES) { gather(blockIdx.x); FENCE_PROXY_ASYNC(); }
    __syncthreads();
    if (wid < 8) NAMED_ARRIVE(1, 512);          // stands in for e2(t-1)
    if (wid == 8 && blockIdx.x < NTILES) {
        TC_FENCE_AFTER();
        if (elect_one()) {
            #pragma unroll 1
            for (int s = 0; s < 17; ++s)
                TC_MMA_SS(tbase + TMEM_D1, a1d + koff(s), w1d + koff(s), s > 0);
            TC_COMMIT(mbar1);
        }
    }

    int ph1 = 0, ph2 = 0;
    for (int tile = blockIdx.x; tile < NTILES; tile += nblocks) {
        const bool has_next = (tile + nblocks < NTILES);

        if (wid < 8) {
            // ---- G-warps: gather(t+1) FIRST, then e2 ----
            MBAR_WAIT(mbar1, ph1);              // MMA1(t) done: A1 SMEM free
            if (has_next) {
                gather(tile + nblocks); FENCE_PROXY_ASYNC();
                NAMED_ARRIVE(2, 288);
            }
            MBAR_WAIT(mbar2, ph2);              // MMA2(t) done: D2 ready
            TC_FENCE_AFTER();
            e2_one(tile);
            TC_FENCE_BEFORE();
            if (has_next) NAMED_ARRIVE(1, 512); // D2 reads done (protects vs MMA2(t+1))
        } else {
            // ---- C-warps (8..15): full E1, MMA issue (warp 8), e2 ----
            MBAR_WAIT(mbar1, ph1);              // D1 ready
            TC_FENCE_AFTER();
            e1_two((wid - 8) >> 2, (wid - 8) & 3);
            TC_FENCE_BEFORE();

            if (wid == 8) {
                NAMED_BAR(1, 512);              // E1(t) done + G e2(t-1) done
                TC_FENCE_AFTER();
                if (elect_one()) {
                    #pragma unroll 1
                    for (int s = 0; s < 8; ++s)
                        TC_MMA_TS(tbase + TMEM_D2, tbase + TMEM_A2 + s * 8,
                                  w2d + koff(s), s > 0);
                    TC_COMMIT(mbar2);
                }
                if (has_next) {
                    NAMED_BAR(2, 288);          // gather(t+1) complete
                    if (elect_one()) {
                        #pragma unroll 1
                        for (int s = 0; s < 17; ++s)
                            TC_MMA_SS(tbase + TMEM_D1, a1d + koff(s), w1d + koff(s), s > 0);
                        TC_COMMIT(mbar1);
                    }
                }
            } else {
                NAMED_ARRIVE(1, 512);
            }
            MBAR_WAIT(mbar2, ph2);
            TC_FENCE_AFTER();
            e2_one(tile);
            TC_FENCE_BEFORE();
        }
        ph1 ^= 1; ph2 ^= 1;
    }

    __syncthreads();
    if (wid == 0) { TC_RELINQ(); TC_DEALLOC(tbase, 512); }

#else
    // plain-sm_103 fallback (never selected on GB300)
    const int tid = threadIdx.x;
    if (tid >= TM) return;
    for (int tile = blockIdx.x; tile < NTILES; tile += nblocks) {
        const int e = tile * TM + tid;
        const int r = g_row[e], c = g_col[e];
        float a[K1];
        #pragma unroll 4
        for (int j = 0; j < D; ++j) { a[j] = x[(size_t)r * D + j]; a[D + j] = x[(size_t)c * D + j]; }
        #pragma unroll
        for (int j = 0; j < DE; ++j) a[2 * D + j] = ea[(size_t)e * DE + j];
        float h[D];
        for (int n = 0; n < D; ++n) {
            float s = eb1[n];
            for (int k = 0; k < K1; ++k) s = fmaf(a[k], eW1raw[(size_t)k * D + n], s);
            h[n] = silu_f(s);
        }
        for (int n = 0; n < D; ++n) {
            float s = eb2[n];
            for (int k = 0; k < D; ++k) s = fmaf(h[k], eW2raw[(size_t)k * D + n], s);
            atomicAdd(g_agg + (size_t)r * D + n, silu_f(s));
        }
    }
#endif
}

// ---------------- fused node kernel (tcgen05 tf32, TS mode) ---------------
__global__ __launch_bounds__(128, 1) void k_node_fused(
    const float* __restrict__ x,
    const float* __restrict__ nb1, const float* __restrict__ nb2,
    const float* __restrict__ nW1raw, const float* __restrict__ nW2raw,
    float* __restrict__ out, int nblocks)
{
#if defined(__CUDA_ARCH__) && defined(__CUDA_ARCH_FEAT_SM103_ALL)
    extern __shared__ uint32_t dsm[];
    __shared__ float s_b1[D], s_b2[D];
    __shared__ uint32_t s_tmem[1];
    __shared__ __align__(8) unsigned long long s_mbar;

    const int tid = threadIdx.x;
    const int wid = tid >> 5;
    const int lane = tid & 31;
    const uint32_t woff = (uint32_t)wid << 21;

    const uint32_t dyn_base = smem_u32(dsm);
    const uint32_t ws1 = (dyn_base + 1023u) & ~1023u;
    const uint32_t ws2 = ws1 + NW1_WORDS * 4;
    uint32_t* w1p = dsm + ((ws1 - dyn_base) >> 2);

    {
        uint4* dst = (uint4*)w1p; const uint4* src = (const uint4*)g_NW1B;
        for (int i = tid; i < (NW1_WORDS + NW2_WORDS) / 4; i += 128) dst[i] = src[i];
        if (tid < D) { s_b1[tid] = nb1[tid]; s_b2[tid] = nb2[tid]; }
    }
    if (wid == 0) TC_ALLOC(smem_u32(s_tmem), 512);
    if (tid == 0) MBAR_INIT(smem_u32(&s_mbar), 1);
    __syncthreads();
    const uint32_t tbase = s_tmem[0];
    const uint32_t mbar = smem_u32(&s_mbar);
    const uint64_t w1d = mk_desc(ws1);
    const uint64_t w2d = mk_desc(ws2);

    int ph = 0;
    for (int tile = blockIdx.x; tile < NNT; tile += nblocks) {
        __syncthreads();

        {
            int n = tile * 128 + tid;
            if (n >= N_NODES) n = N_NODES - 1;
            const float4* xr = (const float4*)(x + (size_t)n * D);
            const float4* ar = (const float4*)(g_agg + (size_t)n * D);
            uint32_t a[32];
            #pragma unroll 1
            for (int ch = 0; ch < 4; ++ch) {
                #pragma unroll
                for (int q = 0; q < 8; ++q) {
                    float4 v = xr[ch * 8 + q];
                    a[q*4+0] = f2tf32(v.x); a[q*4+1] = f2tf32(v.y);
                    a[q*4+2] = f2tf32(v.z); a[q*4+3] = f2tf32(v.w);
                }
                TC_ST_X32(tbase + ch * 32 + woff, a);
            }
            #pragma unroll 1
            for (int ch = 0; ch < 4; ++ch) {
                #pragma unroll
                for (int q = 0; q < 8; ++q) {
                    float4 v = ar[ch * 8 + q];
                    a[q*4+0] = f2tf32(v.x); a[q*4+1] = f2tf32(v.y);
                    a[q*4+2] = f2tf32(v.z); a[q*4+3] = f2tf32(v.w);
                }
                TC_ST_X32(tbase + 128 + ch * 32 + woff, a);
            }
        }
        TC_WAIT_ST();
        TC_FENCE_BEFORE();
        __syncthreads();

        if (wid == 0) {
            TC_FENCE_AFTER();
            if (elect_one()) {
                #pragma unroll 1
                for (int s = 0; s < 32; ++s)
                    TC_MMA_TF32_TS(tbase + 256, tbase + s * 8, w1d + koff(s), s > 0);
                TC_COMMIT(mbar);
            }
        }
        MBAR_WAIT(mbar, ph); ph ^= 1;
        TC_FENCE_AFTER();

        #pragma unroll 1
        for (int ch = 0; ch < 4; ++ch) {
            uint32_t dreg[32], areg[32];
            TC_LD_X32(dreg, tbase + 256 + ch * 32);
            TC_WAIT_LD();
            #pragma unroll
            for (int j = 0; j < 32; ++j)
                areg[j] = f2tf32(silu_f(__uint_as_float(dreg[j]) + s_b1[ch * 32 + j]));
            TC_ST_X32(tbase + ch * 32 + woff, areg);
        }
        TC_WAIT_ST();
        TC_FENCE_BEFORE();
        __syncthreads();

        if (wid == 0) {
            TC_FENCE_AFTER();
            if (elect_one()) {
                #pragma unroll 1
                for (int s = 0; s < 16; ++s)
                    TC_MMA_TF32_TS(tbase + 128, tbase + s * 8, w2d + koff(s), s > 0);
                TC_COMMIT(mbar);
            }
        }
        MBAR_WAIT(mbar, ph); ph ^= 1;
        TC_FENCE_AFTER();

        {
            const int n = tile * 128 + wid * 32 + lane;
            const bool valid = (n < N_NODES);
            const float4* xr = (const float4*)(x + (size_t)n * D);
            float4* orow = (float4*)(out + (size_t)n * D);
            #pragma unroll 1
            for (int ch = 0; ch < 4; ++ch) {
                uint32_t dreg[32];
                TC_LD_X32(dreg, tbase + 128 + ch * 32);
                TC_WAIT_LD();
                if (valid) {
                    #pragma unroll
                    for (int q = 0; q < 8; ++q) {
                        float4 xv = xr[ch * 8 + q];
                        float4 o;
                        o.x = xv.x + __uint_as_float(dreg[q*4+0]) + s_b2[ch*32+q*4+0];
                        o.y = xv.y + __uint_as_float(dreg[q*4+1]) + s_b2[ch*32+q*4+1];
                        o.z = xv.z + __uint_as_float(dreg[q*4+2]) + s_b2[ch*32+q*4+2];
                        o.w = xv.w + __uint_as_float(dreg[q*4+3]) + s_b2[ch*32+q*4+3];
                        orow[ch * 8 + q] = o;
                    }
                }
            }
            TC_FENCE_BEFORE();
        }
    }

    __syncthreads();
    if (wid == 0) { TC_RELINQ(); TC_DEALLOC(tbase, 512); }

#else
    const int tid = threadIdx.x;
    for (int n = blockIdx.x * 128 + tid; n < N_NODES; n += nblocks * 128) {
        float t[D];
        for (int o = 0; o < D; ++o) {
            float s = nb1[o];
            for (int k = 0; k < D; ++k) {
                s = fmaf(x[(size_t)n * D + k], nW1raw[(size_t)k * D + o], s);
                s = fmaf(g_agg[(size_t)n * D + k], nW1raw[(size_t)(D + k) * D + o], s);
            }
            t[o] = silu_f(s);
        }
        for (int o = 0; o < D; ++o) {
            float s = nb2[o];
            for (int k = 0; k < D; ++k) s = fmaf(t[k], nW2raw[(size_t)k * D + o], s);
            out[(size_t)n * D + o] = x[(size_t)n * D + o] + s;
        }
    }
#endif
}

// ---------------- launch --------------------------------------------------
extern "C" void kernel_launch(void* const* d_in, const int* in_sizes, int n_in,
                              void* d_out, int out_size)
{
    const float* x   = (const float*)d_in[0];
    const void*  ei  = d_in[1];
    const float* ea  = (const float*)d_in[2];
    const float* eW1 = (const float*)d_in[3];
    const float* eb1 = (const float*)d_in[4];
    const float* eW2 = (const float*)d_in[5];
    const float* eb2 = (const float*)d_in[6];
    const float* nW1 = (const float*)d_in[7];
    const float* nb1 = (const float*)d_in[8];
    const float* nW2 = (const float*)d_in[9];
    const float* nb2 = (const float*)d_in[10];
    float* out = (float*)d_out;

    int sms = 148;
    cudaDeviceGetAttribute(&sms, cudaDevAttrMultiProcessorCount, 0);

    const int s_edge = 1024 + W1B_BYTES + W2B_BYTES + A1B_BYTES;
    const int s_node = 1024 + (NW1_WORDS + NW2_WORDS) * 4;

    cudaFuncSetAttribute(k_edge_fused, cudaFuncAttributeMaxDynamicSharedMemorySize, s_edge);
    cudaFuncSetAttribute(k_node_fused, cudaFuncAttributeMaxDynamicSharedMemorySize, s_node);

    const size_t cz = (size_t)N_NODES * D;   // covers N_EDGES and all prep ranges

    k_detect<<<1, 1>>>((const int*)ei);
    k_convert_prep<<<(int)((cz + 255) / 256), 256>>>(ei, x, eW1, eW2, nW1, nW2);
    k_edge_fused<<<sms, 512, s_edge>>>(x, ea, eb1, eb2, eW1, eW2, sms);
    k_node_fused<<<sms, 128, s_node>>>(x, nb1, nb2, nW1, nW2, out, sms);
}

// round 16
// speedup vs baseline: 1.5808x; 1.0494x over previous
#include <cuda_runtime.h>
#include <cuda_bf16.h>
#include <cstdint>

#define N_NODES 50000
#define N_EDGES 800000
#define D 128
#define DE 16
#define K1 272
#define K1PAD 320
#define TM 128
#define NTILES (N_EDGES / TM)           // 6250
#define NNT ((N_NODES + 127) / 128)     // 391

#define W1B_BYTES (128 * K1PAD * 2)   // 81920
#define W2B_BYTES (128 * 128 * 2)     // 32768
#define A1B_BYTES (128 * K1PAD * 2)   // 81920
#define NW1_WORDS (256 * 128)
#define NW2_WORDS (128 * 128)

// edge TMEM
#define TMEM_D1 0
#define TMEM_D2 128
#define TMEM_A2 256

#define IDESC_BF16 0x8200490u
#define IDESC_TF32 0x8200910u

// ---------------- scratch -----------------------------------------------
__device__ int      g_is64;
__device__ int      g_row[N_EDGES];
__device__ int      g_col[N_EDGES];
__device__ float    g_agg[(size_t)N_NODES * D];
__device__ uint16_t g_xb[(size_t)N_NODES * D];   // bf16 x copy (12.8MB, L2-resident)
__device__ uint16_t g_W1B[W1B_BYTES / 2];
__device__ uint16_t g_W2B[W2B_BYTES / 2];
__device__ uint32_t g_NW1B[NW1_WORDS];
__device__ uint32_t g_NW2B[NW2_WORDS];

__device__ __forceinline__ float silu_f(float v) {
    float t;
    asm("tanh.approx.f32 %0, %1;" : "=f"(t) : "f"(0.5f * v));
    return v * fmaf(0.5f, t, 0.5f);
}
__device__ __forceinline__ uint32_t smem_u32(const void* p) {
    uint32_t a;
    asm("{ .reg .u64 t; cvta.to.shared.u64 t, %1; cvt.u32.u64 %0, t; }"
        : "=r"(a) : "l"(p));
    return a;
}
__device__ __forceinline__ uint32_t pack_bf16x2(float lo, float hi) {
    uint32_t d;
    asm("cvt.rn.bf16x2.f32 %0, %1, %2;" : "=r"(d) : "f"(hi), "f"(lo));
    return d;
}
__device__ __forceinline__ uint16_t bf16_bits(float v) {
    __nv_bfloat16 b = __float2bfloat16(v);
    return *reinterpret_cast<uint16_t*>(&b);
}
__device__ __forceinline__ uint32_t f2tf32(float f) {
    uint32_t u;
    asm("cvt.rna.tf32.f32 %0, %1;" : "=r"(u) : "f"(f));
    return u;
}
__device__ __forceinline__ void sts8(uint32_t addr, uint32_t a, uint32_t b) {
    asm volatile("st.shared.v2.b32 [%0], {%1, %2};" :: "r"(addr), "r"(a), "r"(b) : "memory");
}
__device__ __forceinline__ uint32_t abyte(int row, int k) {
    return (uint32_t)((((row >> 3) + ((k >> 6) << 4)) << 10) | ((row & 7) << 7) | ((k & 63) << 1));
}
__device__ __forceinline__ uint32_t abyte32(int row, int k) {
    return (uint32_t)((((row >> 3) + ((k >> 5) << 4)) << 10) | ((row & 7) << 7) | ((k & 31) << 2));
}
__device__ __forceinline__ uint32_t swz(uint32_t b) {
    return b ^ ((b >> 3) & 0x70);
}

#if defined(__CUDA_ARCH__) && defined(__CUDA_ARCH_FEAT_SM103_ALL)

__device__ __forceinline__ uint32_t elect_one() {
    uint32_t pred;
    asm volatile("{\n\t.reg .pred p;\n\telect.sync _|p, 0xFFFFFFFF;\n\t"
                 "selp.b32 %0, 1, 0, p;\n\t}" : "=r"(pred));
    return pred;
}

#define TC_ALLOC(smemaddr, n) \
    asm volatile("tcgen05.alloc.cta_group::1.sync.aligned.shared::cta.b32 [%0], %1;" \
                 :: "r"(smemaddr), "r"((uint32_t)(n)) : "memory")
#define TC_RELINQ() \
    asm volatile("tcgen05.relinquish_alloc_permit.cta_group::1.sync.aligned;")
#define TC_DEALLOC(tmem, n) \
    asm volatile("tcgen05.dealloc.cta_group::1.sync.aligned.b32 %0, %1;" \
                 :: "r"(tmem), "r"((uint32_t)(n)))
#define TC_WAIT_ST() asm volatile("tcgen05.wait::st.sync.aligned;" ::: "memory")
#define TC_WAIT_LD() asm volatile("tcgen05.wait::ld.sync.aligned;" ::: "memory")
#define TC_FENCE_BEFORE() asm volatile("tcgen05.fence::before_thread_sync;" ::: "memory")
#define TC_FENCE_AFTER()  asm volatile("tcgen05.fence::after_thread_sync;" ::: "memory")
#define TC_COMMIT(mbar) \
    asm volatile("tcgen05.commit.cta_group::1.mbarrier::arrive::one.shared::cluster.b64 [%0];" \
                 :: "r"(mbar) : "memory")
#define MBAR_INIT(mbar, cnt) \
    asm volatile("mbarrier.init.shared.b64 [%0], %1;" :: "r"(mbar), "r"((uint32_t)(cnt)) : "memory")
#define FENCE_PROXY_ASYNC() \
    asm volatile("fence.proxy.async.shared::cta;" ::: "memory")
#define NAMED_BAR(id, n) \
    asm volatile("bar.sync %0, %1;" :: "r"(id), "r"(n) : "memory")
#define NAMED_ARRIVE(id, n) \
    asm volatile("bar.arrive %0, %1;" :: "r"(id), "r"(n) : "memory")

#define MBAR_WAIT(mbar, ph) do {                                             \
    uint32_t _m = (mbar), _p = (uint32_t)(ph), _d;                           \
    asm volatile("{\n\t.reg .pred p;\n\t"                                    \
        "mbarrier.try_wait.parity.acquire.cta.shared::cta.b64 p, [%1], %2;\n\t" \
        "selp.b32 %0, 1, 0, p;\n\t}" : "=r"(_d) : "r"(_m), "r"(_p) : "memory"); \
    if (!_d) {                                                               \
        asm volatile("{\n\t.reg .pred P1;\n\t"                               \
            "WL_%=:\n\t"                                                     \
            "mbarrier.try_wait.parity.acquire.cta.shared::cta.b64 P1, [%0], %1, 0x989680;\n\t" \
            "@P1 bra.uni WD_%=;\n\t"                                         \
            "bra.uni WL_%=;\n\t"                                             \
            "WD_%=:\n\t}" :: "r"(_m), "r"(_p) : "memory");                   \
    }                                                                        \
} while (0)

#define TC_MMA_SS(dtm, adesc, bdesc, en) do {                                \
    uint32_t _e = (en) ? 1u : 0u;                                            \
    asm volatile("{\n\t.reg .pred p;\n\t"                                    \
        "setp.ne.u32 p, %5, 0;\n\t"                                          \
        "tcgen05.mma.cta_group::1.kind::f16 [%0], %1, %2, %3, {%4, %4, %4, %4}, p;\n\t" \
        "}" :: "r"(dtm), "l"(adesc), "l"(bdesc), "r"(IDESC_BF16),            \
               "r"(0u), "r"(_e) : "memory");                                 \
} while (0)

#define TC_MMA_TS(dtm, atm, bdesc, en) do {                                  \
    uint32_t _e = (en) ? 1u : 0u;                                            \
    asm volatile("{\n\t.reg .pred p;\n\t"                                    \
        "setp.ne.u32 p, %5, 0;\n\t"                                          \
        "tcgen05.mma.cta_group::1.kind::f16 [%0], [%1], %2, %3, {%4, %4, %4, %4}, p;\n\t" \
        "}" :: "r"(dtm), "r"(atm), "l"(bdesc), "r"(IDESC_BF16),              \
               "r"(0u), "r"(_e) : "memory");                                 \
} while (0)

#define TC_MMA_TF32_TS(dtm, atm, bdesc, en) do {                             \
    uint32_t _e = (en) ? 1u : 0u;                                            \
    asm volatile("{\n\t.reg .pred p;\n\t"                                    \
        "setp.ne.u32 p, %5, 0;\n\t"                                          \
        "tcgen05.mma.cta_group::1.kind::tf32 [%0], [%1], %2, %3, {%4, %4, %4, %4}, p;\n\t" \
        "}" :: "r"(dtm), "r"(atm), "l"(bdesc), "r"(IDESC_TF32),              \
               "r"(0u), "r"(_e) : "memory");                                 \
} while (0)

#define TC_ST_X16(tmem_addr, r)                                              \
    asm volatile("tcgen05.st.sync.aligned.32x32b.x16.b32 [%0], "             \
        "{%1, %2, %3, %4, %5, %6, %7, %8, "                                  \
        " %9, %10, %11, %12, %13, %14, %15, %16};"                           \
        :: "r"(tmem_addr),                                                   \
           "r"((r)[0]),  "r"((r)[1]),  "r"((r)[2]),  "r"((r)[3]),            \
           "r"((r)[4]),  "r"((r)[5]),  "r"((r)[6]),  "r"((r)[7]),            \
           "r"((r)[8]),  "r"((r)[9]),  "r"((r)[10]), "r"((r)[11]),           \
           "r"((r)[12]), "r"((r)[13]), "r"((r)[14]), "r"((r)[15])            \
        : "memory")

#define TC_ST_X32(tmem_addr, r)                                              \
    asm volatile("tcgen05.st.sync.aligned.32x32b.x32.b32 [%0], "             \
        "{%1, %2, %3, %4, %5, %6, %7, %8, "                                  \
        " %9, %10, %11, %12, %13, %14, %15, %16, "                           \
        " %17, %18, %19, %20, %21, %22, %23, %24, "                          \
        " %25, %26, %27, %28, %29, %30, %31, %32};"                          \
        :: "r"(tmem_addr),                                                   \
           "r"((r)[0]),  "r"((r)[1]),  "r"((r)[2]),  "r"((r)[3]),            \
           "r"((r)[4]),  "r"((r)[5]),  "r"((r)[6]),  "r"((r)[7]),            \
           "r"((r)[8]),  "r"((r)[9]),  "r"((r)[10]), "r"((r)[11]),           \
           "r"((r)[12]), "r"((r)[13]), "r"((r)[14]), "r"((r)[15]),           \
           "r"((r)[16]), "r"((r)[17]), "r"((r)[18]), "r"((r)[19]),           \
           "r"((r)[20]), "r"((r)[21]), "r"((r)[22]), "r"((r)[23]),           \
           "r"((r)[24]), "r"((r)[25]), "r"((r)[26]), "r"((r)[27]),           \
           "r"((r)[28]), "r"((r)[29]), "r"((r)[30]), "r"((r)[31])            \
        : "memory")

#define TC_LD_X32(r, tmem_addr)                                              \
    asm volatile("tcgen05.ld.sync.aligned.32x32b.x32.b32 "                   \
        "{%0, %1, %2, %3, %4, %5, %6, %7, "                                  \
        " %8, %9, %10, %11, %12, %13, %14, %15, "                            \
        " %16, %17, %18, %19, %20, %21, %22, %23, "                          \
        " %24, %25, %26, %27, %28, %29, %30, %31}, [%32];"                   \
        : "=r"((r)[0]),  "=r"((r)[1]),  "=r"((r)[2]),  "=r"((r)[3]),         \
          "=r"((r)[4]),  "=r"((r)[5]),  "=r"((r)[6]),  "=r"((r)[7]),         \
          "=r"((r)[8]),  "=r"((r)[9]),  "=r"((r)[10]), "=r"((r)[11]),        \
          "=r"((r)[12]), "=r"((r)[13]), "=r"((r)[14]), "=r"((r)[15]),        \
          "=r"((r)[16]), "=r"((r)[17]), "=r"((r)[18]), "=r"((r)[19]),        \
          "=r"((r)[20]), "=r"((r)[21]), "=r"((r)[22]), "=r"((r)[23]),        \
          "=r"((r)[24]), "=r"((r)[25]), "=r"((r)[26]), "=r"((r)[27]),        \
          "=r"((r)[28]), "=r"((r)[29]), "=r"((r)[30]), "=r"((r)[31])         \
        : "r"(tmem_addr))

static constexpr unsigned long long SMEM_DESC_BASE =
    (2ull << 61) | (1ull << 46) | (64ull << 32) | (1ull << 16);
__device__ __forceinline__ uint64_t mk_desc(uint32_t addr) {
    return SMEM_DESC_BASE | ((uint64_t)(addr >> 4) & 0x3FFF);
}
__device__ __forceinline__ uint64_t koff(int s) {
    return (uint64_t)((s >> 2) * 1024 + (s & 3) * 2);
}

#endif // sm_103a device helpers

// ---------------- small kernels ------------------------------------------
__global__ void k_detect(const int* ei32) {
    if (blockIdx.x == 0 && threadIdx.x == 0) {
        int is64 = 1;
        #pragma unroll 1
        for (int i = 0; i < 64; ++i)
            if (ei32[2 * i + 1] != 0) { is64 = 0; break; }
        g_is64 = is64;
    }
}
__global__ void k_convert_prep(const void* ei, const float* __restrict__ x,
                               const float* __restrict__ W1, const float* __restrict__ W2,
                               const float* __restrict__ NW1, const float* __restrict__ NW2) {
    size_t i = (size_t)blockIdx.x * blockDim.x + threadIdx.x;
    if (i < N_EDGES) {
        if (g_is64) {
            const long long* p = (const long long*)ei;
            g_row[i] = (int)p[i];
            g_col[i] = (int)p[(size_t)N_EDGES + i];
        } else {
            const int* p = (const int*)ei;
            g_row[i] = p[i];
            g_col[i] = p[N_EDGES + i];
        }
    }
    if (i < (size_t)N_NODES * D) {
        g_agg[i] = 0.0f;
        g_xb[i] = bf16_bits(x[i]);
    }
    int j = (int)i;
    if (j < 128 * K1PAD) {
        int n = j / K1PAD, k = j % K1PAD;
        float v = (k < K1) ? W1[(size_t)k * 128 + n] : 0.0f;
        g_W1B[swz(abyte(n, k)) >> 1] = bf16_bits(v);
        return;
    }
    j -= 128 * K1PAD;
    if (j < 128 * 128) {
        int n = j / 128, k = j % 128;
        g_W2B[swz(abyte(n, k)) >> 1] = bf16_bits(W2[(size_t)k * 128 + n]);
        return;
    }
    j -= 128 * 128;
    if (j < 128 * 256) {
        int n = j / 256, k = j % 256;
        g_NW1B[swz(abyte32(n, k)) >> 2] = f2tf32(NW1[(size_t)k * 128 + n]);
        return;
    }
    j -= 128 * 256;
    if (j >= 0 && j < 128 * 128) {
        int n = j / 128, k = j % 128;
        g_NW2B[swz(abyte32(n, k)) >> 2] = f2tf32(NW2[(size_t)k * 128 + n]);
    }
}

// ---------------- fused edge kernel (R15 winner, unchanged) ---------------
__global__ __launch_bounds__(512, 1) void k_edge_fused(
    const float* __restrict__ x, const float* __restrict__ ea,
    const float* __restrict__ eb1, const float* __restrict__ eb2,
    const float* __restrict__ eW1raw, const float* __restrict__ eW2raw,
    int nblocks)
{
#if defined(__CUDA_ARCH__) && defined(__CUDA_ARCH_FEAT_SM103_ALL)
    extern __shared__ uint32_t dsm[];
    __shared__ float s_eb1[D], s_eb2[D];
    __shared__ uint32_t s_tmem[1];
    __shared__ __align__(8) unsigned long long s_mbar1, s_mbar2;

    const int tid = threadIdx.x;
    const int wid = tid >> 5;
    const int lane = tid & 31;
    const int chunk = wid >> 2;
    const int sub = wid & 3;

    const uint32_t dyn_base = smem_u32(dsm);
    const uint32_t ws1 = (dyn_base + 1023u) & ~1023u;
    const uint32_t ws2 = ws1 + W1B_BYTES;
    const uint32_t wsA = ws2 + W2B_BYTES;
    uint32_t* w1p = dsm + ((ws1 - dyn_base) >> 2);

    {
        uint4* dst = (uint4*)w1p; const uint4* src = (const uint4*)g_W1B;
        for (int i = tid; i < (W1B_BYTES + W2B_BYTES) / 16; i += 512) dst[i] = src[i];
        if (tid < D) { s_eb1[tid] = eb1[tid]; s_eb2[tid] = eb2[tid]; }
        for (int i = tid; i < 128 * 12; i += 512) {
            int row = i / 12, j = i % 12;
            sts8(wsA + swz(abyte(row, 272 + j * 4)), 0u, 0u);
        }
    }
    if (wid == 0) TC_ALLOC(smem_u32(s_tmem), 512);
    if (tid == 0) { MBAR_INIT(smem_u32(&s_mbar1), 1); MBAR_INIT(smem_u32(&s_mbar2), 1); }
    __syncthreads();
    const uint32_t tbase = s_tmem[0];
    const uint32_t mbar1 = smem_u32(&s_mbar1);
    const uint32_t mbar2 = smem_u32(&s_mbar2);
    const uint64_t a1d = mk_desc(wsA);
    const uint64_t w1d = mk_desc(ws1);
    const uint64_t w2d = mk_desc(ws2);

    auto gather = [&](int tile) {
        const int gw = wid;
        const int e0 = tile * TM + gw * 16;
        const int myr = g_row[e0 + (lane & 15)];
        const int myc = g_col[e0 + (lane & 15)];
        #pragma unroll 16
        for (int i = 0; i < 16; ++i) {
            const int el = gw * 16 + i;
            const int r = __shfl_sync(0xffffffffu, myr, i);
            const int c = __shfl_sync(0xffffffffu, myc, i);
            uint2 v = *(const uint2*)(g_xb + (size_t)r * D + lane * 4);
            sts8(wsA + swz(abyte(el, lane * 4)), v.x, v.y);
            v = *(const uint2*)(g_xb + (size_t)c * D + lane * 4);
            sts8(wsA + swz(abyte(el, 128 + lane * 4)), v.x, v.y);
        }
        #pragma unroll
        for (int i = 0; i < 2; ++i) {
            const int el = gw * 16 + i * 8 + (lane >> 2);
            const int e = tile * TM + el;
            float4 v = *(const float4*)(ea + (size_t)e * DE + (lane & 3) * 4);
            sts8(wsA + swz(abyte(el, 256 + (lane & 3) * 4)),
                 pack_bf16x2(v.x, v.y), pack_bf16x2(v.z, v.w));
        }
    };

    auto e1_two = [&](int cpair, int csub) {
        const uint32_t so = (uint32_t)csub << 21;
        #pragma unroll 1
        for (int h = 0; h < 2; ++h) {
            const int ch = cpair * 2 + h;
            uint32_t dreg[32], areg[16];
            TC_LD_X32(dreg, tbase + TMEM_D1 + ch * 32);
            TC_WAIT_LD();
            #pragma unroll
            for (int m = 0; m < 16; ++m) {
                float v0 = silu_f(__uint_as_float(dreg[2*m])   + s_eb1[ch*32 + 2*m]);
                float v1 = silu_f(__uint_as_float(dreg[2*m+1]) + s_eb1[ch*32 + 2*m+1]);
                areg[m] = pack_bf16x2(v0, v1);
            }
            TC_ST_X16(tbase + TMEM_A2 + ch * 16 + so, areg);
        }
        TC_WAIT_ST();
    };

    auto e2_one = [&](int tile) {
        const int e = tile * TM + sub * 32 + lane;
        float* aggp = g_agg + (size_t)g_row[e] * D;
        uint32_t dreg[32];
        TC_LD_X32(dreg, tbase + TMEM_D2 + chunk * 32);
        TC_WAIT_LD();
        #pragma unroll
        for (int q = 0; q < 8; ++q) {
            float v0 = silu_f(__uint_as_float(dreg[q*4+0]) + s_eb2[chunk*32+q*4+0]);
            float v1 = silu_f(__uint_as_float(dreg[q*4+1]) + s_eb2[chunk*32+q*4+1]);
            float v2 = silu_f(__uint_as_float(dreg[q*4+2]) + s_eb2[chunk*32+q*4+2]);
            float v3 = silu_f(__uint_as_float(dreg[q*4+3]) + s_eb2[chunk*32+q*4+3]);
            asm volatile("red.global.add.v4.f32 [%0], {%1,%2,%3,%4};"
                         :: "l"(aggp + chunk * 32 + q * 4),
                            "f"(v0), "f"(v1), "f"(v2), "f"(v3) : "memory");
        }
    };

    if (wid < 8 && blockIdx.x < NTILES) { gather(blockIdx.x); FENCE_PROXY_ASYNC(); }
    __syncthreads();
    if (wid < 8) NAMED_ARRIVE(1, 512);
    if (wid == 8 && blockIdx.x < NTILES) {
        TC_FENCE_AFTER();
        if (elect_one()) {
            #pragma unroll 1
            for (int s = 0; s < 17; ++s)
                TC_MMA_SS(tbase + TMEM_D1, a1d + koff(s), w1d + koff(s), s > 0);
            TC_COMMIT(mbar1);
        }
    }

    int ph1 = 0, ph2 = 0;
    for (int tile = blockIdx.x; tile < NTILES; tile += nblocks) {
        const bool has_next = (tile + nblocks < NTILES);

        if (wid < 8) {
            MBAR_WAIT(mbar1, ph1);
            if (has_next) {
                gather(tile + nblocks); FENCE_PROXY_ASYNC();
                NAMED_ARRIVE(2, 288);
            }
            MBAR_WAIT(mbar2, ph2);
            TC_FENCE_AFTER();
            e2_one(tile);
            TC_FENCE_BEFORE();
            if (has_next) NAMED_ARRIVE(1, 512);
        } else {
            MBAR_WAIT(mbar1, ph1);
            TC_FENCE_AFTER();
            e1_two((wid - 8) >> 2, (wid - 8) & 3);
            TC_FENCE_BEFORE();

            if (wid == 8) {
                NAMED_BAR(1, 512);
                TC_FENCE_AFTER();
                if (elect_one()) {
                    #pragma unroll 1
                    for (int s = 0; s < 8; ++s)
                        TC_MMA_TS(tbase + TMEM_D2, tbase + TMEM_A2 + s * 8,
                                  w2d + koff(s), s > 0);
                    TC_COMMIT(mbar2);
                }
                if (has_next) {
                    NAMED_BAR(2, 288);
                    if (elect_one()) {
                        #pragma unroll 1
                        for (int s = 0; s < 17; ++s)
                            TC_MMA_SS(tbase + TMEM_D1, a1d + koff(s), w1d + koff(s), s > 0);
                        TC_COMMIT(mbar1);
                    }
                }
            } else {
                NAMED_ARRIVE(1, 512);
            }
            MBAR_WAIT(mbar2, ph2);
            TC_FENCE_AFTER();
            e2_one(tile);
            TC_FENCE_BEFORE();
        }
        ph1 ^= 1; ph2 ^= 1;
    }

    __syncthreads();
    if (wid == 0) { TC_RELINQ(); TC_DEALLOC(tbase, 512); }

#else
    const int tid = threadIdx.x;
    if (tid >= TM) return;
    for (int tile = blockIdx.x; tile < NTILES; tile += nblocks) {
        const int e = tile * TM + tid;
        const int r = g_row[e], c = g_col[e];
        float a[K1];
        #pragma unroll 4
        for (int j = 0; j < D; ++j) { a[j] = x[(size_t)r * D + j]; a[D + j] = x[(size_t)c * D + j]; }
        #pragma unroll
        for (int j = 0; j < DE; ++j) a[2 * D + j] = ea[(size_t)e * DE + j];
        float h[D];
        for (int n = 0; n < D; ++n) {
            float s = eb1[n];
            for (int k = 0; k < K1; ++k) s = fmaf(a[k], eW1raw[(size_t)k * D + n], s);
            h[n] = silu_f(s);
        }
        for (int n = 0; n < D; ++n) {
            float s = eb2[n];
            for (int k = 0; k < D; ++k) s = fmaf(h[k], eW2raw[(size_t)k * D + n], s);
            atomicAdd(g_agg + (size_t)r * D + n, silu_f(s));
        }
    }
#endif
}

// ---------------- fused node kernel: 256 threads, split stages ------------
__global__ __launch_bounds__(256, 1) void k_node_fused(
    const float* __restrict__ x,
    const float* __restrict__ nb1, const float* __restrict__ nb2,
    const float* __restrict__ nW1raw, const float* __restrict__ nW2raw,
    float* __restrict__ out, int nblocks)
{
#if defined(__CUDA_ARCH__) && defined(__CUDA_ARCH_FEAT_SM103_ALL)
    extern __shared__ uint32_t dsm[];
    __shared__ float s_b1[D], s_b2[D];
    __shared__ uint32_t s_tmem[1];
    __shared__ __align__(8) unsigned long long s_mbar;

    const int tid = threadIdx.x;
    const int wid = tid >> 5;          // 0..7
    const int lane = tid & 31;
    const int sub = wid & 3;
    const int half = wid >> 2;         // 0: x / chunks 0-1 ; 1: agg / chunks 2-3
    const uint32_t subo = (uint32_t)sub << 21;

    const uint32_t dyn_base = smem_u32(dsm);
    const uint32_t ws1 = (dyn_base + 1023u) & ~1023u;
    const uint32_t ws2 = ws1 + NW1_WORDS * 4;
    uint32_t* w1p = dsm + ((ws1 - dyn_base) >> 2);

    {
        uint4* dst = (uint4*)w1p; const uint4* src = (const uint4*)g_NW1B;
        for (int i = tid; i < (NW1_WORDS + NW2_WORDS) / 4; i += 256) dst[i] = src[i];
        if (tid < D) { s_b1[tid] = nb1[tid]; s_b2[tid] = nb2[tid]; }
    }
    if (wid == 0) TC_ALLOC(smem_u32(s_tmem), 512);
    if (tid == 0) MBAR_INIT(smem_u32(&s_mbar), 1);
    __syncthreads();
    const uint32_t tbase = s_tmem[0];
    const uint32_t mbar = smem_u32(&s_mbar);
    const uint64_t w1d = mk_desc(ws1);
    const uint64_t w2d = mk_desc(ws2);

    int ph = 0;
    for (int tile = blockIdx.x; tile < NNT; tile += nblocks) {
        __syncthreads();   // prev tile's A2/D2 reads done before A1 overwrite

        // ---- A-load: warps 0-3 -> x (cols 0..127), warps 4-7 -> agg (128..255)
        {
            int n = tile * 128 + sub * 32 + lane;
            if (n >= N_NODES) n = N_NODES - 1;
            const float4* src = (const float4*)((half ? g_agg : x) + (size_t)n * D);
            const uint32_t cbase = tbase + half * 128 + subo;
            uint32_t a[32];
            #pragma unroll 1
            for (int ch = 0; ch < 4; ++ch) {
                #pragma unroll
                for (int q = 0; q < 8; ++q) {
                    float4 v = src[ch * 8 + q];
                    a[q*4+0] = f2tf32(v.x); a[q*4+1] = f2tf32(v.y);
                    a[q*4+2] = f2tf32(v.z); a[q*4+3] = f2tf32(v.w);
                }
                TC_ST_X32(cbase + ch * 32, a);
            }
        }
        TC_WAIT_ST();
        TC_FENCE_BEFORE();
        __syncthreads();

        // ---- MMA1 (tf32 TS): D1 = A1 @ nW1, K=256 -> 32 steps ----
        if (wid == 0) {
            TC_FENCE_AFTER();
            if (elect_one()) {
                #pragma unroll 1
                for (int s = 0; s < 32; ++s)
                    TC_MMA_TF32_TS(tbase + 256, tbase + s * 8, w1d + koff(s), s > 0);
                TC_COMMIT(mbar);
            }
        }
        MBAR_WAIT(mbar, ph); ph ^= 1;
        TC_FENCE_AFTER();

        // ---- E1: each warp 2 chunks (half*2, half*2+1) -> A2 (tf32) ----
        #pragma unroll 1
        for (int h = 0; h < 2; ++h) {
            const int ch = half * 2 + h;
            uint32_t dreg[32], areg[32];
            TC_LD_X32(dreg, tbase + 256 + ch * 32);
            TC_WAIT_LD();
            #pragma unroll
            for (int j = 0; j < 32; ++j)
                areg[j] = f2tf32(silu_f(__uint_as_float(dreg[j]) + s_b1[ch * 32 + j]));
            TC_ST_X32(tbase + ch * 32 + subo, areg);
        }
        TC_WAIT_ST();
        TC_FENCE_BEFORE();
        __syncthreads();

        // ---- MMA2 (tf32 TS): D2 = A2 @ nW2, K=128 -> 16 steps ----
        if (wid == 0) {
            TC_FENCE_AFTER();
            if (elect_one()) {
                #pragma unroll 1
                for (int s = 0; s < 16; ++s)
                    TC_MMA_TF32_TS(tbase + 128, tbase + s * 8, w2d + koff(s), s > 0);
                TC_COMMIT(mbar);
            }
        }
        MBAR_WAIT(mbar, ph); ph ^= 1;
        TC_FENCE_AFTER();

        // ---- E2: each warp 2 chunks -> out = x + D2 + nb2 ----
        {
            const int n = tile * 128 + sub * 32 + lane;
            const bool valid = (n < N_NODES);
            const float4* xr = (const float4*)(x + (size_t)n * D);
            float4* orow = (float4*)(out + (size_t)n * D);
            #pragma unroll 1
            for (int h = 0; h < 2; ++h) {
                const int ch = half * 2 + h;
                uint32_t dreg[32];
                TC_LD_X32(dreg, tbase + 128 + ch * 32);
                TC_WAIT_LD();
                if (valid) {
                    #pragma unroll
                    for (int q = 0; q < 8; ++q) {
                        float4 xv = xr[ch * 8 + q];
                        float4 o;
                        o.x = xv.x + __uint_as_float(dreg[q*4+0]) + s_b2[ch*32+q*4+0];
                        o.y = xv.y + __uint_as_float(dreg[q*4+1]) + s_b2[ch*32+q*4+1];
                        o.z = xv.z + __uint_as_float(dreg[q*4+2]) + s_b2[ch*32+q*4+2];
                        o.w = xv.w + __uint_as_float(dreg[q*4+3]) + s_b2[ch*32+q*4+3];
                        orow[ch * 8 + q] = o;
                    }
                }
            }
            TC_FENCE_BEFORE();
        }
    }

    __syncthreads();
    if (wid == 0) { TC_RELINQ(); TC_DEALLOC(tbase, 512); }

#else
    const int tid = threadIdx.x;
    for (int n = blockIdx.x * 256 + tid; n < N_NODES; n += nblocks * 256) {
        float t[D];
        for (int o = 0; o < D; ++o) {
            float s = nb1[o];
            for (int k = 0; k < D; ++k) {
                s = fmaf(x[(size_t)n * D + k], nW1raw[(size_t)k * D + o], s);
                s = fmaf(g_agg[(size_t)n * D + k], nW1raw[(size_t)(D + k) * D + o], s);
            }
            t[o] = silu_f(s);
        }
        for (int o = 0; o < D; ++o) {
            float s = nb2[o];
            for (int k = 0; k < D; ++k) s = fmaf(t[k], nW2raw[(size_t)k * D + o], s);
            out[(size_t)n * D + o] = x[(size_t)n * D + o] + s;
        }
    }
#endif
}

// ---------------- launch --------------------------------------------------
extern "C" void kernel_launch(void* const* d_in, const int* in_sizes, int n_in,
                              void* d_out, int out_size)
{
    const float* x   = (const float*)d_in[0];
    const void*  ei  = d_in[1];
    const float* ea  = (const float*)d_in[2];
    const float* eW1 = (const float*)d_in[3];
    const float* eb1 = (const float*)d_in[4];
    const float* eW2 = (const float*)d_in[5];
    const float* eb2 = (const float*)d_in[6];
    const float* nW1 = (const float*)d_in[7];
    const float* nb1 = (const float*)d_in[8];
    const float* nW2 = (const float*)d_in[9];
    const float* nb2 = (const float*)d_in[10];
    float* out = (float*)d_out;

    int sms = 148;
    cudaDeviceGetAttribute(&sms, cudaDevAttrMultiProcessorCount, 0);

    const int s_edge = 1024 + W1B_BYTES + W2B_BYTES + A1B_BYTES;
    const int s_node = 1024 + (NW1_WORDS + NW2_WORDS) * 4;

    cudaFuncSetAttribute(k_edge_fused, cudaFuncAttributeMaxDynamicSharedMemorySize, s_edge);
    cudaFuncSetAttribute(k_node_fused, cudaFuncAttributeMaxDynamicSharedMemorySize, s_node);

    const size_t cz = (size_t)N_NODES * D;

    k_detect<<<1, 1>>>((const int*)ei);
    k_convert_prep<<<(int)((cz + 255) / 256), 256>>>(ei, x, eW1, eW2, nW1, nW2);
    k_edge_fused<<<sms, 512, s_edge>>>(x, ea, eb1, eb2, eW1, eW2, sms);
    k_node_fused<<<sms, 256, s_node>>>(x, nb1, nb2, nW1, nW2, out, sms);
}